// round 2
// baseline (speedup 1.0000x reference)
#include <cuda_runtime.h>
#include <cstdint>

// ============================ problem constants ============================
// B=8, N=300 -> BN=2400; G=4; P=O=32; CG=DG=64; IN_DIM=OUT_DIM=256; TEMPER=8

// ===================== scratch (__device__ globals) ========================
__device__ float g_M  [2400u * 16384u];  // qv @ m_w^T + m_b   (bn, g*4096 + c*64 + d)
__device__ float g_V  [2400u * 16384u];  // qv @ v_w^T + v_b
__device__ float g_S  [2400u * 4096u];   // qv @ s_w^T + s_b   (bn, g*1024 + o*32 + p)
__device__ float g_Q  [2400u * 4096u];   // qv @ q_w^T + q_b   (bn, g*1024 + o*32 + i)
__device__ float g_FMS[2400u * 8192u];   // reg branch (bn, g*2048 + o*64 + d)
__device__ float g_FC [2400u * 8192u];   // cls branch
__device__ float g_TMP[2u * 614400u];    // pre-LN rows (z, bn, 256)

// ===================== packed f32x2 (FFMA2) helpers ========================
__device__ __forceinline__ unsigned long long pack2(float lo, float hi) {
    unsigned long long r;
    asm("mov.b64 %0, {%1, %2};" : "=l"(r) : "f"(lo), "f"(hi));
    return r;
}
__device__ __forceinline__ void unpack2(float& lo, float& hi, unsigned long long v) {
    asm("mov.b64 {%0, %1}, %2;" : "=f"(lo), "=f"(hi) : "l"(v));
}
__device__ __forceinline__ void fma2(unsigned long long& d, unsigned long long a,
                                     unsigned long long b, unsigned long long c) {
    asm("fma.rn.f32x2 %0, %1, %2, %3;" : "=l"(d) : "l"(a), "l"(b), "l"(c));
}

// ============ NT GEMM: C[M,Nout] = A[M,K] @ W[Nout,K]^T + bias =============
// blockIdx.z in {0,1} selects operand set (two GEMMs batched per launch).
template<int BM, int BNt, int BK, int TM, int TN>
__global__ void __launch_bounds__(256) gemm_nt(
    const float* __restrict__ A0, const float* __restrict__ W0,
    const float* __restrict__ b0, float* __restrict__ C0,
    const float* __restrict__ A1, const float* __restrict__ W1,
    const float* __restrict__ b1, float* __restrict__ C1,
    int M, int Nout, int K)
{
    __shared__ __align__(16) float As[BK][BM + 4];
    __shared__ __align__(16) float Ws[BK][BNt + 4];

    const float* A    = blockIdx.z ? A1 : A0;
    const float* W    = blockIdx.z ? W1 : W0;
    const float* bias = blockIdx.z ? b1 : b0;
    float*       C    = blockIdx.z ? C1 : C0;

    const int tid = threadIdx.x;
    const int tx  = tid % (BNt / TN);
    const int ty  = tid / (BNt / TN);
    const int m0  = blockIdx.y * BM;
    const int n0  = blockIdx.x * BNt;

    constexpr int THREADS = (BM / TM) * (BNt / TN);
    static_assert(THREADS == 256, "need 256 threads");
    constexpr int KQ  = BK / 4;
    constexpr int RPP = THREADS / KQ;
    constexpr int A_LOADS = BM / RPP;
    constexpr int W_LOADS = BNt / RPP;

    const int lrow = tid / KQ;
    const int lk   = (tid % KQ) * 4;

    unsigned long long acc[TM][TN / 2] = {};

    for (int k0 = 0; k0 < K; k0 += BK) {
#pragma unroll
        for (int i = 0; i < A_LOADS; i++) {
            int row = i * RPP + lrow;
            int gm  = m0 + row;
            float4 v = make_float4(0.f, 0.f, 0.f, 0.f);
            if (gm < M) v = *(const float4*)(A + (size_t)gm * K + k0 + lk);
            As[lk + 0][row] = v.x; As[lk + 1][row] = v.y;
            As[lk + 2][row] = v.z; As[lk + 3][row] = v.w;
        }
#pragma unroll
        for (int i = 0; i < W_LOADS; i++) {
            int row = i * RPP + lrow;
            float4 v = *(const float4*)(W + (size_t)(n0 + row) * K + k0 + lk);
            Ws[lk + 0][row] = v.x; Ws[lk + 1][row] = v.y;
            Ws[lk + 2][row] = v.z; Ws[lk + 3][row] = v.w;
        }
        __syncthreads();
#pragma unroll
        for (int kk = 0; kk < BK; kk++) {
            unsigned long long bb[TN / 2];
            const unsigned long long* bp =
                reinterpret_cast<const unsigned long long*>(&Ws[kk][tx * TN]);
#pragma unroll
            for (int j = 0; j < TN / 2; j++) bb[j] = bp[j];
#pragma unroll
            for (int i = 0; i < TM; i++) {
                float av = As[kk][ty * TM + i];
                unsigned long long aa = pack2(av, av);
#pragma unroll
                for (int j = 0; j < TN / 2; j++) fma2(acc[i][j], aa, bb[j], acc[i][j]);
            }
        }
        __syncthreads();
    }

#pragma unroll
    for (int i = 0; i < TM; i++) {
        int gm = m0 + ty * TM + i;
        if (gm >= M) continue;
#pragma unroll
        for (int j = 0; j < TN / 2; j++) {
            float lo, hi;
            unpack2(lo, hi, acc[i][j]);
            int gn = n0 + tx * TN + 2 * j;
            C[(size_t)gm * Nout + gn]     = lo + bias[gn];
            C[(size_t)gm * Nout + gn + 1] = hi + bias[gn + 1];
        }
    }
}

// ======================= fused per-(bn,g) kernel ===========================
// LayerNorm over 2048 elems held as 4x4 regs per thread (128 threads), + ReLU
__device__ __forceinline__ void ln2048_relu(float acc[4][4], float* red) {
    float s = 0.f, q = 0.f;
#pragma unroll
    for (int i = 0; i < 4; i++)
#pragma unroll
        for (int j = 0; j < 4; j++) { s += acc[i][j]; q += acc[i][j] * acc[i][j]; }
#pragma unroll
    for (int o = 16; o > 0; o >>= 1) {
        s += __shfl_xor_sync(0xffffffffu, s, o);
        q += __shfl_xor_sync(0xffffffffu, q, o);
    }
    int w = threadIdx.x >> 5;
    __syncthreads();                       // WAR protection on red
    if ((threadIdx.x & 31) == 0) { red[w] = s; red[4 + w] = q; }
    __syncthreads();
    s = red[0] + red[1] + red[2] + red[3];
    q = red[4] + red[5] + red[6] + red[7];
    float mean = s * (1.f / 2048.f);
    float var  = q * (1.f / 2048.f) - mean * mean;
    float inv  = rsqrtf(var + 1e-5f);
#pragma unroll
    for (int i = 0; i < 4; i++)
#pragma unroll
        for (int j = 0; j < 4; j++)
            acc[i][j] = fmaxf((acc[i][j] - mean) * inv, 0.f);
}

// 32xNN output via 4x4 per-thread tile (tx in [0,16), ty in [0,8)).
// acc[i][j] = sum_k Am[(4ty+i)*SA + k] * Bm[k*SB + 4tx + j]
template<int SA, int SB, int KD>
__device__ __forceinline__ void mm4x4(float acc[4][4], const float* Am,
                                      const float* Bm, int tx, int ty) {
#pragma unroll
    for (int i = 0; i < 4; i++)
#pragma unroll
        for (int j = 0; j < 4; j++) acc[i][j] = 0.f;
#pragma unroll 8
    for (int k = 0; k < KD; k++) {
        float4 b = *(const float4*)(Bm + k * SB + tx * 4);
#pragma unroll
        for (int i = 0; i < 4; i++) {
            float a = Am[(ty * 4 + i) * SA + k];
            acc[i][0] = fmaf(a, b.x, acc[i][0]);
            acc[i][1] = fmaf(a, b.y, acc[i][1]);
            acc[i][2] = fmaf(a, b.z, acc[i][2]);
            acc[i][3] = fmaf(a, b.w, acc[i][3]);
        }
    }
}

// 32x32 output via 2x4 per-thread tile (tx8 in [0,8), ty16 in [0,16)).
// B normal: acc[i][j] = sum_k Am[(2ty16+i)*SA + k] * Bm[k*SB + 4tx8 + j]
template<int SA, int SB, int KD>
__device__ __forceinline__ void mm2x4(float acc[2][4], const float* Am,
                                      const float* Bm, int tx8, int ty16) {
#pragma unroll
    for (int i = 0; i < 2; i++)
#pragma unroll
        for (int j = 0; j < 4; j++) acc[i][j] = 0.f;
#pragma unroll 8
    for (int k = 0; k < KD; k++) {
        float4 b = *(const float4*)(Bm + k * SB + tx8 * 4);
        float a0 = Am[(2 * ty16 + 0) * SA + k];
        float a1 = Am[(2 * ty16 + 1) * SA + k];
        acc[0][0] = fmaf(a0, b.x, acc[0][0]); acc[0][1] = fmaf(a0, b.y, acc[0][1]);
        acc[0][2] = fmaf(a0, b.z, acc[0][2]); acc[0][3] = fmaf(a0, b.w, acc[0][3]);
        acc[1][0] = fmaf(a1, b.x, acc[1][0]); acc[1][1] = fmaf(a1, b.y, acc[1][1]);
        acc[1][2] = fmaf(a1, b.z, acc[1][2]); acc[1][3] = fmaf(a1, b.w, acc[1][3]);
    }
}

// 32x32 output, B transposed: acc[i][j] = sum_k Am[(2ty16+i)*SA+k]*Bm[(4tx8+j)*SB+k]
template<int SA, int SB, int KD>
__device__ __forceinline__ void mm2x4_bt(float acc[2][4], const float* Am,
                                         const float* Bm, int tx8, int ty16) {
#pragma unroll
    for (int i = 0; i < 2; i++)
#pragma unroll
        for (int j = 0; j < 4; j++) acc[i][j] = 0.f;
#pragma unroll 8
    for (int k = 0; k < KD; k++) {
        float a0 = Am[(2 * ty16 + 0) * SA + k];
        float a1 = Am[(2 * ty16 + 1) * SA + k];
#pragma unroll
        for (int j = 0; j < 4; j++) {
            float bv = Bm[(4 * tx8 + j) * SB + k];
            acc[0][j] = fmaf(a0, bv, acc[0][j]);
            acc[1][j] = fmaf(a1, bv, acc[1][j]);
        }
    }
}

__global__ void __launch_bounds__(128) fused_bg(
    const float* __restrict__ feats,
    const float* __restrict__ kw_g, const float* __restrict__ kb_g)
{
    // 48,672 B static smem
    __shared__ __align__(16) float sF[32 * 68];   // f   [p][c]
    __shared__ __align__(16) float sW[64 * 68];   // M -> Vw -> (first half) kw
    __shared__ __align__(16) float sX[32 * 68];   // fM -> v  [*][d]
    __shared__ __align__(16) float sD[32 * 36];   // S [o][p] -> att [o][p]
    __shared__ __align__(16) float sQ[32 * 36];   // q [o][i]
    __shared__ __align__(16) float sK[32 * 36];   // k [i][p]
    __shared__ float red[8];

    const int bn = blockIdx.x, g = blockIdx.y;
    const int tid = threadIdx.x;
    const int tx = tid & 15,  ty  = tid >> 4;    // 4x4 map for 32x64
    const int tx8 = tid & 7,  ty16 = tid >> 3;   // 2x4 map for 32x32
    const size_t bg = (size_t)bn * 4 + g;

    // ---- loads: f, M, S, Q ----
    {
        const float* fsrc = feats + bg * 2048;
#pragma unroll
        for (int it = 0; it < 4; it++) {
            int idx = it * 512 + tid * 4;
            *(float4*)&sF[(idx >> 6) * 68 + (idx & 63)] = *(const float4*)(fsrc + idx);
        }
        const float* msrc = g_M + bg * 4096;
#pragma unroll
        for (int it = 0; it < 8; it++) {
            int idx = it * 512 + tid * 4;
            *(float4*)&sW[(idx >> 6) * 68 + (idx & 63)] = *(const float4*)(msrc + idx);
        }
        const float* ssrc = g_S + bg * 1024;
        const float* qsrc = g_Q + bg * 1024;
#pragma unroll
        for (int it = 0; it < 2; it++) {
            int idx = it * 512 + tid * 4;
            *(float4*)&sD[(idx >> 5) * 36 + (idx & 31)] = *(const float4*)(ssrc + idx);
            *(float4*)&sQ[(idx >> 5) * 36 + (idx & 31)] = *(const float4*)(qsrc + idx);
        }
    }
    __syncthreads();

    float acc[4][4];

    // ---- fM = relu(ln2d(f @ M)) -> sX ----
    mm4x4<68, 68, 64>(acc, sF, sW, tx, ty);
    ln2048_relu(acc, red);
#pragma unroll
    for (int i = 0; i < 4; i++)
        *(float4*)&sX[(ty * 4 + i) * 68 + tx * 4] =
            make_float4(acc[i][0], acc[i][1], acc[i][2], acc[i][3]);
    __syncthreads();

    // ---- fMS = relu(ln2d(S @ fM)) -> g_FMS ----
    mm4x4<36, 68, 32>(acc, sD, sX, tx, ty);
    ln2048_relu(acc, red);
    {
        float* dst = g_FMS + bg * 2048;
#pragma unroll
        for (int i = 0; i < 4; i++)
            *(float4*)(dst + (ty * 4 + i) * 64 + tx * 4) =
                make_float4(acc[i][0], acc[i][1], acc[i][2], acc[i][3]);
    }

    // ---- reload Vw into sW (ln's barrier already past all sW reads) ----
    {
        const float* vsrc = g_V + bg * 4096;
#pragma unroll
        for (int it = 0; it < 8; it++) {
            int idx = it * 512 + tid * 4;
            *(float4*)&sW[(idx >> 6) * 68 + (idx & 63)] = *(const float4*)(vsrc + idx);
        }
    }
    __syncthreads();

    // ---- v = relu(ln2d(f @ Vw)) -> sX ----
    mm4x4<68, 68, 64>(acc, sF, sW, tx, ty);
    ln2048_relu(acc, red);
#pragma unroll
    for (int i = 0; i < 4; i++)
        *(float4*)&sX[(ty * 4 + i) * 68 + tx * 4] =
            make_float4(acc[i][0], acc[i][1], acc[i][2], acc[i][3]);

    // ---- load kw[g] into first half of sW (Vw reads done before ln barrier) ----
    {
        const float* ksrc = kw_g + g * 2048;
#pragma unroll
        for (int it = 0; it < 4; it++) {
            int idx = it * 512 + tid * 4;
            *(float4*)&sW[(idx >> 6) * 68 + (idx & 63)] = *(const float4*)(ksrc + idx);
        }
    }
    __syncthreads();

    // ---- k[i][p] = sum_d kw[i][d] * v[p][d] + kb[i] -> sK ----
    {
        float a2[2][4];
        mm2x4_bt<68, 68, 64>(a2, sW, sX, tx8, ty16);
#pragma unroll
        for (int i = 0; i < 2; i++) {
            float bias = kb_g[g * 32 + 2 * ty16 + i];
#pragma unroll
            for (int j = 0; j < 4; j++)
                sK[(2 * ty16 + i) * 36 + 4 * tx8 + j] = a2[i][j] + bias;
        }
    }
    __syncthreads();

    // ---- scores = q @ k / 8 ; softmax over p ; -> sD (att) ----
    {
        float a2[2][4];
        mm2x4<36, 36, 32>(a2, sQ, sK, tx8, ty16);
#pragma unroll
        for (int i = 0; i < 2; i++) {
            float m = a2[i][0];
#pragma unroll
            for (int j = 1; j < 4; j++) m = fmaxf(m, a2[i][j]);
#pragma unroll
            for (int o = 4; o > 0; o >>= 1)
                m = fmaxf(m, __shfl_xor_sync(0xffffffffu, m, o));
            float s = 0.f;
#pragma unroll
            for (int j = 0; j < 4; j++) {
                a2[i][j] = __expf((a2[i][j] - m) * 0.125f);
                s += a2[i][j];
            }
#pragma unroll
            for (int o = 4; o > 0; o >>= 1)
                s += __shfl_xor_sync(0xffffffffu, s, o);
            float inv = __frcp_rn(s);
#pragma unroll
            for (int j = 0; j < 4; j++)
                sD[(2 * ty16 + i) * 36 + 4 * tx8 + j] = a2[i][j] * inv;
        }
    }
    __syncthreads();

    // ---- fc = relu(ln2d(att @ v)) -> g_FC ----
    mm4x4<36, 68, 32>(acc, sD, sX, tx, ty);
    ln2048_relu(acc, red);
    {
        float* dst = g_FC + bg * 2048;
#pragma unroll
        for (int i = 0; i < 4; i++)
            *(float4*)(dst + (ty * 4 + i) * 64 + tx * 4) =
                make_float4(acc[i][0], acc[i][1], acc[i][2], acc[i][3]);
    }
}

// ====================== residual + affine LayerNorm ========================
__global__ void __launch_bounds__(256) final_ln(
    const float* __restrict__ qv,
    const float* __restrict__ wA, const float* __restrict__ bA,
    const float* __restrict__ wB, const float* __restrict__ bB,
    float* __restrict__ out)
{
    const int r = blockIdx.x, z = blockIdx.y, c = threadIdx.x;
    const float* w = z ? wB : wA;
    const float* b = z ? bB : bA;
    float x = qv[(size_t)r * 256 + c] + g_TMP[(size_t)z * 614400 + (size_t)r * 256 + c];

    __shared__ float sred[16];
    float s = x, q = x * x;
#pragma unroll
    for (int o = 16; o > 0; o >>= 1) {
        s += __shfl_xor_sync(0xffffffffu, s, o);
        q += __shfl_xor_sync(0xffffffffu, q, o);
    }
    int wp = threadIdx.x >> 5;
    if ((threadIdx.x & 31) == 0) { sred[wp] = s; sred[8 + wp] = q; }
    __syncthreads();
    float S = 0.f, Q2 = 0.f;
#pragma unroll
    for (int i = 0; i < 8; i++) { S += sred[i]; Q2 += sred[8 + i]; }
    float mean = S * (1.f / 256.f);
    float var  = Q2 * (1.f / 256.f) - mean * mean;
    float inv  = rsqrtf(var + 1e-5f);
    out[(size_t)z * 614400 + (size_t)r * 256 + c] = (x - mean) * inv * w[c] + b[c];
}

// ================================ launcher =================================
extern "C" void kernel_launch(void* const* d_in, const int* in_sizes, int n_in,
                              void* d_out, int out_size)
{
    const float* feats = (const float*)d_in[0];
    const float* qv    = (const float*)d_in[1];
    const float* m_w   = (const float*)d_in[7];
    const float* m_b   = (const float*)d_in[8];
    const float* s_w   = (const float*)d_in[9];
    const float* s_b   = (const float*)d_in[10];
    const float* q_w   = (const float*)d_in[11];
    const float* q_b   = (const float*)d_in[12];
    const float* v_w   = (const float*)d_in[13];
    const float* v_b   = (const float*)d_in[14];
    const float* k_w   = (const float*)d_in[15];
    const float* k_b   = (const float*)d_in[16];
    const float* Wv_w  = (const float*)d_in[17];
    const float* Wv_b  = (const float*)d_in[18];
    const float* Wv2_w = (const float*)d_in[19];
    const float* Wv2_b = (const float*)d_in[20];
    const float* lnA_w = (const float*)d_in[21];
    const float* lnA_b = (const float*)d_in[22];
    const float* lnB_w = (const float*)d_in[23];
    const float* lnB_b = (const float*)d_in[24];
    float* out = (float*)d_out;

    float *gM, *gV, *gS, *gQ, *gFMS, *gFC, *gTMP;
    cudaGetSymbolAddress((void**)&gM,   g_M);
    cudaGetSymbolAddress((void**)&gV,   g_V);
    cudaGetSymbolAddress((void**)&gS,   g_S);
    cudaGetSymbolAddress((void**)&gQ,   g_Q);
    cudaGetSymbolAddress((void**)&gFMS, g_FMS);
    cudaGetSymbolAddress((void**)&gFC,  g_FC);
    cudaGetSymbolAddress((void**)&gTMP, g_TMP);

    // 1) M / V generators: (2400x256) @ (16384x256)^T
    gemm_nt<128, 128, 16, 8, 8><<<dim3(128, 19, 2), 256>>>(
        qv, m_w, m_b, gM, qv, v_w, v_b, gV, 2400, 16384, 256);

    // 2) S / Q generators: (2400x256) @ (4096x256)^T
    gemm_nt<128, 128, 16, 8, 8><<<dim3(32, 19, 2), 256>>>(
        qv, s_w, s_b, gS, qv, q_w, q_b, gQ, 2400, 4096, 256);

    // 3) fused per-(bn, g) dynamic conv + attention
    fused_bg<<<dim3(2400, 4), 128>>>(feats, k_w, k_b);

    // 4) output projections: (2400x8192) @ (256x8192)^T
    gemm_nt<64, 64, 32, 4, 4><<<dim3(4, 38, 2), 256>>>(
        gFMS, Wv_w, Wv_b, gTMP, gFC, Wv2_w, Wv2_b, gTMP + 614400, 2400, 256, 8192);

    // 5) residual + affine LayerNorm -> out (reg rows then cls rows)
    final_ln<<<dim3(2400, 2), 256>>>(qv, lnA_w, lnA_b, lnB_w, lnB_b, out);
}

// round 5
// speedup vs baseline: 1.9772x; 1.9772x over previous
#include <cuda_runtime.h>
#include <cuda_bf16.h>
#include <cstdint>

// ============================ problem constants ============================
// B=8, N=300 -> BN=2400; G=4; P=O=32; CG=DG=64; IN_DIM=OUT_DIM=256; TEMPER=8

// ===================== scratch (__device__ globals) ========================
__device__ float g_M[39321600];   // (bn, g*4096 + c*64 + d)
__device__ float g_V[39321600];
__device__ float g_S[9830400];    // (bn, g*1024 + o*32 + p)
__device__ float g_Q[9830400];
__device__ float g_P[9830400];    // 16 split-K slices of (2400,256)

__device__ __nv_bfloat16 g_qvh[614400],  g_qvl[614400];
__device__ __nv_bfloat16 g_mwh[4194304], g_mwl[4194304];
__device__ __nv_bfloat16 g_vwh[4194304], g_vwl[4194304];
__device__ __nv_bfloat16 g_swh[1048576], g_swl[1048576];
__device__ __nv_bfloat16 g_qwh[1048576], g_qwl[1048576];
__device__ __nv_bfloat16 g_Wvh[2097152], g_Wvl[2097152];
__device__ __nv_bfloat16 g_W2h[2097152], g_W2l[2097152];
__device__ __nv_bfloat16 g_FMSh[19660800], g_FMSl[19660800];
__device__ __nv_bfloat16 g_FCh[19660800],  g_FCl[19660800];

// ============================ small helpers ================================
__device__ __forceinline__ uint32_t smem_u32(const void* p) {
    uint32_t a;
    asm("{ .reg .u64 t; cvta.to.shared.u64 t, %1; cvt.u32.u64 %0, t; }"
        : "=r"(a) : "l"(p));
    return a;
}
__device__ __forceinline__ void split_bf16(float x, __nv_bfloat16& h, __nv_bfloat16& l) {
    h = __float2bfloat16(x);
    l = __float2bfloat16(x - __bfloat162float(h));
}
__device__ __forceinline__ void ldmx4(uint32_t r[4], uint32_t addr) {
    asm volatile("ldmatrix.sync.aligned.m8n8.x4.shared.b16 {%0,%1,%2,%3}, [%4];"
                 : "=r"(r[0]), "=r"(r[1]), "=r"(r[2]), "=r"(r[3]) : "r"(addr));
}
__device__ __forceinline__ void mma_bf16(float d[4], const uint32_t a[4],
                                         const uint32_t b0, const uint32_t b1) {
    asm volatile(
        "mma.sync.aligned.m16n8k16.row.col.f32.bf16.bf16.f32 "
        "{%0,%1,%2,%3}, {%4,%5,%6,%7}, {%8,%9}, {%0,%1,%2,%3};"
        : "+f"(d[0]), "+f"(d[1]), "+f"(d[2]), "+f"(d[3])
        : "r"(a[0]), "r"(a[1]), "r"(a[2]), "r"(a[3]), "r"(b0), "r"(b1));
}

// ================= operand split prep (fp32 -> bf16 hi/lo) =================
__global__ void __launch_bounds__(256) split_kernel(
    const float* __restrict__ qv, const float* __restrict__ mw,
    const float* __restrict__ vw, const float* __restrict__ sw,
    const float* __restrict__ qw, const float* __restrict__ Wv,
    const float* __restrict__ W2)
{
    const float* src; __nv_bfloat16 *dh, *dl; int n;
    switch (blockIdx.z) {
        case 0: src = qv; dh = g_qvh; dl = g_qvl; n = 614400;  break;
        case 1: src = mw; dh = g_mwh; dl = g_mwl; n = 4194304; break;
        case 2: src = vw; dh = g_vwh; dl = g_vwl; n = 4194304; break;
        case 3: src = sw; dh = g_swh; dl = g_swl; n = 1048576; break;
        case 4: src = qw; dh = g_qwh; dl = g_qwl; n = 1048576; break;
        case 5: src = Wv; dh = g_Wvh; dl = g_Wvl; n = 2097152; break;
        default:src = W2; dh = g_W2h; dl = g_W2l; n = 2097152; break;
    }
    int i = (blockIdx.x * 256 + threadIdx.x) * 4;
    if (i >= n) return;
    float4 v = *(const float4*)(src + i);
    union U { __nv_bfloat16 b[4]; uint2 u; } H, L;
    split_bf16(v.x, H.b[0], L.b[0]);
    split_bf16(v.y, H.b[1], L.b[1]);
    split_bf16(v.z, H.b[2], L.b[2]);
    split_bf16(v.w, H.b[3], L.b[3]);
    *(uint2*)(dh + i) = H.u;
    *(uint2*)(dl + i) = L.u;
}

// ============ HMMA bf16x3 NT GEMM: C[M,Nout] = A@W^T (+bias @ks==0) ========
// BM=128, BN=128, BK=32, 256 threads (8 warps, warp tile 32x64).
// blockIdx.z = z*splitk + ks; this CTA covers K range [ks*kPerCta, +kPerCta).
static constexpr int RS = 40;  // smem row stride in bf16 elems (80B, 16B-aligned)

__global__ void __launch_bounds__(256) hmma_gemm(
    const __nv_bfloat16* __restrict__ Ah0, const __nv_bfloat16* __restrict__ Al0,
    const __nv_bfloat16* __restrict__ Wh0, const __nv_bfloat16* __restrict__ Wl0,
    const float* __restrict__ b0, float* __restrict__ C0,
    const __nv_bfloat16* __restrict__ Ah1, const __nv_bfloat16* __restrict__ Al1,
    const __nv_bfloat16* __restrict__ Wh1, const __nv_bfloat16* __restrict__ Wl1,
    const float* __restrict__ b1, float* __restrict__ C1,
    int M, int Nout, int lda, int kPerCta, int splitk, size_t sliceStride)
{
    __shared__ __align__(16) __nv_bfloat16 sAh[128 * RS];
    __shared__ __align__(16) __nv_bfloat16 sAl[128 * RS];
    __shared__ __align__(16) __nv_bfloat16 sBh[128 * RS];
    __shared__ __align__(16) __nv_bfloat16 sBl[128 * RS];

    const int tid = threadIdx.x, wid = tid >> 5, lane = tid & 31;
    const int z  = blockIdx.z / splitk;
    const int ks = blockIdx.z % splitk;
    const __nv_bfloat16* Ah = z ? Ah1 : Ah0;
    const __nv_bfloat16* Al = z ? Al1 : Al0;
    const __nv_bfloat16* Wh = z ? Wh1 : Wh0;
    const __nv_bfloat16* Wl = z ? Wl1 : Wl0;
    const float* bias = z ? b1 : b0;
    float* Cp = (z ? C1 : C0) + (size_t)ks * sliceStride;

    const int m0 = blockIdx.y * 128;
    const int n0 = blockIdx.x * 128;
    const int kBegin = ks * kPerCta;
    const int NC = kPerCta / 32;

    const int wm = (wid & 3) * 32;   // warp rows within tile
    const int wn = (wid >> 2) * 64;  // warp cols within tile

    // loader index map: idx = tid + 256*j ; row = idx>>2 ; seg = idx&3
    const int lrow = tid >> 2;
    const int lseg = (tid & 3) * 8;

    float acc[2][8][4];
#pragma unroll
    for (int i = 0; i < 2; i++)
#pragma unroll
        for (int j = 0; j < 8; j++)
#pragma unroll
            for (int q = 0; q < 4; q++) acc[i][j][q] = 0.f;

    uint4 rA[2], rAl[2], rB[2], rBl[2];

    auto load_regs = [&](int c) {
        const int kk = kBegin + c * 32;
#pragma unroll
        for (int j = 0; j < 2; j++) {
            int row = lrow + 64 * j;
            int gm = m0 + row;
            if (gm < M) {
                size_t go = (size_t)gm * lda + kk + lseg;
                rA[j]  = *(const uint4*)(Ah + go);
                rAl[j] = *(const uint4*)(Al + go);
            } else {
                rA[j] = rAl[j] = make_uint4(0u, 0u, 0u, 0u);
            }
            size_t gw = (size_t)(n0 + row) * lda + kk + lseg;
            rB[j]  = *(const uint4*)(Wh + gw);
            rBl[j] = *(const uint4*)(Wl + gw);
        }
    };
    auto store_smem = [&]() {
#pragma unroll
        for (int j = 0; j < 2; j++) {
            int off = (lrow + 64 * j) * RS + lseg;
            *(uint4*)(sAh + off) = rA[j];
            *(uint4*)(sAl + off) = rAl[j];
            *(uint4*)(sBh + off) = rB[j];
            *(uint4*)(sBl + off) = rBl[j];
        }
    };

    const uint32_t uAh = smem_u32(sAh), uAl = smem_u32(sAl);
    const uint32_t uBh = smem_u32(sBh), uBl = smem_u32(sBl);
    // ldmatrix address components
    const int arow = lane & 15, acol = (lane >> 4) * 8;           // A tiles
    const int bgrp = lane >> 3, brow = lane & 7;                  // B tiles
    const int bn_off = (bgrp >> 1) * 8 + brow;
    const int bk_off = (bgrp & 1) * 8;

    load_regs(0);

    for (int c = 0; c < NC; c++) {
        store_smem();
        __syncthreads();
        if (c + 1 < NC) load_regs(c + 1);

#pragma unroll
        for (int ksp = 0; ksp < 2; ksp++) {
            uint32_t fAh[2][4], fAl[2][4], fBh[4][4], fBl[4][4];
#pragma unroll
            for (int mi = 0; mi < 2; mi++) {
                uint32_t off = 2u * ((wm + mi * 16 + arow) * RS + ksp * 16 + acol);
                ldmx4(fAh[mi], uAh + off);
                ldmx4(fAl[mi], uAl + off);
            }
#pragma unroll
            for (int nb = 0; nb < 4; nb++) {
                uint32_t off = 2u * ((wn + nb * 16 + bn_off) * RS + ksp * 16 + bk_off);
                ldmx4(fBh[nb], uBh + off);
                ldmx4(fBl[nb], uBl + off);
            }
#pragma unroll
            for (int mi = 0; mi < 2; mi++)
#pragma unroll
                for (int nf = 0; nf < 8; nf++) {
                    const uint32_t* bh = &fBh[nf >> 1][(nf & 1) * 2];
                    const uint32_t* bl = &fBl[nf >> 1][(nf & 1) * 2];
                    mma_bf16(acc[mi][nf], fAh[mi], bh[0], bh[1]);
                    mma_bf16(acc[mi][nf], fAl[mi], bh[0], bh[1]);
                    mma_bf16(acc[mi][nf], fAh[mi], bl[0], bl[1]);
                }
        }
        __syncthreads();
    }

    // ---- epilogue ----
    const bool addB = (ks == 0);
    const int erow = lane >> 2, ecol = (lane & 3) * 2;
#pragma unroll
    for (int mi = 0; mi < 2; mi++) {
        int r0 = m0 + wm + mi * 16 + erow;
#pragma unroll
        for (int half = 0; half < 2; half++) {
            int r = r0 + half * 8;
            if (r >= M) continue;
            float* crow = Cp + (size_t)r * Nout;
#pragma unroll
            for (int nf = 0; nf < 8; nf++) {
                int col = n0 + wn + nf * 8 + ecol;
                float2 o;
                o.x = acc[mi][nf][half * 2 + 0];
                o.y = acc[mi][nf][half * 2 + 1];
                if (addB) { o.x += __ldg(bias + col); o.y += __ldg(bias + col + 1); }
                *(float2*)(crow + col) = o;
            }
        }
    }
}

// ======================= fused per-(bn,g) kernel ===========================
__device__ __forceinline__ void ln2048_relu(float acc[4][4], float* red) {
    float s = 0.f, q = 0.f;
#pragma unroll
    for (int i = 0; i < 4; i++)
#pragma unroll
        for (int j = 0; j < 4; j++) { s += acc[i][j]; q += acc[i][j] * acc[i][j]; }
#pragma unroll
    for (int o = 16; o > 0; o >>= 1) {
        s += __shfl_xor_sync(0xffffffffu, s, o);
        q += __shfl_xor_sync(0xffffffffu, q, o);
    }
    int w = threadIdx.x >> 5;
    __syncthreads();
    if ((threadIdx.x & 31) == 0) { red[w] = s; red[4 + w] = q; }
    __syncthreads();
    s = red[0] + red[1] + red[2] + red[3];
    q = red[4] + red[5] + red[6] + red[7];
    float mean = s * (1.f / 2048.f);
    float var  = q * (1.f / 2048.f) - mean * mean;
    float inv  = rsqrtf(var + 1e-5f);
#pragma unroll
    for (int i = 0; i < 4; i++)
#pragma unroll
        for (int j = 0; j < 4; j++)
            acc[i][j] = fmaxf((acc[i][j] - mean) * inv, 0.f);
}

template<int SA, int SB, int KD>
__device__ __forceinline__ void mm4x4(float acc[4][4], const float* Am,
                                      const float* Bm, int tx, int ty) {
#pragma unroll
    for (int i = 0; i < 4; i++)
#pragma unroll
        for (int j = 0; j < 4; j++) acc[i][j] = 0.f;
#pragma unroll 8
    for (int k = 0; k < KD; k++) {
        float4 b = *(const float4*)(Bm + k * SB + tx * 4);
#pragma unroll
        for (int i = 0; i < 4; i++) {
            float a = Am[(ty * 4 + i) * SA + k];
            acc[i][0] = fmaf(a, b.x, acc[i][0]);
            acc[i][1] = fmaf(a, b.y, acc[i][1]);
            acc[i][2] = fmaf(a, b.z, acc[i][2]);
            acc[i][3] = fmaf(a, b.w, acc[i][3]);
        }
    }
}

template<int SA, int SB, int KD>
__device__ __forceinline__ void mm2x4(float acc[2][4], const float* Am,
                                      const float* Bm, int tx8, int ty16) {
#pragma unroll
    for (int i = 0; i < 2; i++)
#pragma unroll
        for (int j = 0; j < 4; j++) acc[i][j] = 0.f;
#pragma unroll 8
    for (int k = 0; k < KD; k++) {
        float4 b = *(const float4*)(Bm + k * SB + tx8 * 4);
        float a0 = Am[(2 * ty16 + 0) * SA + k];
        float a1 = Am[(2 * ty16 + 1) * SA + k];
        acc[0][0] = fmaf(a0, b.x, acc[0][0]); acc[0][1] = fmaf(a0, b.y, acc[0][1]);
        acc[0][2] = fmaf(a0, b.z, acc[0][2]); acc[0][3] = fmaf(a0, b.w, acc[0][3]);
        acc[1][0] = fmaf(a1, b.x, acc[1][0]); acc[1][1] = fmaf(a1, b.y, acc[1][1]);
        acc[1][2] = fmaf(a1, b.z, acc[1][2]); acc[1][3] = fmaf(a1, b.w, acc[1][3]);
    }
}

template<int SA, int SB, int KD>
__device__ __forceinline__ void mm2x4_bt(float acc[2][4], const float* Am,
                                         const float* Bm, int tx8, int ty16) {
#pragma unroll
    for (int i = 0; i < 2; i++)
#pragma unroll
        for (int j = 0; j < 4; j++) acc[i][j] = 0.f;
#pragma unroll 8
    for (int k = 0; k < KD; k++) {
        float a0 = Am[(2 * ty16 + 0) * SA + k];
        float a1 = Am[(2 * ty16 + 1) * SA + k];
#pragma unroll
        for (int j = 0; j < 4; j++) {
            float bv = Bm[(4 * tx8 + j) * SB + k];
            acc[0][j] = fmaf(a0, bv, acc[0][j]);
            acc[1][j] = fmaf(a1, bv, acc[1][j]);
        }
    }
}

__device__ __forceinline__ void store_split4(__nv_bfloat16* dh, __nv_bfloat16* dl,
                                             size_t off, float4 v) {
    union U { __nv_bfloat16 b[4]; uint2 u; } H, L;
    split_bf16(v.x, H.b[0], L.b[0]);
    split_bf16(v.y, H.b[1], L.b[1]);
    split_bf16(v.z, H.b[2], L.b[2]);
    split_bf16(v.w, H.b[3], L.b[3]);
    *(uint2*)(dh + off) = H.u;
    *(uint2*)(dl + off) = L.u;
}

__global__ void __launch_bounds__(128) fused_bg(
    const float* __restrict__ feats,
    const float* __restrict__ kw_g, const float* __restrict__ kb_g)
{
    __shared__ __align__(16) float sF[32 * 68];
    __shared__ __align__(16) float sW[64 * 68];
    __shared__ __align__(16) float sX[32 * 68];
    __shared__ __align__(16) float sD[32 * 36];
    __shared__ __align__(16) float sQm[32 * 36];
    __shared__ __align__(16) float sK[32 * 36];
    __shared__ float red[8];

    const int bn = blockIdx.x, g = blockIdx.y;
    const int tid = threadIdx.x;
    const int tx = tid & 15,  ty   = tid >> 4;
    const int tx8 = tid & 7,  ty16 = tid >> 3;
    const size_t bg = (size_t)bn * 4 + g;

    {
        const float* fsrc = feats + bg * 2048;
#pragma unroll
        for (int it = 0; it < 4; it++) {
            int idx = it * 512 + tid * 4;
            *(float4*)&sF[(idx >> 6) * 68 + (idx & 63)] = *(const float4*)(fsrc + idx);
        }
        const float* msrc = g_M + bg * 4096;
#pragma unroll
        for (int it = 0; it < 8; it++) {
            int idx = it * 512 + tid * 4;
            *(float4*)&sW[(idx >> 6) * 68 + (idx & 63)] = *(const float4*)(msrc + idx);
        }
        const float* ssrc = g_S + bg * 1024;
        const float* qsrc = g_Q + bg * 1024;
#pragma unroll
        for (int it = 0; it < 2; it++) {
            int idx = it * 512 + tid * 4;
            *(float4*)&sD[(idx >> 5) * 36 + (idx & 31)]  = *(const float4*)(ssrc + idx);
            *(float4*)&sQm[(idx >> 5) * 36 + (idx & 31)] = *(const float4*)(qsrc + idx);
        }
    }
    __syncthreads();

    float acc[4][4];

    // fM = relu(ln2d(f @ M)) -> sX
    mm4x4<68, 68, 64>(acc, sF, sW, tx, ty);
    ln2048_relu(acc, red);
#pragma unroll
    for (int i = 0; i < 4; i++)
        *(float4*)&sX[(ty * 4 + i) * 68 + tx * 4] =
            make_float4(acc[i][0], acc[i][1], acc[i][2], acc[i][3]);
    __syncthreads();

    // fMS = relu(ln2d(S @ fM)) -> bf16 hi/lo
    mm4x4<36, 68, 32>(acc, sD, sX, tx, ty);
    ln2048_relu(acc, red);
#pragma unroll
    for (int i = 0; i < 4; i++)
        store_split4(g_FMSh, g_FMSl, bg * 2048 + (size_t)(ty * 4 + i) * 64 + tx * 4,
                     make_float4(acc[i][0], acc[i][1], acc[i][2], acc[i][3]));

    // reload Vw into sW
    {
        const float* vsrc = g_V + bg * 4096;
#pragma unroll
        for (int it = 0; it < 8; it++) {
            int idx = it * 512 + tid * 4;
            *(float4*)&sW[(idx >> 6) * 68 + (idx & 63)] = *(const float4*)(vsrc + idx);
        }
    }
    __syncthreads();

    // v = relu(ln2d(f @ Vw)) -> sX
    mm4x4<68, 68, 64>(acc, sF, sW, tx, ty);
    ln2048_relu(acc, red);
#pragma unroll
    for (int i = 0; i < 4; i++)
        *(float4*)&sX[(ty * 4 + i) * 68 + tx * 4] =
            make_float4(acc[i][0], acc[i][1], acc[i][2], acc[i][3]);

    // load kw[g] into first half of sW
    {
        const float* ksrc = kw_g + g * 2048;
#pragma unroll
        for (int it = 0; it < 4; it++) {
            int idx = it * 512 + tid * 4;
            *(float4*)&sW[(idx >> 6) * 68 + (idx & 63)] = *(const float4*)(ksrc + idx);
        }
    }
    __syncthreads();

    // k[i][p] = kw[i]·v[p] + kb[i]
    {
        float a2[2][4];
        mm2x4_bt<68, 68, 64>(a2, sW, sX, tx8, ty16);
#pragma unroll
        for (int i = 0; i < 2; i++) {
            float bias = kb_g[g * 32 + 2 * ty16 + i];
#pragma unroll
            for (int j = 0; j < 4; j++)
                sK[(2 * ty16 + i) * 36 + 4 * tx8 + j] = a2[i][j] + bias;
        }
    }
    __syncthreads();

    // softmax(q @ k / 8) -> sD
    {
        float a2[2][4];
        mm2x4<36, 36, 32>(a2, sQm, sK, tx8, ty16);
#pragma unroll
        for (int i = 0; i < 2; i++) {
            float m = a2[i][0];
#pragma unroll
            for (int j = 1; j < 4; j++) m = fmaxf(m, a2[i][j]);
#pragma unroll
            for (int o = 4; o > 0; o >>= 1)
                m = fmaxf(m, __shfl_xor_sync(0xffffffffu, m, o));
            float s = 0.f;
#pragma unroll
            for (int j = 0; j < 4; j++) {
                a2[i][j] = __expf((a2[i][j] - m) * 0.125f);
                s += a2[i][j];
            }
#pragma unroll
            for (int o = 4; o > 0; o >>= 1)
                s += __shfl_xor_sync(0xffffffffu, s, o);
            float inv = __frcp_rn(s);
#pragma unroll
            for (int j = 0; j < 4; j++)
                sD[(2 * ty16 + i) * 36 + 4 * tx8 + j] = a2[i][j] * inv;
        }
    }
    __syncthreads();

    // fc = relu(ln2d(att @ v)) -> bf16 hi/lo
    mm4x4<36, 68, 32>(acc, sD, sX, tx, ty);
    ln2048_relu(acc, red);
#pragma unroll
    for (int i = 0; i < 4; i++)
        store_split4(g_FCh, g_FCl, bg * 2048 + (size_t)(ty * 4 + i) * 64 + tx * 4,
                     make_float4(acc[i][0], acc[i][1], acc[i][2], acc[i][3]));
}

// ============== residual + split-K reduce + affine LayerNorm ===============
__global__ void __launch_bounds__(256) final_ln(
    const float* __restrict__ qv,
    const float* __restrict__ wA, const float* __restrict__ bA,
    const float* __restrict__ wB, const float* __restrict__ bB,
    float* __restrict__ out)
{
    const int r = blockIdx.x, z = blockIdx.y, c = threadIdx.x;
    const float* w = z ? wB : wA;
    const float* b = z ? bB : bA;
    float x = qv[(size_t)r * 256 + c];
#pragma unroll
    for (int k = 0; k < 8; k++)
        x += g_P[(size_t)(z * 8 + k) * 614400 + (size_t)r * 256 + c];

    __shared__ float sred[16];
    float s = x, q = x * x;
#pragma unroll
    for (int o = 16; o > 0; o >>= 1) {
        s += __shfl_xor_sync(0xffffffffu, s, o);
        q += __shfl_xor_sync(0xffffffffu, q, o);
    }
    int wp = threadIdx.x >> 5;
    if ((threadIdx.x & 31) == 0) { sred[wp] = s; sred[8 + wp] = q; }
    __syncthreads();
    float S = 0.f, Q2 = 0.f;
#pragma unroll
    for (int i = 0; i < 8; i++) { S += sred[i]; Q2 += sred[8 + i]; }
    float mean = S * (1.f / 256.f);
    float var  = Q2 * (1.f / 256.f) - mean * mean;
    float inv  = rsqrtf(var + 1e-5f);
    out[(size_t)z * 614400 + (size_t)r * 256 + c] = (x - mean) * inv * w[c] + b[c];
}

// ================================ launcher =================================
extern "C" void kernel_launch(void* const* d_in, const int* in_sizes, int n_in,
                              void* d_out, int out_size)
{
    const float* feats = (const float*)d_in[0];
    const float* qv    = (const float*)d_in[1];
    const float* m_w   = (const float*)d_in[7];
    const float* m_b   = (const float*)d_in[8];
    const float* s_w   = (const float*)d_in[9];
    const float* s_b   = (const float*)d_in[10];
    const float* q_w   = (const float*)d_in[11];
    const float* q_b   = (const float*)d_in[12];
    const float* v_w   = (const float*)d_in[13];
    const float* v_b   = (const float*)d_in[14];
    const float* k_w   = (const float*)d_in[15];
    const float* k_b   = (const float*)d_in[16];
    const float* Wv_w  = (const float*)d_in[17];
    const float* Wv_b  = (const float*)d_in[18];
    const float* Wv2_w = (const float*)d_in[19];
    const float* Wv2_b = (const float*)d_in[20];
    const float* lnA_w = (const float*)d_in[21];
    const float* lnA_b = (const float*)d_in[22];
    const float* lnB_w = (const float*)d_in[23];
    const float* lnB_b = (const float*)d_in[24];
    float* out = (float*)d_out;

    float *gM, *gV, *gS, *gQ, *gP;
    cudaGetSymbolAddress((void**)&gM, g_M);
    cudaGetSymbolAddress((void**)&gV, g_V);
    cudaGetSymbolAddress((void**)&gS, g_S);
    cudaGetSymbolAddress((void**)&gQ, g_Q);
    cudaGetSymbolAddress((void**)&gP, g_P);
    __nv_bfloat16 *qvh, *qvl, *mwh, *mwl, *vwh, *vwl, *swh, *swl, *qwh, *qwl;
    __nv_bfloat16 *Wvh, *Wvl, *W2h, *W2l, *FMSh, *FMSl, *FCh, *FCl;
    cudaGetSymbolAddress((void**)&qvh, g_qvh);   cudaGetSymbolAddress((void**)&qvl, g_qvl);
    cudaGetSymbolAddress((void**)&mwh, g_mwh);   cudaGetSymbolAddress((void**)&mwl, g_mwl);
    cudaGetSymbolAddress((void**)&vwh, g_vwh);   cudaGetSymbolAddress((void**)&vwl, g_vwl);
    cudaGetSymbolAddress((void**)&swh, g_swh);   cudaGetSymbolAddress((void**)&swl, g_swl);
    cudaGetSymbolAddress((void**)&qwh, g_qwh);   cudaGetSymbolAddress((void**)&qwl, g_qwl);
    cudaGetSymbolAddress((void**)&Wvh, g_Wvh);   cudaGetSymbolAddress((void**)&Wvl, g_Wvl);
    cudaGetSymbolAddress((void**)&W2h, g_W2h);   cudaGetSymbolAddress((void**)&W2l, g_W2l);
    cudaGetSymbolAddress((void**)&FMSh, g_FMSh); cudaGetSymbolAddress((void**)&FMSl, g_FMSl);
    cudaGetSymbolAddress((void**)&FCh, g_FCh);   cudaGetSymbolAddress((void**)&FCl, g_FCl);

    // 0) split fp32 operands into bf16 hi/lo
    split_kernel<<<dim3(4096, 1, 7), 256>>>(qv, m_w, v_w, s_w, q_w, Wv_w, Wv2_w);

    // 1) M / V generators: (2400x256) @ (16384x256)^T, K=256
    hmma_gemm<<<dim3(128, 19, 2), 256>>>(
        qvh, qvl, mwh, mwl, m_b, gM,
        qvh, qvl, vwh, vwl, v_b, gV,
        2400, 16384, 256, 256, 1, 0);

    // 2) S / Q generators: (2400x256) @ (4096x256)^T, K=256
    hmma_gemm<<<dim3(32, 19, 2), 256>>>(
        qvh, qvl, swh, swl, s_b, gS,
        qvh, qvl, qwh, qwl, q_b, gQ,
        2400, 4096, 256, 256, 1, 0);

    // 3) fused per-(bn,g) dynamic conv + attention (emits bf16 hi/lo FMS/FC)
    fused_bg<<<dim3(2400, 4), 128>>>(feats, k_w, k_b);

    // 4) output projections: (2400x8192) @ (256x8192)^T, split-K=8
    hmma_gemm<<<dim3(2, 19, 16), 256>>>(
        FMSh, FMSl, Wvh, Wvl, Wv_b, gP,
        FCh,  FCl,  W2h, W2l, Wv2_b, gP + 8 * 614400,
        2400, 256, 8192, 1024, 8, 614400);

    // 5) residual + split-K reduce + affine LayerNorm
    final_ln<<<dim3(2400, 2), 256>>>(qv, lnA_w, lnA_b, lnB_w, lnB_b, out);
}

// round 6
// speedup vs baseline: 2.0024x; 1.0127x over previous
#include <cuda_runtime.h>
#include <cuda_bf16.h>
#include <cstdint>

// ============================ problem constants ============================
// B=8, N=300 -> BN=2400; G=4; P=O=32; CG=DG=64; IN_DIM=OUT_DIM=256; TEMPER=8

// ===================== scratch (__device__ globals) ========================
__device__ float g_M[39321600];   // (bn, g*4096 + c*64 + d)
__device__ float g_V[39321600];
__device__ float g_S[9830400];    // (bn, g*1024 + o*32 + p)
__device__ float g_Q[9830400];
__device__ float g_P[9830400];    // 16 split-K slices of (2400,256)

__device__ __nv_bfloat16 g_qvh[614400],  g_qvl[614400];
__device__ __nv_bfloat16 g_mwh[4194304], g_mwl[4194304];
__device__ __nv_bfloat16 g_vwh[4194304], g_vwl[4194304];
__device__ __nv_bfloat16 g_swh[1048576], g_swl[1048576];
__device__ __nv_bfloat16 g_qwh[1048576], g_qwl[1048576];
__device__ __nv_bfloat16 g_Wvh[2097152], g_Wvl[2097152];
__device__ __nv_bfloat16 g_W2h[2097152], g_W2l[2097152];
__device__ __nv_bfloat16 g_FMSh[19660800], g_FMSl[19660800];
__device__ __nv_bfloat16 g_FCh[19660800],  g_FCl[19660800];

// ============================ small helpers ================================
__device__ __forceinline__ uint32_t smem_u32(const void* p) {
    uint32_t a;
    asm("{ .reg .u64 t; cvta.to.shared.u64 t, %1; cvt.u32.u64 %0, t; }"
        : "=r"(a) : "l"(p));
    return a;
}
__device__ __forceinline__ void split_bf16(float x, __nv_bfloat16& h, __nv_bfloat16& l) {
    h = __float2bfloat16(x);
    l = __float2bfloat16(x - __bfloat162float(h));
}
__device__ __forceinline__ void ldmx4(uint32_t r[4], uint32_t addr) {
    asm volatile("ldmatrix.sync.aligned.m8n8.x4.shared.b16 {%0,%1,%2,%3}, [%4];"
                 : "=r"(r[0]), "=r"(r[1]), "=r"(r[2]), "=r"(r[3]) : "r"(addr));
}
__device__ __forceinline__ void mma_bf16(float d[4], const uint32_t a[4],
                                         const uint32_t b0, const uint32_t b1) {
    asm volatile(
        "mma.sync.aligned.m16n8k16.row.col.f32.bf16.bf16.f32 "
        "{%0,%1,%2,%3}, {%4,%5,%6,%7}, {%8,%9}, {%0,%1,%2,%3};"
        : "+f"(d[0]), "+f"(d[1]), "+f"(d[2]), "+f"(d[3])
        : "r"(a[0]), "r"(a[1]), "r"(a[2]), "r"(a[3]), "r"(b0), "r"(b1));
}
// packed f32x2
__device__ __forceinline__ unsigned long long pack2(float lo, float hi) {
    unsigned long long r;
    asm("mov.b64 %0, {%1, %2};" : "=l"(r) : "f"(lo), "f"(hi));
    return r;
}
__device__ __forceinline__ void unpack2(float& lo, float& hi, unsigned long long v) {
    asm("mov.b64 {%0, %1}, %2;" : "=f"(lo), "=f"(hi) : "l"(v));
}
__device__ __forceinline__ void fma2(unsigned long long& d, unsigned long long a,
                                     unsigned long long b, unsigned long long c) {
    asm("fma.rn.f32x2 %0, %1, %2, %3;" : "=l"(d) : "l"(a), "l"(b), "l"(c));
}

// ================= operand split prep (fp32 -> bf16 hi/lo) =================
__global__ void __launch_bounds__(256) split_kernel(
    const float* __restrict__ qv, const float* __restrict__ mw,
    const float* __restrict__ vw, const float* __restrict__ sw,
    const float* __restrict__ qw, const float* __restrict__ Wv,
    const float* __restrict__ W2)
{
    const float* src; __nv_bfloat16 *dh, *dl; int n;
    switch (blockIdx.z) {
        case 0: src = qv; dh = g_qvh; dl = g_qvl; n = 614400;  break;
        case 1: src = mw; dh = g_mwh; dl = g_mwl; n = 4194304; break;
        case 2: src = vw; dh = g_vwh; dl = g_vwl; n = 4194304; break;
        case 3: src = sw; dh = g_swh; dl = g_swl; n = 1048576; break;
        case 4: src = qw; dh = g_qwh; dl = g_qwl; n = 1048576; break;
        case 5: src = Wv; dh = g_Wvh; dl = g_Wvl; n = 2097152; break;
        default:src = W2; dh = g_W2h; dl = g_W2l; n = 2097152; break;
    }
    int i = (blockIdx.x * 256 + threadIdx.x) * 4;
    if (i >= n) return;
    float4 v = *(const float4*)(src + i);
    union U { __nv_bfloat16 b[4]; uint2 u; } H, L;
    split_bf16(v.x, H.b[0], L.b[0]);
    split_bf16(v.y, H.b[1], L.b[1]);
    split_bf16(v.z, H.b[2], L.b[2]);
    split_bf16(v.w, H.b[3], L.b[3]);
    *(uint2*)(dh + i) = H.u;
    *(uint2*)(dl + i) = L.u;
}

// ============ HMMA bf16x3 NT GEMM: C[M,Nout] = A@W^T (+bias @ks==0) ========
static constexpr int RS = 40;  // smem row stride in bf16 elems (80B)

__global__ void __launch_bounds__(256) hmma_gemm(
    const __nv_bfloat16* __restrict__ Ah0, const __nv_bfloat16* __restrict__ Al0,
    const __nv_bfloat16* __restrict__ Wh0, const __nv_bfloat16* __restrict__ Wl0,
    const float* __restrict__ b0, float* __restrict__ C0,
    const __nv_bfloat16* __restrict__ Ah1, const __nv_bfloat16* __restrict__ Al1,
    const __nv_bfloat16* __restrict__ Wh1, const __nv_bfloat16* __restrict__ Wl1,
    const float* __restrict__ b1, float* __restrict__ C1,
    int M, int Nout, int lda, int kPerCta, int splitk, size_t sliceStride)
{
    __shared__ __align__(16) __nv_bfloat16 sAh[128 * RS];
    __shared__ __align__(16) __nv_bfloat16 sAl[128 * RS];
    __shared__ __align__(16) __nv_bfloat16 sBh[128 * RS];
    __shared__ __align__(16) __nv_bfloat16 sBl[128 * RS];

    const int tid = threadIdx.x, wid = tid >> 5, lane = tid & 31;
    const int z  = blockIdx.z / splitk;
    const int ks = blockIdx.z % splitk;
    const __nv_bfloat16* Ah = z ? Ah1 : Ah0;
    const __nv_bfloat16* Al = z ? Al1 : Al0;
    const __nv_bfloat16* Wh = z ? Wh1 : Wh0;
    const __nv_bfloat16* Wl = z ? Wl1 : Wl0;
    const float* bias = z ? b1 : b0;
    float* Cp = (z ? C1 : C0) + (size_t)ks * sliceStride;

    const int m0 = blockIdx.y * 128;
    const int n0 = blockIdx.x * 128;
    const int kBegin = ks * kPerCta;
    const int NC = kPerCta / 32;

    const int wm = (wid & 3) * 32;
    const int wn = (wid >> 2) * 64;

    const int lrow = tid >> 2;
    const int lseg = (tid & 3) * 8;

    float acc[2][8][4];
#pragma unroll
    for (int i = 0; i < 2; i++)
#pragma unroll
        for (int j = 0; j < 8; j++)
#pragma unroll
            for (int q = 0; q < 4; q++) acc[i][j][q] = 0.f;

    uint4 rA[2], rAl[2], rB[2], rBl[2];

    auto load_regs = [&](int c) {
        const int kk = kBegin + c * 32;
#pragma unroll
        for (int j = 0; j < 2; j++) {
            int row = lrow + 64 * j;
            int gm = m0 + row;
            if (gm < M) {
                size_t go = (size_t)gm * lda + kk + lseg;
                rA[j]  = *(const uint4*)(Ah + go);
                rAl[j] = *(const uint4*)(Al + go);
            } else {
                rA[j] = rAl[j] = make_uint4(0u, 0u, 0u, 0u);
            }
            size_t gw = (size_t)(n0 + row) * lda + kk + lseg;
            rB[j]  = *(const uint4*)(Wh + gw);
            rBl[j] = *(const uint4*)(Wl + gw);
        }
    };
    auto store_smem = [&]() {
#pragma unroll
        for (int j = 0; j < 2; j++) {
            int off = (lrow + 64 * j) * RS + lseg;
            *(uint4*)(sAh + off) = rA[j];
            *(uint4*)(sAl + off) = rAl[j];
            *(uint4*)(sBh + off) = rB[j];
            *(uint4*)(sBl + off) = rBl[j];
        }
    };

    const uint32_t uAh = smem_u32(sAh), uAl = smem_u32(sAl);
    const uint32_t uBh = smem_u32(sBh), uBl = smem_u32(sBl);
    const int arow = lane & 15, acol = (lane >> 4) * 8;
    const int bgrp = lane >> 3, brow = lane & 7;
    const int bn_off = (bgrp >> 1) * 8 + brow;
    const int bk_off = (bgrp & 1) * 8;

    load_regs(0);

    for (int c = 0; c < NC; c++) {
        store_smem();
        __syncthreads();
        if (c + 1 < NC) load_regs(c + 1);

#pragma unroll
        for (int ksp = 0; ksp < 2; ksp++) {
            uint32_t fAh[2][4], fAl[2][4], fBh[4][4], fBl[4][4];
#pragma unroll
            for (int mi = 0; mi < 2; mi++) {
                uint32_t off = 2u * ((wm + mi * 16 + arow) * RS + ksp * 16 + acol);
                ldmx4(fAh[mi], uAh + off);
                ldmx4(fAl[mi], uAl + off);
            }
#pragma unroll
            for (int nb = 0; nb < 4; nb++) {
                uint32_t off = 2u * ((wn + nb * 16 + bn_off) * RS + ksp * 16 + bk_off);
                ldmx4(fBh[nb], uBh + off);
                ldmx4(fBl[nb], uBl + off);
            }
#pragma unroll
            for (int mi = 0; mi < 2; mi++)
#pragma unroll
                for (int nf = 0; nf < 8; nf++) {
                    const uint32_t* bh = &fBh[nf >> 1][(nf & 1) * 2];
                    const uint32_t* bl = &fBl[nf >> 1][(nf & 1) * 2];
                    mma_bf16(acc[mi][nf], fAh[mi], bh[0], bh[1]);
                    mma_bf16(acc[mi][nf], fAl[mi], bh[0], bh[1]);
                    mma_bf16(acc[mi][nf], fAh[mi], bl[0], bl[1]);
                }
        }
        __syncthreads();
    }

    const bool addB = (ks == 0);
    const int erow = lane >> 2, ecol = (lane & 3) * 2;
#pragma unroll
    for (int mi = 0; mi < 2; mi++) {
        int r0 = m0 + wm + mi * 16 + erow;
#pragma unroll
        for (int half = 0; half < 2; half++) {
            int r = r0 + half * 8;
            if (r >= M) continue;
            float* crow = Cp + (size_t)r * Nout;
#pragma unroll
            for (int nf = 0; nf < 8; nf++) {
                int col = n0 + wn + nf * 8 + ecol;
                float2 o;
                o.x = acc[mi][nf][half * 2 + 0];
                o.y = acc[mi][nf][half * 2 + 1];
                if (addB) { o.x += __ldg(bias + col); o.y += __ldg(bias + col + 1); }
                *(float2*)(crow + col) = o;
            }
        }
    }
}

// ======================= fused per-(bn,g) kernel ===========================
__device__ __forceinline__ void ln2048_relu(float acc[4][4], float* red) {
    float s = 0.f, q = 0.f;
#pragma unroll
    for (int i = 0; i < 4; i++)
#pragma unroll
        for (int j = 0; j < 4; j++) { s += acc[i][j]; q += acc[i][j] * acc[i][j]; }
#pragma unroll
    for (int o = 16; o > 0; o >>= 1) {
        s += __shfl_xor_sync(0xffffffffu, s, o);
        q += __shfl_xor_sync(0xffffffffu, q, o);
    }
    int w = threadIdx.x >> 5;
    __syncthreads();
    if ((threadIdx.x & 31) == 0) { red[w] = s; red[4 + w] = q; }
    __syncthreads();
    s = red[0] + red[1] + red[2] + red[3];
    q = red[4] + red[5] + red[6] + red[7];
    float mean = s * (1.f / 2048.f);
    float var  = q * (1.f / 2048.f) - mean * mean;
    float inv  = rsqrtf(var + 1e-5f);
#pragma unroll
    for (int i = 0; i < 4; i++)
#pragma unroll
        for (int j = 0; j < 4; j++)
            acc[i][j] = fmaxf((acc[i][j] - mean) * inv, 0.f);
}

// 32xNN, 4x4 tile, f32x2-packed over output columns; A loaded as float4 over k.
template<int SA, int SB, int KD>
__device__ __forceinline__ void mm4x4(float acc[4][4], const float* Am,
                                      const float* Bm, int tx, int ty) {
    unsigned long long pc[4][2] = {};
#pragma unroll
    for (int k4 = 0; k4 < KD; k4 += 4) {
        float4 a[4];
#pragma unroll
        for (int i = 0; i < 4; i++)
            a[i] = *(const float4*)(Am + (ty * 4 + i) * SA + k4);
#pragma unroll
        for (int kk = 0; kk < 4; kk++) {
            const unsigned long long* bp =
                (const unsigned long long*)(Bm + (k4 + kk) * SB + tx * 4);
            unsigned long long b01 = bp[0], b23 = bp[1];
#pragma unroll
            for (int i = 0; i < 4; i++) {
                float av = (kk == 0) ? a[i].x : (kk == 1) ? a[i].y
                         : (kk == 2) ? a[i].z : a[i].w;
                unsigned long long aa = pack2(av, av);
                fma2(pc[i][0], aa, b01, pc[i][0]);
                fma2(pc[i][1], aa, b23, pc[i][1]);
            }
        }
    }
#pragma unroll
    for (int i = 0; i < 4; i++) {
        unpack2(acc[i][0], acc[i][1], pc[i][0]);
        unpack2(acc[i][2], acc[i][3], pc[i][1]);
    }
}

// 32x32, 2x4 tile, f32x2-packed over output columns.
template<int SA, int SB, int KD>
__device__ __forceinline__ void mm2x4(float acc[2][4], const float* Am,
                                      const float* Bm, int tx8, int ty16) {
    unsigned long long pc[2][2] = {};
#pragma unroll
    for (int k4 = 0; k4 < KD; k4 += 4) {
        float4 a0 = *(const float4*)(Am + (2 * ty16 + 0) * SA + k4);
        float4 a1 = *(const float4*)(Am + (2 * ty16 + 1) * SA + k4);
#pragma unroll
        for (int kk = 0; kk < 4; kk++) {
            const unsigned long long* bp =
                (const unsigned long long*)(Bm + (k4 + kk) * SB + tx8 * 4);
            unsigned long long b01 = bp[0], b23 = bp[1];
            float v0 = (kk == 0) ? a0.x : (kk == 1) ? a0.y : (kk == 2) ? a0.z : a0.w;
            float v1 = (kk == 0) ? a1.x : (kk == 1) ? a1.y : (kk == 2) ? a1.z : a1.w;
            unsigned long long aa0 = pack2(v0, v0), aa1 = pack2(v1, v1);
            fma2(pc[0][0], aa0, b01, pc[0][0]);
            fma2(pc[0][1], aa0, b23, pc[0][1]);
            fma2(pc[1][0], aa1, b01, pc[1][0]);
            fma2(pc[1][1], aa1, b23, pc[1][1]);
        }
    }
#pragma unroll
    for (int i = 0; i < 2; i++) {
        unpack2(acc[i][0], acc[i][1], pc[i][0]);
        unpack2(acc[i][2], acc[i][3], pc[i][1]);
    }
}

// 32x32, B transposed; pack along k (dot product via f32x2, reduce lo+hi at end)
template<int SA, int SB, int KD>
__device__ __forceinline__ void mm2x4_bt(float acc[2][4], const float* Am,
                                         const float* Bm, int tx8, int ty16) {
    unsigned long long pc[2][4] = {};
#pragma unroll
    for (int k4 = 0; k4 < KD; k4 += 4) {
        const unsigned long long* a0p =
            (const unsigned long long*)(Am + (2 * ty16 + 0) * SA + k4);
        const unsigned long long* a1p =
            (const unsigned long long*)(Am + (2 * ty16 + 1) * SA + k4);
        unsigned long long a0[2] = { a0p[0], a0p[1] };
        unsigned long long a1[2] = { a1p[0], a1p[1] };
#pragma unroll
        for (int j = 0; j < 4; j++) {
            const unsigned long long* bp =
                (const unsigned long long*)(Bm + (4 * tx8 + j) * SB + k4);
            unsigned long long b0 = bp[0], b1 = bp[1];
            fma2(pc[0][j], a0[0], b0, pc[0][j]);
            fma2(pc[0][j], a0[1], b1, pc[0][j]);
            fma2(pc[1][j], a1[0], b0, pc[1][j]);
            fma2(pc[1][j], a1[1], b1, pc[1][j]);
        }
    }
#pragma unroll
    for (int i = 0; i < 2; i++)
#pragma unroll
        for (int j = 0; j < 4; j++) {
            float lo, hi;
            unpack2(lo, hi, pc[i][j]);
            acc[i][j] = lo + hi;
        }
}

__device__ __forceinline__ void store_split4(__nv_bfloat16* dh, __nv_bfloat16* dl,
                                             size_t off, float4 v) {
    union U { __nv_bfloat16 b[4]; uint2 u; } H, L;
    split_bf16(v.x, H.b[0], L.b[0]);
    split_bf16(v.y, H.b[1], L.b[1]);
    split_bf16(v.z, H.b[2], L.b[2]);
    split_bf16(v.w, H.b[3], L.b[3]);
    *(uint2*)(dh + off) = H.u;
    *(uint2*)(dl + off) = L.u;
}

__global__ void __launch_bounds__(128) fused_bg(
    const float* __restrict__ feats,
    const float* __restrict__ kw_g, const float* __restrict__ kb_g)
{
    __shared__ __align__(16) float sF[32 * 68];
    __shared__ __align__(16) float sW[64 * 68];
    __shared__ __align__(16) float sX[32 * 68];
    __shared__ __align__(16) float sD[32 * 36];
    __shared__ __align__(16) float sQm[32 * 36];
    __shared__ __align__(16) float sK[32 * 36];
    __shared__ float red[8];

    const int bn = blockIdx.x, g = blockIdx.y;
    const int tid = threadIdx.x;
    const int tx = tid & 15,  ty   = tid >> 4;
    const int tx8 = tid & 7,  ty16 = tid >> 3;
    const size_t bg = (size_t)bn * 4 + g;

    {
        const float* fsrc = feats + bg * 2048;
#pragma unroll
        for (int it = 0; it < 4; it++) {
            int idx = it * 512 + tid * 4;
            *(float4*)&sF[(idx >> 6) * 68 + (idx & 63)] = *(const float4*)(fsrc + idx);
        }
        const float* msrc = g_M + bg * 4096;
#pragma unroll
        for (int it = 0; it < 8; it++) {
            int idx = it * 512 + tid * 4;
            *(float4*)&sW[(idx >> 6) * 68 + (idx & 63)] = *(const float4*)(msrc + idx);
        }
        const float* ssrc = g_S + bg * 1024;
        const float* qsrc = g_Q + bg * 1024;
#pragma unroll
        for (int it = 0; it < 2; it++) {
            int idx = it * 512 + tid * 4;
            *(float4*)&sD[(idx >> 5) * 36 + (idx & 31)]  = *(const float4*)(ssrc + idx);
            *(float4*)&sQm[(idx >> 5) * 36 + (idx & 31)] = *(const float4*)(qsrc + idx);
        }
    }
    __syncthreads();

    float acc[4][4];

    // fM = relu(ln2d(f @ M)) -> sX
    mm4x4<68, 68, 64>(acc, sF, sW, tx, ty);
    ln2048_relu(acc, red);
#pragma unroll
    for (int i = 0; i < 4; i++)
        *(float4*)&sX[(ty * 4 + i) * 68 + tx * 4] =
            make_float4(acc[i][0], acc[i][1], acc[i][2], acc[i][3]);
    __syncthreads();

    // fMS = relu(ln2d(S @ fM)) -> bf16 hi/lo
    mm4x4<36, 68, 32>(acc, sD, sX, tx, ty);
    ln2048_relu(acc, red);
#pragma unroll
    for (int i = 0; i < 4; i++)
        store_split4(g_FMSh, g_FMSl, bg * 2048 + (size_t)(ty * 4 + i) * 64 + tx * 4,
                     make_float4(acc[i][0], acc[i][1], acc[i][2], acc[i][3]));

    // reload Vw into sW
    {
        const float* vsrc = g_V + bg * 4096;
#pragma unroll
        for (int it = 0; it < 8; it++) {
            int idx = it * 512 + tid * 4;
            *(float4*)&sW[(idx >> 6) * 68 + (idx & 63)] = *(const float4*)(vsrc + idx);
        }
    }
    __syncthreads();

    // v = relu(ln2d(f @ Vw)) -> sX
    mm4x4<68, 68, 64>(acc, sF, sW, tx, ty);
    ln2048_relu(acc, red);
#pragma unroll
    for (int i = 0; i < 4; i++)
        *(float4*)&sX[(ty * 4 + i) * 68 + tx * 4] =
            make_float4(acc[i][0], acc[i][1], acc[i][2], acc[i][3]);

    // load kw[g] into first half of sW
    {
        const float* ksrc = kw_g + g * 2048;
#pragma unroll
        for (int it = 0; it < 4; it++) {
            int idx = it * 512 + tid * 4;
            *(float4*)&sW[(idx >> 6) * 68 + (idx & 63)] = *(const float4*)(ksrc + idx);
        }
    }
    __syncthreads();

    // k[i][p] = kw[i]·v[p] + kb[i]
    {
        float a2[2][4];
        mm2x4_bt<68, 68, 64>(a2, sW, sX, tx8, ty16);
#pragma unroll
        for (int i = 0; i < 2; i++) {
            float bias = kb_g[g * 32 + 2 * ty16 + i];
#pragma unroll
            for (int j = 0; j < 4; j++)
                sK[(2 * ty16 + i) * 36 + 4 * tx8 + j] = a2[i][j] + bias;
        }
    }
    __syncthreads();

    // softmax(q @ k / 8) -> sD
    {
        float a2[2][4];
        mm2x4<36, 36, 32>(a2, sQm, sK, tx8, ty16);
#pragma unroll
        for (int i = 0; i < 2; i++) {
            float m = a2[i][0];
#pragma unroll
            for (int j = 1; j < 4; j++) m = fmaxf(m, a2[i][j]);
#pragma unroll
            for (int o = 4; o > 0; o >>= 1)
                m = fmaxf(m, __shfl_xor_sync(0xffffffffu, m, o));
            float s = 0.f;
#pragma unroll
            for (int j = 0; j < 4; j++) {
                a2[i][j] = __expf((a2[i][j] - m) * 0.125f);
                s += a2[i][j];
            }
#pragma unroll
            for (int o = 4; o > 0; o >>= 1)
                s += __shfl_xor_sync(0xffffffffu, s, o);
            float inv = __frcp_rn(s);
#pragma unroll
            for (int j = 0; j < 4; j++)
                sD[(2 * ty16 + i) * 36 + 4 * tx8 + j] = a2[i][j] * inv;
        }
    }
    __syncthreads();

    // fc = relu(ln2d(att @ v)) -> bf16 hi/lo
    mm4x4<36, 68, 32>(acc, sD, sX, tx, ty);
    ln2048_relu(acc, red);
#pragma unroll
    for (int i = 0; i < 4; i++)
        store_split4(g_FCh, g_FCl, bg * 2048 + (size_t)(ty * 4 + i) * 64 + tx * 4,
                     make_float4(acc[i][0], acc[i][1], acc[i][2], acc[i][3]));
}

// ============== residual + split-K reduce + affine LayerNorm ===============
__global__ void __launch_bounds__(256) final_ln(
    const float* __restrict__ qv,
    const float* __restrict__ wA, const float* __restrict__ bA,
    const float* __restrict__ wB, const float* __restrict__ bB,
    float* __restrict__ out)
{
    const int r = blockIdx.x, z = blockIdx.y, c = threadIdx.x;
    const float* w = z ? wB : wA;
    const float* b = z ? bB : bA;
    float x = qv[(size_t)r * 256 + c];
#pragma unroll
    for (int k = 0; k < 8; k++)
        x += g_P[(size_t)(z * 8 + k) * 614400 + (size_t)r * 256 + c];

    __shared__ float sred[16];
    float s = x, q = x * x;
#pragma unroll
    for (int o = 16; o > 0; o >>= 1) {
        s += __shfl_xor_sync(0xffffffffu, s, o);
        q += __shfl_xor_sync(0xffffffffu, q, o);
    }
    int wp = threadIdx.x >> 5;
    if ((threadIdx.x & 31) == 0) { sred[wp] = s; sred[8 + wp] = q; }
    __syncthreads();
    float S = 0.f, Q2 = 0.f;
#pragma unroll
    for (int i = 0; i < 8; i++) { S += sred[i]; Q2 += sred[8 + i]; }
    float mean = S * (1.f / 256.f);
    float var  = Q2 * (1.f / 256.f) - mean * mean;
    float inv  = rsqrtf(var + 1e-5f);
    out[(size_t)z * 614400 + (size_t)r * 256 + c] = (x - mean) * inv * w[c] + b[c];
}

// ================================ launcher =================================
extern "C" void kernel_launch(void* const* d_in, const int* in_sizes, int n_in,
                              void* d_out, int out_size)
{
    const float* feats = (const float*)d_in[0];
    const float* qv    = (const float*)d_in[1];
    const float* m_w   = (const float*)d_in[7];
    const float* m_b   = (const float*)d_in[8];
    const float* s_w   = (const float*)d_in[9];
    const float* s_b   = (const float*)d_in[10];
    const float* q_w   = (const float*)d_in[11];
    const float* q_b   = (const float*)d_in[12];
    const float* v_w   = (const float*)d_in[13];
    const float* v_b   = (const float*)d_in[14];
    const float* k_w   = (const float*)d_in[15];
    const float* k_b   = (const float*)d_in[16];
    const float* Wv_w  = (const float*)d_in[17];
    const float* Wv_b  = (const float*)d_in[18];
    const float* Wv2_w = (const float*)d_in[19];
    const float* Wv2_b = (const float*)d_in[20];
    const float* lnA_w = (const float*)d_in[21];
    const float* lnA_b = (const float*)d_in[22];
    const float* lnB_w = (const float*)d_in[23];
    const float* lnB_b = (const float*)d_in[24];
    float* out = (float*)d_out;

    float *gM, *gV, *gS, *gQ, *gP;
    cudaGetSymbolAddress((void**)&gM, g_M);
    cudaGetSymbolAddress((void**)&gV, g_V);
    cudaGetSymbolAddress((void**)&gS, g_S);
    cudaGetSymbolAddress((void**)&gQ, g_Q);
    cudaGetSymbolAddress((void**)&gP, g_P);
    __nv_bfloat16 *qvh, *qvl, *mwh, *mwl, *vwh, *vwl, *swh, *swl, *qwh, *qwl;
    __nv_bfloat16 *Wvh, *Wvl, *W2h, *W2l, *FMSh, *FMSl, *FCh, *FCl;
    cudaGetSymbolAddress((void**)&qvh, g_qvh);   cudaGetSymbolAddress((void**)&qvl, g_qvl);
    cudaGetSymbolAddress((void**)&mwh, g_mwh);   cudaGetSymbolAddress((void**)&mwl, g_mwl);
    cudaGetSymbolAddress((void**)&vwh, g_vwh);   cudaGetSymbolAddress((void**)&vwl, g_vwl);
    cudaGetSymbolAddress((void**)&swh, g_swh);   cudaGetSymbolAddress((void**)&swl, g_swl);
    cudaGetSymbolAddress((void**)&qwh, g_qwh);   cudaGetSymbolAddress((void**)&qwl, g_qwl);
    cudaGetSymbolAddress((void**)&Wvh, g_Wvh);   cudaGetSymbolAddress((void**)&Wvl, g_Wvl);
    cudaGetSymbolAddress((void**)&W2h, g_W2h);   cudaGetSymbolAddress((void**)&W2l, g_W2l);
    cudaGetSymbolAddress((void**)&FMSh, g_FMSh); cudaGetSymbolAddress((void**)&FMSl, g_FMSl);
    cudaGetSymbolAddress((void**)&FCh, g_FCh);   cudaGetSymbolAddress((void**)&FCl, g_FCl);

    // 0) split fp32 operands into bf16 hi/lo
    split_kernel<<<dim3(4096, 1, 7), 256>>>(qv, m_w, v_w, s_w, q_w, Wv_w, Wv2_w);

    // 1) M / V generators: (2400x256) @ (16384x256)^T, K=256
    hmma_gemm<<<dim3(128, 19, 2), 256>>>(
        qvh, qvl, mwh, mwl, m_b, gM,
        qvh, qvl, vwh, vwl, v_b, gV,
        2400, 16384, 256, 256, 1, 0);

    // 2) S / Q generators: (2400x256) @ (4096x256)^T, K=256
    hmma_gemm<<<dim3(32, 19, 2), 256>>>(
        qvh, qvl, swh, swl, s_b, gS,
        qvh, qvl, qwh, qwl, q_b, gQ,
        2400, 4096, 256, 256, 1, 0);

    // 3) fused per-(bn,g) dynamic conv + attention (emits bf16 hi/lo FMS/FC)
    fused_bg<<<dim3(2400, 4), 128>>>(feats, k_w, k_b);

    // 4) output projections: (2400x8192) @ (256x8192)^T, split-K=8
    hmma_gemm<<<dim3(2, 19, 16), 256>>>(
        FMSh, FMSl, Wvh, Wvl, Wv_b, gP,
        FCh,  FCl,  W2h, W2l, Wv2_b, gP + 8 * 614400,
        2400, 256, 8192, 1024, 8, 614400);

    // 5) residual + split-K reduce + affine LayerNorm
    final_ln<<<dim3(2400, 2), 256>>>(qv, lnA_w, lnA_b, lnB_w, lnB_b, out);
}

// round 7
// speedup vs baseline: 2.0621x; 1.0298x over previous
#include <cuda_runtime.h>
#include <cuda_bf16.h>
#include <cstdint>

// ============================ problem constants ============================
// B=8, N=300 -> BN=2400; G=4; P=O=32; CG=DG=64; IN_DIM=OUT_DIM=256; TEMPER=8

// ===================== scratch (__device__ globals) ========================
__device__ float g_M[39321600];   // (bn, g*4096 + c*64 + d)
__device__ float g_V[39321600];
__device__ float g_S[9830400];    // (bn, g*1024 + o*32 + p)
__device__ float g_Q[9830400];
__device__ float g_P[9830400];    // 16 split-K slices of (2400,256)

__device__ __nv_bfloat16 g_qvh[614400],  g_qvl[614400];
__device__ __nv_bfloat16 g_mwh[4194304], g_mwl[4194304];
__device__ __nv_bfloat16 g_vwh[4194304], g_vwl[4194304];
__device__ __nv_bfloat16 g_swh[1048576], g_swl[1048576];
__device__ __nv_bfloat16 g_qwh[1048576], g_qwl[1048576];
__device__ __nv_bfloat16 g_Wvh[2097152], g_Wvl[2097152];
__device__ __nv_bfloat16 g_W2h[2097152], g_W2l[2097152];
__device__ __nv_bfloat16 g_FMSh[19660800], g_FMSl[19660800];
__device__ __nv_bfloat16 g_FCh[19660800],  g_FCl[19660800];

// ============================ small helpers ================================
__device__ __forceinline__ uint32_t smem_u32(const void* p) {
    uint32_t a;
    asm("{ .reg .u64 t; cvta.to.shared.u64 t, %1; cvt.u32.u64 %0, t; }"
        : "=r"(a) : "l"(p));
    return a;
}
__device__ __forceinline__ void split_bf16(float x, __nv_bfloat16& h, __nv_bfloat16& l) {
    h = __float2bfloat16(x);
    l = __float2bfloat16(x - __bfloat162float(h));
}
__device__ __forceinline__ void ldmx4(uint32_t r[4], uint32_t addr) {
    asm volatile("ldmatrix.sync.aligned.m8n8.x4.shared.b16 {%0,%1,%2,%3}, [%4];"
                 : "=r"(r[0]), "=r"(r[1]), "=r"(r[2]), "=r"(r[3]) : "r"(addr));
}
__device__ __forceinline__ void ldmx4_t(uint32_t r[4], uint32_t addr) {
    asm volatile("ldmatrix.sync.aligned.m8n8.x4.trans.shared.b16 {%0,%1,%2,%3}, [%4];"
                 : "=r"(r[0]), "=r"(r[1]), "=r"(r[2]), "=r"(r[3]) : "r"(addr));
}
__device__ __forceinline__ void mma_bf16(float d[4], const uint32_t a[4],
                                         const uint32_t b0, const uint32_t b1) {
    asm volatile(
        "mma.sync.aligned.m16n8k16.row.col.f32.bf16.bf16.f32 "
        "{%0,%1,%2,%3}, {%4,%5,%6,%7}, {%8,%9}, {%0,%1,%2,%3};"
        : "+f"(d[0]), "+f"(d[1]), "+f"(d[2]), "+f"(d[3])
        : "r"(a[0]), "r"(a[1]), "r"(a[2]), "r"(a[3]), "r"(b0), "r"(b1));
}
__device__ __forceinline__ uint32_t bf2_pack(float a, float b) {
    __nv_bfloat16 h0 = __float2bfloat16(a), h1 = __float2bfloat16(b);
    union { __nv_bfloat16 h[2]; uint32_t u; } U;
    U.h[0] = h0; U.h[1] = h1;
    return U.u;
}

// ================= operand split prep (fp32 -> bf16 hi/lo) =================
__global__ void __launch_bounds__(256) split_kernel(
    const float* __restrict__ qv, const float* __restrict__ mw,
    const float* __restrict__ vw, const float* __restrict__ sw,
    const float* __restrict__ qw, const float* __restrict__ Wv,
    const float* __restrict__ W2)
{
    const float* src; __nv_bfloat16 *dh, *dl; int n;
    switch (blockIdx.z) {
        case 0: src = qv; dh = g_qvh; dl = g_qvl; n = 614400;  break;
        case 1: src = mw; dh = g_mwh; dl = g_mwl; n = 4194304; break;
        case 2: src = vw; dh = g_vwh; dl = g_vwl; n = 4194304; break;
        case 3: src = sw; dh = g_swh; dl = g_swl; n = 1048576; break;
        case 4: src = qw; dh = g_qwh; dl = g_qwl; n = 1048576; break;
        case 5: src = Wv; dh = g_Wvh; dl = g_Wvl; n = 2097152; break;
        default:src = W2; dh = g_W2h; dl = g_W2l; n = 2097152; break;
    }
    int i = (blockIdx.x * 256 + threadIdx.x) * 4;
    if (i >= n) return;
    float4 v = *(const float4*)(src + i);
    union U { __nv_bfloat16 b[4]; uint2 u; } H, L;
    split_bf16(v.x, H.b[0], L.b[0]);
    split_bf16(v.y, H.b[1], L.b[1]);
    split_bf16(v.z, H.b[2], L.b[2]);
    split_bf16(v.w, H.b[3], L.b[3]);
    *(uint2*)(dh + i) = H.u;
    *(uint2*)(dl + i) = L.u;
}

// ============ HMMA bf16x3 NT GEMM: C[M,Nout] = A@W^T (+bias @ks==0) ========
static constexpr int RS = 40;

__global__ void __launch_bounds__(256) hmma_gemm(
    const __nv_bfloat16* __restrict__ Ah0, const __nv_bfloat16* __restrict__ Al0,
    const __nv_bfloat16* __restrict__ Wh0, const __nv_bfloat16* __restrict__ Wl0,
    const float* __restrict__ b0, float* __restrict__ C0,
    const __nv_bfloat16* __restrict__ Ah1, const __nv_bfloat16* __restrict__ Al1,
    const __nv_bfloat16* __restrict__ Wh1, const __nv_bfloat16* __restrict__ Wl1,
    const float* __restrict__ b1, float* __restrict__ C1,
    int M, int Nout, int lda, int kPerCta, int splitk, size_t sliceStride)
{
    __shared__ __align__(16) __nv_bfloat16 sAh[128 * RS];
    __shared__ __align__(16) __nv_bfloat16 sAl[128 * RS];
    __shared__ __align__(16) __nv_bfloat16 sBh[128 * RS];
    __shared__ __align__(16) __nv_bfloat16 sBl[128 * RS];

    const int tid = threadIdx.x, wid = tid >> 5, lane = tid & 31;
    const int z  = blockIdx.z / splitk;
    const int ks = blockIdx.z % splitk;
    const __nv_bfloat16* Ah = z ? Ah1 : Ah0;
    const __nv_bfloat16* Al = z ? Al1 : Al0;
    const __nv_bfloat16* Wh = z ? Wh1 : Wh0;
    const __nv_bfloat16* Wl = z ? Wl1 : Wl0;
    const float* bias = z ? b1 : b0;
    float* Cp = (z ? C1 : C0) + (size_t)ks * sliceStride;

    const int m0 = blockIdx.y * 128;
    const int n0 = blockIdx.x * 128;
    const int kBegin = ks * kPerCta;
    const int NC = kPerCta / 32;

    const int wm = (wid & 3) * 32;
    const int wn = (wid >> 2) * 64;

    const int lrow = tid >> 2;
    const int lseg = (tid & 3) * 8;

    float acc[2][8][4];
#pragma unroll
    for (int i = 0; i < 2; i++)
#pragma unroll
        for (int j = 0; j < 8; j++)
#pragma unroll
            for (int q = 0; q < 4; q++) acc[i][j][q] = 0.f;

    uint4 rA[2], rAl[2], rB[2], rBl[2];

    auto load_regs = [&](int c) {
        const int kk = kBegin + c * 32;
#pragma unroll
        for (int j = 0; j < 2; j++) {
            int row = lrow + 64 * j;
            int gm = m0 + row;
            if (gm < M) {
                size_t go = (size_t)gm * lda + kk + lseg;
                rA[j]  = *(const uint4*)(Ah + go);
                rAl[j] = *(const uint4*)(Al + go);
            } else {
                rA[j] = rAl[j] = make_uint4(0u, 0u, 0u, 0u);
            }
            size_t gw = (size_t)(n0 + row) * lda + kk + lseg;
            rB[j]  = *(const uint4*)(Wh + gw);
            rBl[j] = *(const uint4*)(Wl + gw);
        }
    };
    auto store_smem = [&]() {
#pragma unroll
        for (int j = 0; j < 2; j++) {
            int off = (lrow + 64 * j) * RS + lseg;
            *(uint4*)(sAh + off) = rA[j];
            *(uint4*)(sAl + off) = rAl[j];
            *(uint4*)(sBh + off) = rB[j];
            *(uint4*)(sBl + off) = rBl[j];
        }
    };

    const uint32_t uAh = smem_u32(sAh), uAl = smem_u32(sAl);
    const uint32_t uBh = smem_u32(sBh), uBl = smem_u32(sBl);
    const int arow = lane & 15, acol = (lane >> 4) * 8;
    const int bgrp = lane >> 3, brow = lane & 7;
    const int bn_off = (bgrp >> 1) * 8 + brow;
    const int bk_off = (bgrp & 1) * 8;

    load_regs(0);

    for (int c = 0; c < NC; c++) {
        store_smem();
        __syncthreads();
        if (c + 1 < NC) load_regs(c + 1);

#pragma unroll
        for (int ksp = 0; ksp < 2; ksp++) {
            uint32_t fAh[2][4], fAl[2][4], fBh[4][4], fBl[4][4];
#pragma unroll
            for (int mi = 0; mi < 2; mi++) {
                uint32_t off = 2u * ((wm + mi * 16 + arow) * RS + ksp * 16 + acol);
                ldmx4(fAh[mi], uAh + off);
                ldmx4(fAl[mi], uAl + off);
            }
#pragma unroll
            for (int nb = 0; nb < 4; nb++) {
                uint32_t off = 2u * ((wn + nb * 16 + bn_off) * RS + ksp * 16 + bk_off);
                ldmx4(fBh[nb], uBh + off);
                ldmx4(fBl[nb], uBl + off);
            }
#pragma unroll
            for (int mi = 0; mi < 2; mi++)
#pragma unroll
                for (int nf = 0; nf < 8; nf++) {
                    const uint32_t* bh = &fBh[nf >> 1][(nf & 1) * 2];
                    const uint32_t* bl = &fBl[nf >> 1][(nf & 1) * 2];
                    mma_bf16(acc[mi][nf], fAh[mi], bh[0], bh[1]);
                    mma_bf16(acc[mi][nf], fAl[mi], bh[0], bh[1]);
                    mma_bf16(acc[mi][nf], fAh[mi], bl[0], bl[1]);
                }
        }
        __syncthreads();
    }

    const bool addB = (ks == 0);
    const int erow = lane >> 2, ecol = (lane & 3) * 2;
#pragma unroll
    for (int mi = 0; mi < 2; mi++) {
        int r0 = m0 + wm + mi * 16 + erow;
#pragma unroll
        for (int half = 0; half < 2; half++) {
            int r = r0 + half * 8;
            if (r >= M) continue;
            float* crow = Cp + (size_t)r * Nout;
#pragma unroll
            for (int nf = 0; nf < 8; nf++) {
                int col = n0 + wn + nf * 8 + ecol;
                float2 o;
                o.x = acc[mi][nf][half * 2 + 0];
                o.y = acc[mi][nf][half * 2 + 1];
                if (addB) { o.x += __ldg(bias + col); o.y += __ldg(bias + col + 1); }
                *(float2*)(crow + col) = o;
            }
        }
    }
}

// ================== fused per-(bn,g) kernel (full HMMA) ====================
// smem strides (bf16 elems): wide buffers 72 (144B rows), narrow 40 (80B rows)
static constexpr int STW = 72;
static constexpr int STN = 40;
// dynamic smem layout (bf16 elem offsets)
static constexpr int O_FH = 0;          // f hi        32*72
static constexpr int O_FL = 2304;       // f lo
static constexpr int O_WH = 4608;       // M/Vw hi     64*72
static constexpr int O_WL = 9216;
static constexpr int O_XH = 13824;      // fM/v hi     32*72
static constexpr int O_XL = 16128;
static constexpr int O_SH = 18432;      // S/att hi    32*40
static constexpr int O_SL = 19712;
static constexpr int O_QH = 20992;      // q hi
static constexpr int O_QL = 22272;
static constexpr int O_KH = 23552;      // k hi
static constexpr int O_KL = 24832;
static constexpr int BF_ELEMS = 26112;  // total bf16 elems
static constexpr int FUSED_SMEM = BF_ELEMS * 2 + 32 * 36 * 4 + 32;  // + sc + red

// LN over 2048 elems held as 16 regs/thread (128 threads) + ReLU
__device__ __forceinline__ void ln2048_relu(float acc[4][4], float* red) {
    float s = 0.f, q = 0.f;
#pragma unroll
    for (int i = 0; i < 4; i++)
#pragma unroll
        for (int j = 0; j < 4; j++) { s += acc[i][j]; q += acc[i][j] * acc[i][j]; }
#pragma unroll
    for (int o = 16; o > 0; o >>= 1) {
        s += __shfl_xor_sync(0xffffffffu, s, o);
        q += __shfl_xor_sync(0xffffffffu, q, o);
    }
    int w = threadIdx.x >> 5;
    __syncthreads();
    if ((threadIdx.x & 31) == 0) { red[w] = s; red[4 + w] = q; }
    __syncthreads();
    s = red[0] + red[1] + red[2] + red[3];
    q = red[4] + red[5] + red[6] + red[7];
    float mean = s * (1.f / 2048.f);
    float var  = q * (1.f / 2048.f) - mean * mean;
    float inv  = rsqrtf(var + 1e-5f);
#pragma unroll
    for (int i = 0; i < 4; i++)
#pragma unroll
        for (int j = 0; j < 4; j++)
            acc[i][j] = fmaxf((acc[i][j] - mean) * inv, 0.f);
}

// fragment matmul: C(32 x NB*8 per warp pair) += 3-pass bf16 split product.
// A: [32][SA] rows=m, k-contig. B: TRANS ? stored [k][SB] : stored [n][SB].
template<int NB, int KT, bool TRANS, int SA, int SB>
__device__ __forceinline__ void mm_frag(float acc[NB][4],
    const __nv_bfloat16* AH, const __nv_bfloat16* AL,
    const __nv_bfloat16* BH, const __nv_bfloat16* BL,
    int rw, int wn, int lane)
{
    const int arow = lane & 15, acol8 = (lane >> 4) * 8;
    const int b1 = ((lane >> 4) << 3) + (lane & 7);
    const int b2 = ((lane >> 3) & 1) * 8;
#pragma unroll
    for (int i = 0; i < NB; i++)
#pragma unroll
        for (int j = 0; j < 4; j++) acc[i][j] = 0.f;
#pragma unroll
    for (int kt = 0; kt < KT; kt++) {
        uint32_t aH[4], aL[4];
        ldmx4(aH, smem_u32(AH + (rw + arow) * SA + kt * 16 + acol8));
        ldmx4(aL, smem_u32(AL + (rw + arow) * SA + kt * 16 + acol8));
#pragma unroll
        for (int nt = 0; nt < NB / 2; nt++) {
            uint32_t bH[4], bL[4];
            if (TRANS) {
                ldmx4_t(bH, smem_u32(BH + (kt * 16 + b1) * SB + wn + nt * 16 + b2));
                ldmx4_t(bL, smem_u32(BL + (kt * 16 + b1) * SB + wn + nt * 16 + b2));
            } else {
                ldmx4(bH, smem_u32(BH + (wn + nt * 16 + b1) * SB + kt * 16 + b2));
                ldmx4(bL, smem_u32(BL + (wn + nt * 16 + b1) * SB + kt * 16 + b2));
            }
#pragma unroll
            for (int h = 0; h < 2; h++) {
                int nb = nt * 2 + h;
                uint32_t h0, h1, l0, l1;
                if (TRANS) { h0 = bH[h]; h1 = bH[h + 2]; l0 = bL[h]; l1 = bL[h + 2]; }
                else       { h0 = bH[2 * h]; h1 = bH[2 * h + 1];
                             l0 = bL[2 * h]; l1 = bL[2 * h + 1]; }
                mma_bf16(acc[nb], aH, h0, h1);
                mma_bf16(acc[nb], aL, h0, h1);
                mma_bf16(acc[nb], aH, l0, l1);
            }
        }
    }
}

// global fp32 -> smem bf16 hi/lo with padded stride (W = source row width)
template<int W, int ST>
__device__ __forceinline__ void load_split_smem(const float* __restrict__ src, int n,
                                                __nv_bfloat16* dh, __nv_bfloat16* dl,
                                                int tid)
{
#pragma unroll
    for (int idx = tid * 4; idx < n; idx += 512) {
        int row = idx / W, col = idx % W;
        float4 v = *(const float4*)(src + idx);
        union U { __nv_bfloat16 b[4]; uint2 u; } H, L;
        split_bf16(v.x, H.b[0], L.b[0]);
        split_bf16(v.y, H.b[1], L.b[1]);
        split_bf16(v.z, H.b[2], L.b[2]);
        split_bf16(v.w, H.b[3], L.b[3]);
        *(uint2*)(dh + row * ST + col) = H.u;
        *(uint2*)(dl + row * ST + col) = L.u;
    }
}

__global__ void __launch_bounds__(128) fused_bg(
    const float* __restrict__ feats,
    const float* __restrict__ kw_g, const float* __restrict__ kb_g)
{
    extern __shared__ char dynsm[];
    __nv_bfloat16* bfb = (__nv_bfloat16*)dynsm;
    __nv_bfloat16 *fH = bfb + O_FH, *fL = bfb + O_FL;
    __nv_bfloat16 *wH = bfb + O_WH, *wL = bfb + O_WL;
    __nv_bfloat16 *xH = bfb + O_XH, *xL = bfb + O_XL;
    __nv_bfloat16 *sH = bfb + O_SH, *sL = bfb + O_SL;
    __nv_bfloat16 *qH = bfb + O_QH, *qL = bfb + O_QL;
    __nv_bfloat16 *kH = bfb + O_KH, *kL = bfb + O_KL;
    float* sc  = (float*)(dynsm + BF_ELEMS * 2);
    float* red = sc + 32 * 36;

    const int bn = blockIdx.x, g = blockIdx.y;
    const int tid = threadIdx.x;
    const int lane = tid & 31, wrp = tid >> 5;
    const int rw   = (wrp & 1) * 16;   // warp row base
    const int wn32 = (wrp >> 1) * 32;  // warp col base (64-wide out)
    const int wn16 = (wrp >> 1) * 16;  // warp col base (32-wide out)
    const int lr = lane >> 2, lc = 2 * (lane & 3);
    const size_t bg = (size_t)bn * 4 + g;

    // ---- stage inputs: f, M, S, q ----
    load_split_smem<64, STW>(feats + bg * 2048, 2048, fH, fL, tid);
    load_split_smem<64, STW>(g_M + bg * 4096, 4096, wH, wL, tid);
    load_split_smem<32, STN>(g_S + bg * 1024, 1024, sH, sL, tid);
    load_split_smem<32, STN>(g_Q + bg * 1024, 1024, qH, qL, tid);
    __syncthreads();

    float acc[4][4];

    // ---- fM = relu(ln2d(f @ M)) -> x ----
    mm_frag<4, 4, true, STW, STW>(acc, fH, fL, wH, wL, rw, wn32, lane);
    ln2048_relu(acc, red);
#pragma unroll
    for (int nb = 0; nb < 4; nb++) {
        int c = wn32 + nb * 8 + lc;
        int r0 = rw + lr;
        *(uint32_t*)(xH + r0 * STW + c)       = bf2_pack(acc[nb][0], acc[nb][1]);
        *(uint32_t*)(xH + (r0 + 8) * STW + c) = bf2_pack(acc[nb][2], acc[nb][3]);
        float h0 = __bfloat162float(__float2bfloat16(acc[nb][0]));
        float h1 = __bfloat162float(__float2bfloat16(acc[nb][1]));
        float h2 = __bfloat162float(__float2bfloat16(acc[nb][2]));
        float h3 = __bfloat162float(__float2bfloat16(acc[nb][3]));
        *(uint32_t*)(xL + r0 * STW + c)       = bf2_pack(acc[nb][0] - h0, acc[nb][1] - h1);
        *(uint32_t*)(xL + (r0 + 8) * STW + c) = bf2_pack(acc[nb][2] - h2, acc[nb][3] - h3);
    }
    __syncthreads();

    // ---- fMS = relu(ln2d(S @ fM)) -> global bf16 hi/lo ----
    mm_frag<4, 2, true, STN, STW>(acc, sH, sL, xH, xL, rw, wn32, lane);
    ln2048_relu(acc, red);
#pragma unroll
    for (int nb = 0; nb < 4; nb++) {
        int c = wn32 + nb * 8 + lc;
        int r0 = rw + lr;
        size_t o0 = bg * 2048 + (size_t)r0 * 64 + c;
        size_t o1 = bg * 2048 + (size_t)(r0 + 8) * 64 + c;
        *(uint32_t*)(g_FMSh + o0) = bf2_pack(acc[nb][0], acc[nb][1]);
        *(uint32_t*)(g_FMSh + o1) = bf2_pack(acc[nb][2], acc[nb][3]);
        float h0 = __bfloat162float(__float2bfloat16(acc[nb][0]));
        float h1 = __bfloat162float(__float2bfloat16(acc[nb][1]));
        float h2 = __bfloat162float(__float2bfloat16(acc[nb][2]));
        float h3 = __bfloat162float(__float2bfloat16(acc[nb][3]));
        *(uint32_t*)(g_FMSl + o0) = bf2_pack(acc[nb][0] - h0, acc[nb][1] - h1);
        *(uint32_t*)(g_FMSl + o1) = bf2_pack(acc[nb][2] - h2, acc[nb][3] - h3);
    }
    // Vw into w (M dead: all warps passed post-fM barrier; mm2 doesn't read w)
    load_split_smem<64, STW>(g_V + bg * 4096, 4096, wH, wL, tid);
    __syncthreads();

    // ---- v = relu(ln2d(f @ Vw)) -> x ----
    mm_frag<4, 4, true, STW, STW>(acc, fH, fL, wH, wL, rw, wn32, lane);
    ln2048_relu(acc, red);
    __syncthreads();  // everyone done reading f (and x from mm2)
#pragma unroll
    for (int nb = 0; nb < 4; nb++) {
        int c = wn32 + nb * 8 + lc;
        int r0 = rw + lr;
        *(uint32_t*)(xH + r0 * STW + c)       = bf2_pack(acc[nb][0], acc[nb][1]);
        *(uint32_t*)(xH + (r0 + 8) * STW + c) = bf2_pack(acc[nb][2], acc[nb][3]);
        float h0 = __bfloat162float(__float2bfloat16(acc[nb][0]));
        float h1 = __bfloat162float(__float2bfloat16(acc[nb][1]));
        float h2 = __bfloat162float(__float2bfloat16(acc[nb][2]));
        float h3 = __bfloat162float(__float2bfloat16(acc[nb][3]));
        *(uint32_t*)(xL + r0 * STW + c)       = bf2_pack(acc[nb][0] - h0, acc[nb][1] - h1);
        *(uint32_t*)(xL + (r0 + 8) * STW + c) = bf2_pack(acc[nb][2] - h2, acc[nb][3] - h3);
    }
    // kw into f (f dead now)
    load_split_smem<64, STW>(kw_g + g * 2048, 2048, fH, fL, tid);
    __syncthreads();

    float a2[2][4];

    // ---- k[i][p] = kw @ v^T + kb -> kH/kL (B = v non-trans) ----
    mm_frag<2, 4, false, STW, STW>(a2, fH, fL, xH, xL, rw, wn16, lane);
    {
        int r0 = rw + lr;
        float b0 = __ldg(kb_g + g * 32 + r0);
        float b1 = __ldg(kb_g + g * 32 + r0 + 8);
#pragma unroll
        for (int nb = 0; nb < 2; nb++) {
            int c = wn16 + nb * 8 + lc;
            float v0 = a2[nb][0] + b0, v1 = a2[nb][1] + b0;
            float v2 = a2[nb][2] + b1, v3 = a2[nb][3] + b1;
            *(uint32_t*)(kH + r0 * STN + c)       = bf2_pack(v0, v1);
            *(uint32_t*)(kH + (r0 + 8) * STN + c) = bf2_pack(v2, v3);
            float h0 = __bfloat162float(__float2bfloat16(v0));
            float h1 = __bfloat162float(__float2bfloat16(v1));
            float h2 = __bfloat162float(__float2bfloat16(v2));
            float h3 = __bfloat162float(__float2bfloat16(v3));
            *(uint32_t*)(kL + r0 * STN + c)       = bf2_pack(v0 - h0, v1 - h1);
            *(uint32_t*)(kL + (r0 + 8) * STN + c) = bf2_pack(v2 - h2, v3 - h3);
        }
    }
    __syncthreads();

    // ---- scores = q @ k -> sc (fp32) ----
    mm_frag<2, 2, true, STN, STN>(a2, qH, qL, kH, kL, rw, wn16, lane);
    {
        int r0 = rw + lr;
#pragma unroll
        for (int nb = 0; nb < 2; nb++) {
            int c = wn16 + nb * 8 + lc;
            *(float2*)(sc + r0 * 36 + c)       = make_float2(a2[nb][0], a2[nb][1]);
            *(float2*)(sc + (r0 + 8) * 36 + c) = make_float2(a2[nb][2], a2[nb][3]);
        }
    }
    __syncthreads();

    // ---- softmax(sc / 8) -> att (bf16 hi/lo in s buffers; S dead) ----
    {
        const int tx8 = tid & 7, ty16 = tid >> 3;
#pragma unroll
        for (int i = 0; i < 2; i++) {
            int row = 2 * ty16 + i;
            float v[4];
#pragma unroll
            for (int j = 0; j < 4; j++) v[j] = sc[row * 36 + 4 * tx8 + j];
            float m = fmaxf(fmaxf(v[0], v[1]), fmaxf(v[2], v[3]));
#pragma unroll
            for (int o = 4; o > 0; o >>= 1)
                m = fmaxf(m, __shfl_xor_sync(0xffffffffu, m, o));
            float s = 0.f;
#pragma unroll
            for (int j = 0; j < 4; j++) { v[j] = __expf((v[j] - m) * 0.125f); s += v[j]; }
#pragma unroll
            for (int o = 4; o > 0; o >>= 1)
                s += __shfl_xor_sync(0xffffffffu, s, o);
            float inv = __frcp_rn(s);
#pragma unroll
            for (int j = 0; j < 4; j++) {
                float p = v[j] * inv;
                __nv_bfloat16 h, l;
                split_bf16(p, h, l);
                sH[row * STN + 4 * tx8 + j] = h;
                sL[row * STN + 4 * tx8 + j] = l;
            }
        }
    }
    __syncthreads();

    // ---- fc = relu(ln2d(att @ v)) -> global bf16 hi/lo ----
    mm_frag<4, 2, true, STN, STW>(acc, sH, sL, xH, xL, rw, wn32, lane);
    ln2048_relu(acc, red);
#pragma unroll
    for (int nb = 0; nb < 4; nb++) {
        int c = wn32 + nb * 8 + lc;
        int r0 = rw + lr;
        size_t o0 = bg * 2048 + (size_t)r0 * 64 + c;
        size_t o1 = bg * 2048 + (size_t)(r0 + 8) * 64 + c;
        *(uint32_t*)(g_FCh + o0) = bf2_pack(acc[nb][0], acc[nb][1]);
        *(uint32_t*)(g_FCh + o1) = bf2_pack(acc[nb][2], acc[nb][3]);
        float h0 = __bfloat162float(__float2bfloat16(acc[nb][0]));
        float h1 = __bfloat162float(__float2bfloat16(acc[nb][1]));
        float h2 = __bfloat162float(__float2bfloat16(acc[nb][2]));
        float h3 = __bfloat162float(__float2bfloat16(acc[nb][3]));
        *(uint32_t*)(g_FCl + o0) = bf2_pack(acc[nb][0] - h0, acc[nb][1] - h1);
        *(uint32_t*)(g_FCl + o1) = bf2_pack(acc[nb][2] - h2, acc[nb][3] - h3);
    }
}

// ============== residual + split-K reduce + affine LayerNorm ===============
__global__ void __launch_bounds__(256) final_ln(
    const float* __restrict__ qv,
    const float* __restrict__ wA, const float* __restrict__ bA,
    const float* __restrict__ wB, const float* __restrict__ bB,
    float* __restrict__ out)
{
    const int r = blockIdx.x, z = blockIdx.y, c = threadIdx.x;
    const float* w = z ? wB : wA;
    const float* b = z ? bB : bA;
    float x = qv[(size_t)r * 256 + c];
#pragma unroll
    for (int k = 0; k < 8; k++)
        x += g_P[(size_t)(z * 8 + k) * 614400 + (size_t)r * 256 + c];

    __shared__ float sred[16];
    float s = x, q = x * x;
#pragma unroll
    for (int o = 16; o > 0; o >>= 1) {
        s += __shfl_xor_sync(0xffffffffu, s, o);
        q += __shfl_xor_sync(0xffffffffu, q, o);
    }
    int wp = threadIdx.x >> 5;
    if ((threadIdx.x & 31) == 0) { sred[wp] = s; sred[8 + wp] = q; }
    __syncthreads();
    float S = 0.f, Q2 = 0.f;
#pragma unroll
    for (int i = 0; i < 8; i++) { S += sred[i]; Q2 += sred[8 + i]; }
    float mean = S * (1.f / 256.f);
    float var  = Q2 * (1.f / 256.f) - mean * mean;
    float inv  = rsqrtf(var + 1e-5f);
    out[(size_t)z * 614400 + (size_t)r * 256 + c] = (x - mean) * inv * w[c] + b[c];
}

// ================================ launcher =================================
extern "C" void kernel_launch(void* const* d_in, const int* in_sizes, int n_in,
                              void* d_out, int out_size)
{
    const float* feats = (const float*)d_in[0];
    const float* qv    = (const float*)d_in[1];
    const float* m_w   = (const float*)d_in[7];
    const float* m_b   = (const float*)d_in[8];
    const float* s_w   = (const float*)d_in[9];
    const float* s_b   = (const float*)d_in[10];
    const float* q_w   = (const float*)d_in[11];
    const float* q_b   = (const float*)d_in[12];
    const float* v_w   = (const float*)d_in[13];
    const float* v_b   = (const float*)d_in[14];
    const float* k_w   = (const float*)d_in[15];
    const float* k_b   = (const float*)d_in[16];
    const float* Wv_w  = (const float*)d_in[17];
    const float* Wv_b  = (const float*)d_in[18];
    const float* Wv2_w = (const float*)d_in[19];
    const float* Wv2_b = (const float*)d_in[20];
    const float* lnA_w = (const float*)d_in[21];
    const float* lnA_b = (const float*)d_in[22];
    const float* lnB_w = (const float*)d_in[23];
    const float* lnB_b = (const float*)d_in[24];
    float* out = (float*)d_out;

    float *gM, *gV, *gS, *gQ, *gP;
    cudaGetSymbolAddress((void**)&gM, g_M);
    cudaGetSymbolAddress((void**)&gV, g_V);
    cudaGetSymbolAddress((void**)&gS, g_S);
    cudaGetSymbolAddress((void**)&gQ, g_Q);
    cudaGetSymbolAddress((void**)&gP, g_P);
    __nv_bfloat16 *qvh, *qvl, *mwh, *mwl, *vwh, *vwl, *swh, *swl, *qwh, *qwl;
    __nv_bfloat16 *Wvh, *Wvl, *W2h, *W2l, *FMSh, *FMSl, *FCh, *FCl;
    cudaGetSymbolAddress((void**)&qvh, g_qvh);   cudaGetSymbolAddress((void**)&qvl, g_qvl);
    cudaGetSymbolAddress((void**)&mwh, g_mwh);   cudaGetSymbolAddress((void**)&mwl, g_mwl);
    cudaGetSymbolAddress((void**)&vwh, g_vwh);   cudaGetSymbolAddress((void**)&vwl, g_vwl);
    cudaGetSymbolAddress((void**)&swh, g_swh);   cudaGetSymbolAddress((void**)&swl, g_swl);
    cudaGetSymbolAddress((void**)&qwh, g_qwh);   cudaGetSymbolAddress((void**)&qwl, g_qwl);
    cudaGetSymbolAddress((void**)&Wvh, g_Wvh);   cudaGetSymbolAddress((void**)&Wvl, g_Wvl);
    cudaGetSymbolAddress((void**)&W2h, g_W2h);   cudaGetSymbolAddress((void**)&W2l, g_W2l);
    cudaGetSymbolAddress((void**)&FMSh, g_FMSh); cudaGetSymbolAddress((void**)&FMSl, g_FMSl);
    cudaGetSymbolAddress((void**)&FCh, g_FCh);   cudaGetSymbolAddress((void**)&FCl, g_FCl);

    cudaFuncSetAttribute(fused_bg, cudaFuncAttributeMaxDynamicSharedMemorySize, FUSED_SMEM);

    // 0) split fp32 operands into bf16 hi/lo
    split_kernel<<<dim3(4096, 1, 7), 256>>>(qv, m_w, v_w, s_w, q_w, Wv_w, Wv2_w);

    // 1) M / V generators: (2400x256) @ (16384x256)^T, K=256
    hmma_gemm<<<dim3(128, 19, 2), 256>>>(
        qvh, qvl, mwh, mwl, m_b, gM,
        qvh, qvl, vwh, vwl, v_b, gV,
        2400, 16384, 256, 256, 1, 0);

    // 2) S / Q generators: (2400x256) @ (4096x256)^T, K=256
    hmma_gemm<<<dim3(32, 19, 2), 256>>>(
        qvh, qvl, swh, swl, s_b, gS,
        qvh, qvl, qwh, qwl, q_b, gQ,
        2400, 4096, 256, 256, 1, 0);

    // 3) fused per-(bn,g) dynamic conv + attention (full HMMA)
    fused_bg<<<dim3(2400, 4), 128, FUSED_SMEM>>>(feats, k_w, k_b);

    // 4) output projections: (2400x8192) @ (256x8192)^T, split-K=8
    hmma_gemm<<<dim3(2, 19, 16), 256>>>(
        FMSh, FMSl, Wvh, Wvl, Wv_b, gP,
        FCh,  FCl,  W2h, W2l, Wv2_b, gP + 8 * 614400,
        2400, 256, 8192, 1024, 8, 614400);

    // 5) residual + split-K reduce + affine LayerNorm
    final_ln<<<dim3(2400, 2), 256>>>(qv, lnA_w, lnA_b, lnB_w, lnB_b, out);
}

// round 8
// speedup vs baseline: 2.1776x; 1.0560x over previous
#include <cuda_runtime.h>
#include <cuda_bf16.h>
#include <cstdint>

// ============================ problem constants ============================
// B=8, N=300 -> BN=2400; G=4; P=O=32; CG=DG=64; IN_DIM=OUT_DIM=256; TEMPER=8

// ===================== scratch (__device__ globals) ========================
__device__ float g_P[9830400];    // 16 split-K slices of (2400,256)

__device__ __nv_bfloat16 g_Mh[39321600], g_Ml[39321600];  // (bn, g*4096+c*64+d)
__device__ __nv_bfloat16 g_Vh[39321600], g_Vl[39321600];
__device__ __nv_bfloat16 g_Sh[9830400],  g_Sl[9830400];   // (bn, g*1024+o*32+p)
__device__ __nv_bfloat16 g_Qh[9830400],  g_Ql[9830400];

__device__ __nv_bfloat16 g_qvh[614400],  g_qvl[614400];
__device__ __nv_bfloat16 g_mwh[4194304], g_mwl[4194304];
__device__ __nv_bfloat16 g_vwh[4194304], g_vwl[4194304];
__device__ __nv_bfloat16 g_swh[1048576], g_swl[1048576];
__device__ __nv_bfloat16 g_qwh[1048576], g_qwl[1048576];
__device__ __nv_bfloat16 g_Wvh[2097152], g_Wvl[2097152];
__device__ __nv_bfloat16 g_W2h[2097152], g_W2l[2097152];
__device__ __nv_bfloat16 g_FMSh[19660800], g_FMSl[19660800];
__device__ __nv_bfloat16 g_FCh[19660800],  g_FCl[19660800];

// ============================ small helpers ================================
__device__ __forceinline__ uint32_t smem_u32(const void* p) {
    uint32_t a;
    asm("{ .reg .u64 t; cvta.to.shared.u64 t, %1; cvt.u32.u64 %0, t; }"
        : "=r"(a) : "l"(p));
    return a;
}
__device__ __forceinline__ void split_bf16(float x, __nv_bfloat16& h, __nv_bfloat16& l) {
    h = __float2bfloat16(x);
    l = __float2bfloat16(x - __bfloat162float(h));
}
__device__ __forceinline__ void ldmx4(uint32_t r[4], uint32_t addr) {
    asm volatile("ldmatrix.sync.aligned.m8n8.x4.shared.b16 {%0,%1,%2,%3}, [%4];"
                 : "=r"(r[0]), "=r"(r[1]), "=r"(r[2]), "=r"(r[3]) : "r"(addr));
}
__device__ __forceinline__ void ldmx4_t(uint32_t r[4], uint32_t addr) {
    asm volatile("ldmatrix.sync.aligned.m8n8.x4.trans.shared.b16 {%0,%1,%2,%3}, [%4];"
                 : "=r"(r[0]), "=r"(r[1]), "=r"(r[2]), "=r"(r[3]) : "r"(addr));
}
__device__ __forceinline__ void mma_bf16(float d[4], const uint32_t a[4],
                                         const uint32_t b0, const uint32_t b1) {
    asm volatile(
        "mma.sync.aligned.m16n8k16.row.col.f32.bf16.bf16.f32 "
        "{%0,%1,%2,%3}, {%4,%5,%6,%7}, {%8,%9}, {%0,%1,%2,%3};"
        : "+f"(d[0]), "+f"(d[1]), "+f"(d[2]), "+f"(d[3])
        : "r"(a[0]), "r"(a[1]), "r"(a[2]), "r"(a[3]), "r"(b0), "r"(b1));
}
__device__ __forceinline__ uint32_t bf2_pack(float a, float b) {
    union { __nv_bfloat16 h[2]; uint32_t u; } U;
    U.h[0] = __float2bfloat16(a); U.h[1] = __float2bfloat16(b);
    return U.u;
}
// split two floats: returns hi-pair packed, lo-pair packed
__device__ __forceinline__ void split2_pack(float a, float b, uint32_t& hp, uint32_t& lp) {
    __nv_bfloat16 ha = __float2bfloat16(a), hb = __float2bfloat16(b);
    union { __nv_bfloat16 h[2]; uint32_t u; } H, L;
    H.h[0] = ha; H.h[1] = hb;
    L.h[0] = __float2bfloat16(a - __bfloat162float(ha));
    L.h[1] = __float2bfloat16(b - __bfloat162float(hb));
    hp = H.u; lp = L.u;
}

// ================= operand split prep (fp32 -> bf16 hi/lo) =================
__global__ void __launch_bounds__(256) split_kernel(
    const float* __restrict__ qv, const float* __restrict__ mw,
    const float* __restrict__ vw, const float* __restrict__ sw,
    const float* __restrict__ qw, const float* __restrict__ Wv,
    const float* __restrict__ W2)
{
    const float* src; __nv_bfloat16 *dh, *dl; int n;
    switch (blockIdx.z) {
        case 0: src = qv; dh = g_qvh; dl = g_qvl; n = 614400;  break;
        case 1: src = mw; dh = g_mwh; dl = g_mwl; n = 4194304; break;
        case 2: src = vw; dh = g_vwh; dl = g_vwl; n = 4194304; break;
        case 3: src = sw; dh = g_swh; dl = g_swl; n = 1048576; break;
        case 4: src = qw; dh = g_qwh; dl = g_qwl; n = 1048576; break;
        case 5: src = Wv; dh = g_Wvh; dl = g_Wvl; n = 2097152; break;
        default:src = W2; dh = g_W2h; dl = g_W2l; n = 2097152; break;
    }
    int i = (blockIdx.x * 256 + threadIdx.x) * 4;
    if (i >= n) return;
    float4 v = *(const float4*)(src + i);
    union U { __nv_bfloat16 b[4]; uint2 u; } H, L;
    split_bf16(v.x, H.b[0], L.b[0]);
    split_bf16(v.y, H.b[1], L.b[1]);
    split_bf16(v.z, H.b[2], L.b[2]);
    split_bf16(v.w, H.b[3], L.b[3]);
    *(uint2*)(dh + i) = H.u;
    *(uint2*)(dl + i) = L.u;
}

// ============ HMMA bf16x3 NT GEMM: C[M,Nout] = A@W^T (+bias @ks==0) ========
// OBF: write bf16 hi/lo pair outputs instead of fp32.
static constexpr int RS = 40;

template<bool OBF>
__global__ void __launch_bounds__(256) hmma_gemm(
    const __nv_bfloat16* __restrict__ Ah0, const __nv_bfloat16* __restrict__ Al0,
    const __nv_bfloat16* __restrict__ Wh0, const __nv_bfloat16* __restrict__ Wl0,
    const float* __restrict__ b0, float* __restrict__ C0,
    __nv_bfloat16* __restrict__ Ch0, __nv_bfloat16* __restrict__ Cl0,
    const __nv_bfloat16* __restrict__ Ah1, const __nv_bfloat16* __restrict__ Al1,
    const __nv_bfloat16* __restrict__ Wh1, const __nv_bfloat16* __restrict__ Wl1,
    const float* __restrict__ b1, float* __restrict__ C1,
    __nv_bfloat16* __restrict__ Ch1, __nv_bfloat16* __restrict__ Cl1,
    int M, int Nout, int lda, int kPerCta, int splitk, size_t sliceStride)
{
    __shared__ __align__(16) __nv_bfloat16 sAh[128 * RS];
    __shared__ __align__(16) __nv_bfloat16 sAl[128 * RS];
    __shared__ __align__(16) __nv_bfloat16 sBh[128 * RS];
    __shared__ __align__(16) __nv_bfloat16 sBl[128 * RS];

    const int tid = threadIdx.x, wid = tid >> 5, lane = tid & 31;
    const int z  = blockIdx.z / splitk;
    const int ks = blockIdx.z % splitk;
    const __nv_bfloat16* Ah = z ? Ah1 : Ah0;
    const __nv_bfloat16* Al = z ? Al1 : Al0;
    const __nv_bfloat16* Wh = z ? Wh1 : Wh0;
    const __nv_bfloat16* Wl = z ? Wl1 : Wl0;
    const float* bias = z ? b1 : b0;
    float* Cp = (z ? C1 : C0) + (size_t)ks * sliceStride;
    __nv_bfloat16* Chp = z ? Ch1 : Ch0;
    __nv_bfloat16* Clp = z ? Cl1 : Cl0;

    const int m0 = blockIdx.y * 128;
    const int n0 = blockIdx.x * 128;
    const int kBegin = ks * kPerCta;
    const int NC = kPerCta / 32;

    const int wm = (wid & 3) * 32;
    const int wn = (wid >> 2) * 64;

    const int lrow = tid >> 2;
    const int lseg = (tid & 3) * 8;

    float acc[2][8][4];
#pragma unroll
    for (int i = 0; i < 2; i++)
#pragma unroll
        for (int j = 0; j < 8; j++)
#pragma unroll
            for (int q = 0; q < 4; q++) acc[i][j][q] = 0.f;

    uint4 rA[2], rAl[2], rB[2], rBl[2];

    auto load_regs = [&](int c) {
        const int kk = kBegin + c * 32;
#pragma unroll
        for (int j = 0; j < 2; j++) {
            int row = lrow + 64 * j;
            int gm = m0 + row;
            if (gm < M) {
                size_t go = (size_t)gm * lda + kk + lseg;
                rA[j]  = *(const uint4*)(Ah + go);
                rAl[j] = *(const uint4*)(Al + go);
            } else {
                rA[j] = rAl[j] = make_uint4(0u, 0u, 0u, 0u);
            }
            size_t gw = (size_t)(n0 + row) * lda + kk + lseg;
            rB[j]  = *(const uint4*)(Wh + gw);
            rBl[j] = *(const uint4*)(Wl + gw);
        }
    };
    auto store_smem = [&]() {
#pragma unroll
        for (int j = 0; j < 2; j++) {
            int off = (lrow + 64 * j) * RS + lseg;
            *(uint4*)(sAh + off) = rA[j];
            *(uint4*)(sAl + off) = rAl[j];
            *(uint4*)(sBh + off) = rB[j];
            *(uint4*)(sBl + off) = rBl[j];
        }
    };

    const uint32_t uAh = smem_u32(sAh), uAl = smem_u32(sAl);
    const uint32_t uBh = smem_u32(sBh), uBl = smem_u32(sBl);
    const int arow = lane & 15, acol = (lane >> 4) * 8;
    const int bgrp = lane >> 3, brow = lane & 7;
    const int bn_off = (bgrp >> 1) * 8 + brow;
    const int bk_off = (bgrp & 1) * 8;

    load_regs(0);

    for (int c = 0; c < NC; c++) {
        store_smem();
        __syncthreads();
        if (c + 1 < NC) load_regs(c + 1);

#pragma unroll
        for (int ksp = 0; ksp < 2; ksp++) {
            uint32_t fAh[2][4], fAl[2][4], fBh[4][4], fBl[4][4];
#pragma unroll
            for (int mi = 0; mi < 2; mi++) {
                uint32_t off = 2u * ((wm + mi * 16 + arow) * RS + ksp * 16 + acol);
                ldmx4(fAh[mi], uAh + off);
                ldmx4(fAl[mi], uAl + off);
            }
#pragma unroll
            for (int nb = 0; nb < 4; nb++) {
                uint32_t off = 2u * ((wn + nb * 16 + bn_off) * RS + ksp * 16 + bk_off);
                ldmx4(fBh[nb], uBh + off);
                ldmx4(fBl[nb], uBl + off);
            }
#pragma unroll
            for (int mi = 0; mi < 2; mi++)
#pragma unroll
                for (int nf = 0; nf < 8; nf++) {
                    const uint32_t* bh = &fBh[nf >> 1][(nf & 1) * 2];
                    const uint32_t* bl = &fBl[nf >> 1][(nf & 1) * 2];
                    mma_bf16(acc[mi][nf], fAh[mi], bh[0], bh[1]);
                    mma_bf16(acc[mi][nf], fAl[mi], bh[0], bh[1]);
                    mma_bf16(acc[mi][nf], fAh[mi], bl[0], bl[1]);
                }
        }
        __syncthreads();
    }

    const bool addB = (ks == 0);
    const int erow = lane >> 2, ecol = (lane & 3) * 2;
#pragma unroll
    for (int mi = 0; mi < 2; mi++) {
        int r0 = m0 + wm + mi * 16 + erow;
#pragma unroll
        for (int half = 0; half < 2; half++) {
            int r = r0 + half * 8;
            if (r >= M) continue;
#pragma unroll
            for (int nf = 0; nf < 8; nf++) {
                int col = n0 + wn + nf * 8 + ecol;
                float x0 = acc[mi][nf][half * 2 + 0];
                float x1 = acc[mi][nf][half * 2 + 1];
                if (addB) { x0 += __ldg(bias + col); x1 += __ldg(bias + col + 1); }
                if (OBF) {
                    uint32_t hp, lp;
                    split2_pack(x0, x1, hp, lp);
                    size_t o = (size_t)r * Nout + col;
                    *(uint32_t*)(Chp + o) = hp;
                    *(uint32_t*)(Clp + o) = lp;
                } else {
                    *(float2*)(Cp + (size_t)r * Nout + col) = make_float2(x0, x1);
                }
            }
        }
    }
}

// ================== fused per-(bn,g) kernel (full HMMA) ====================
static constexpr int STW = 72;
static constexpr int STN = 40;
static constexpr int O_FH = 0;          // f hi        32*72
static constexpr int O_FL = 2304;
static constexpr int O_WH = 4608;       // M/Vw hi     64*72
static constexpr int O_WL = 9216;
static constexpr int O_XH = 13824;      // fM/v hi     32*72
static constexpr int O_XL = 16128;
static constexpr int O_SH = 18432;      // S/att hi    32*40
static constexpr int O_SL = 19712;
static constexpr int O_QH = 20992;      // q hi
static constexpr int O_QL = 22272;
static constexpr int O_KH = 23552;      // k hi
static constexpr int O_KL = 24832;
static constexpr int BF_ELEMS = 26112;
static constexpr int FUSED_SMEM = BF_ELEMS * 2 + 32 * 36 * 4 + 32;

__device__ __forceinline__ void ln2048_relu(float acc[4][4], float* red) {
    float s = 0.f, q = 0.f;
#pragma unroll
    for (int i = 0; i < 4; i++)
#pragma unroll
        for (int j = 0; j < 4; j++) { s += acc[i][j]; q += acc[i][j] * acc[i][j]; }
#pragma unroll
    for (int o = 16; o > 0; o >>= 1) {
        s += __shfl_xor_sync(0xffffffffu, s, o);
        q += __shfl_xor_sync(0xffffffffu, q, o);
    }
    int w = threadIdx.x >> 5;
    __syncthreads();
    if ((threadIdx.x & 31) == 0) { red[w] = s; red[4 + w] = q; }
    __syncthreads();
    s = red[0] + red[1] + red[2] + red[3];
    q = red[4] + red[5] + red[6] + red[7];
    float mean = s * (1.f / 2048.f);
    float var  = q * (1.f / 2048.f) - mean * mean;
    float inv  = rsqrtf(var + 1e-5f);
#pragma unroll
    for (int i = 0; i < 4; i++)
#pragma unroll
        for (int j = 0; j < 4; j++)
            acc[i][j] = fmaxf((acc[i][j] - mean) * inv, 0.f);
}

template<int NB, int KT, bool TRANS, int SA, int SB>
__device__ __forceinline__ void mm_frag(float acc[NB][4],
    const __nv_bfloat16* AH, const __nv_bfloat16* AL,
    const __nv_bfloat16* BH, const __nv_bfloat16* BL,
    int rw, int wn, int lane)
{
    const int arow = lane & 15, acol8 = (lane >> 4) * 8;
    const int b1 = ((lane >> 4) << 3) + (lane & 7);
    const int b2 = ((lane >> 3) & 1) * 8;
#pragma unroll
    for (int i = 0; i < NB; i++)
#pragma unroll
        for (int j = 0; j < 4; j++) acc[i][j] = 0.f;
#pragma unroll
    for (int kt = 0; kt < KT; kt++) {
        uint32_t aH[4], aL[4];
        ldmx4(aH, smem_u32(AH + (rw + arow) * SA + kt * 16 + acol8));
        ldmx4(aL, smem_u32(AL + (rw + arow) * SA + kt * 16 + acol8));
#pragma unroll
        for (int nt = 0; nt < NB / 2; nt++) {
            uint32_t bH[4], bL[4];
            if (TRANS) {
                ldmx4_t(bH, smem_u32(BH + (kt * 16 + b1) * SB + wn + nt * 16 + b2));
                ldmx4_t(bL, smem_u32(BL + (kt * 16 + b1) * SB + wn + nt * 16 + b2));
            } else {
                ldmx4(bH, smem_u32(BH + (wn + nt * 16 + b1) * SB + kt * 16 + b2));
                ldmx4(bL, smem_u32(BL + (wn + nt * 16 + b1) * SB + kt * 16 + b2));
            }
#pragma unroll
            for (int h = 0; h < 2; h++) {
                int nb = nt * 2 + h;
                uint32_t h0, h1, l0, l1;
                if (TRANS) { h0 = bH[h]; h1 = bH[h + 2]; l0 = bL[h]; l1 = bL[h + 2]; }
                else       { h0 = bH[2 * h]; h1 = bH[2 * h + 1];
                             l0 = bL[2 * h]; l1 = bL[2 * h + 1]; }
                mma_bf16(acc[nb], aH, h0, h1);
                mma_bf16(acc[nb], aL, h0, h1);
                mma_bf16(acc[nb], aH, l0, l1);
            }
        }
    }
}

// fp32 global -> smem bf16 hi/lo with padded stride
template<int W, int ST>
__device__ __forceinline__ void load_split_smem(const float* __restrict__ src, int n,
                                                __nv_bfloat16* dh, __nv_bfloat16* dl,
                                                int tid)
{
#pragma unroll
    for (int idx = tid * 4; idx < n; idx += 512) {
        int row = idx / W, col = idx % W;
        float4 v = *(const float4*)(src + idx);
        union U { __nv_bfloat16 b[4]; uint2 u; } H, L;
        split_bf16(v.x, H.b[0], L.b[0]);
        split_bf16(v.y, H.b[1], L.b[1]);
        split_bf16(v.z, H.b[2], L.b[2]);
        split_bf16(v.w, H.b[3], L.b[3]);
        *(uint2*)(dh + row * ST + col) = H.u;
        *(uint2*)(dl + row * ST + col) = L.u;
    }
}

// bf16 hi/lo global -> smem with padded stride (pure copy)
template<int W, int ST>
__device__ __forceinline__ void load_bf16_smem(const __nv_bfloat16* __restrict__ srcH,
                                               const __nv_bfloat16* __restrict__ srcL,
                                               int n, __nv_bfloat16* dh,
                                               __nv_bfloat16* dl, int tid)
{
#pragma unroll
    for (int idx = tid * 8; idx < n; idx += 1024) {
        int row = idx / W, col = idx % W;
        *(uint4*)(dh + row * ST + col) = *(const uint4*)(srcH + idx);
        *(uint4*)(dl + row * ST + col) = *(const uint4*)(srcL + idx);
    }
}

__global__ void __launch_bounds__(128, 4) fused_bg(
    const float* __restrict__ feats,
    const float* __restrict__ kw_g, const float* __restrict__ kb_g)
{
    extern __shared__ char dynsm[];
    __nv_bfloat16* bfb = (__nv_bfloat16*)dynsm;
    __nv_bfloat16 *fH = bfb + O_FH, *fL = bfb + O_FL;
    __nv_bfloat16 *wH = bfb + O_WH, *wL = bfb + O_WL;
    __nv_bfloat16 *xH = bfb + O_XH, *xL = bfb + O_XL;
    __nv_bfloat16 *sH = bfb + O_SH, *sL = bfb + O_SL;
    __nv_bfloat16 *qH = bfb + O_QH, *qL = bfb + O_QL;
    __nv_bfloat16 *kH = bfb + O_KH, *kL = bfb + O_KL;
    float* sc  = (float*)(dynsm + BF_ELEMS * 2);
    float* red = sc + 32 * 36;

    const int bn = blockIdx.x, g = blockIdx.y;
    const int tid = threadIdx.x;
    const int lane = tid & 31, wrp = tid >> 5;
    const int rw   = (wrp & 1) * 16;
    const int wn32 = (wrp >> 1) * 32;
    const int wn16 = (wrp >> 1) * 16;
    const int lr = lane >> 2, lc = 2 * (lane & 3);
    const size_t bg = (size_t)bn * 4 + g;

    // ---- prefetch V tile into registers (DRAM latency overlapped w/ stage 1)
    uint4 pvH[4], pvL[4];
    {
        const uint4* vh = (const uint4*)(g_Vh + bg * 4096 + tid * 32);
        const uint4* vl = (const uint4*)(g_Vl + bg * 4096 + tid * 32);
#pragma unroll
        for (int j = 0; j < 4; j++) { pvH[j] = vh[j]; pvL[j] = vl[j]; }
    }

    // ---- stage inputs: f (fp32 split), M / S / q (bf16 copies) ----
    load_split_smem<64, STW>(feats + bg * 2048, 2048, fH, fL, tid);
    load_bf16_smem<64, STW>(g_Mh + bg * 4096, g_Ml + bg * 4096, 4096, wH, wL, tid);
    load_bf16_smem<32, STN>(g_Sh + bg * 1024, g_Sl + bg * 1024, 1024, sH, sL, tid);
    load_bf16_smem<32, STN>(g_Qh + bg * 1024, g_Ql + bg * 1024, 1024, qH, qL, tid);
    __syncthreads();

    float acc[4][4];

    // ---- fM = relu(ln2d(f @ M)) -> x ----
    mm_frag<4, 4, true, STW, STW>(acc, fH, fL, wH, wL, rw, wn32, lane);
    ln2048_relu(acc, red);
    // w buffer dead (all warps past ln's first barrier) -> deposit prefetched V
    {
        int vrow = tid >> 1, vcb = (tid & 1) * 32;
#pragma unroll
        for (int j = 0; j < 4; j++) {
            *(uint4*)(wH + vrow * STW + vcb + j * 8) = pvH[j];
            *(uint4*)(wL + vrow * STW + vcb + j * 8) = pvL[j];
        }
    }
#pragma unroll
    for (int nb = 0; nb < 4; nb++) {
        int c = wn32 + nb * 8 + lc;
        int r0 = rw + lr;
        uint32_t hp, lp;
        split2_pack(acc[nb][0], acc[nb][1], hp, lp);
        *(uint32_t*)(xH + r0 * STW + c) = hp;
        *(uint32_t*)(xL + r0 * STW + c) = lp;
        split2_pack(acc[nb][2], acc[nb][3], hp, lp);
        *(uint32_t*)(xH + (r0 + 8) * STW + c) = hp;
        *(uint32_t*)(xL + (r0 + 8) * STW + c) = lp;
    }
    __syncthreads();

    // ---- fMS = relu(ln2d(S @ fM)) -> global bf16 hi/lo ----
    mm_frag<4, 2, true, STN, STW>(acc, sH, sL, xH, xL, rw, wn32, lane);
    ln2048_relu(acc, red);
#pragma unroll
    for (int nb = 0; nb < 4; nb++) {
        int c = wn32 + nb * 8 + lc;
        int r0 = rw + lr;
        size_t o0 = bg * 2048 + (size_t)r0 * 64 + c;
        size_t o1 = bg * 2048 + (size_t)(r0 + 8) * 64 + c;
        uint32_t hp, lp;
        split2_pack(acc[nb][0], acc[nb][1], hp, lp);
        *(uint32_t*)(g_FMSh + o0) = hp;
        *(uint32_t*)(g_FMSl + o0) = lp;
        split2_pack(acc[nb][2], acc[nb][3], hp, lp);
        *(uint32_t*)(g_FMSh + o1) = hp;
        *(uint32_t*)(g_FMSl + o1) = lp;
    }
    __syncthreads();

    // ---- v = relu(ln2d(f @ Vw)) -> x ----
    mm_frag<4, 4, true, STW, STW>(acc, fH, fL, wH, wL, rw, wn32, lane);
    ln2048_relu(acc, red);
    __syncthreads();  // all done reading f and x (from fMS stage)
#pragma unroll
    for (int nb = 0; nb < 4; nb++) {
        int c = wn32 + nb * 8 + lc;
        int r0 = rw + lr;
        uint32_t hp, lp;
        split2_pack(acc[nb][0], acc[nb][1], hp, lp);
        *(uint32_t*)(xH + r0 * STW + c) = hp;
        *(uint32_t*)(xL + r0 * STW + c) = lp;
        split2_pack(acc[nb][2], acc[nb][3], hp, lp);
        *(uint32_t*)(xH + (r0 + 8) * STW + c) = hp;
        *(uint32_t*)(xL + (r0 + 8) * STW + c) = lp;
    }
    // kw into f (f dead now)
    load_split_smem<64, STW>(kw_g + g * 2048, 2048, fH, fL, tid);
    __syncthreads();

    float a2[2][4];

    // ---- k[i][p] = kw @ v^T + kb -> kH/kL ----
    mm_frag<2, 4, false, STW, STW>(a2, fH, fL, xH, xL, rw, wn16, lane);
    {
        int r0 = rw + lr;
        float b0 = __ldg(kb_g + g * 32 + r0);
        float b1 = __ldg(kb_g + g * 32 + r0 + 8);
#pragma unroll
        for (int nb = 0; nb < 2; nb++) {
            int c = wn16 + nb * 8 + lc;
            uint32_t hp, lp;
            split2_pack(a2[nb][0] + b0, a2[nb][1] + b0, hp, lp);
            *(uint32_t*)(kH + r0 * STN + c) = hp;
            *(uint32_t*)(kL + r0 * STN + c) = lp;
            split2_pack(a2[nb][2] + b1, a2[nb][3] + b1, hp, lp);
            *(uint32_t*)(kH + (r0 + 8) * STN + c) = hp;
            *(uint32_t*)(kL + (r0 + 8) * STN + c) = lp;
        }
    }
    __syncthreads();

    // ---- scores = q @ k -> sc (fp32) ----
    mm_frag<2, 2, true, STN, STN>(a2, qH, qL, kH, kL, rw, wn16, lane);
    {
        int r0 = rw + lr;
#pragma unroll
        for (int nb = 0; nb < 2; nb++) {
            int c = wn16 + nb * 8 + lc;
            *(float2*)(sc + r0 * 36 + c)       = make_float2(a2[nb][0], a2[nb][1]);
            *(float2*)(sc + (r0 + 8) * 36 + c) = make_float2(a2[nb][2], a2[nb][3]);
        }
    }
    __syncthreads();

    // ---- softmax(sc / 8) -> att (into s buffers) ----
    {
        const int tx8 = tid & 7, ty16 = tid >> 3;
#pragma unroll
        for (int i = 0; i < 2; i++) {
            int row = 2 * ty16 + i;
            float v[4];
#pragma unroll
            for (int j = 0; j < 4; j++) v[j] = sc[row * 36 + 4 * tx8 + j];
            float m = fmaxf(fmaxf(v[0], v[1]), fmaxf(v[2], v[3]));
#pragma unroll
            for (int o = 4; o > 0; o >>= 1)
                m = fmaxf(m, __shfl_xor_sync(0xffffffffu, m, o));
            float s = 0.f;
#pragma unroll
            for (int j = 0; j < 4; j++) { v[j] = __expf((v[j] - m) * 0.125f); s += v[j]; }
#pragma unroll
            for (int o = 4; o > 0; o >>= 1)
                s += __shfl_xor_sync(0xffffffffu, s, o);
            float inv = __frcp_rn(s);
#pragma unroll
            for (int j = 0; j < 4; j++) {
                float p = v[j] * inv;
                __nv_bfloat16 h, l;
                split_bf16(p, h, l);
                sH[row * STN + 4 * tx8 + j] = h;
                sL[row * STN + 4 * tx8 + j] = l;
            }
        }
    }
    __syncthreads();

    // ---- fc = relu(ln2d(att @ v)) -> global bf16 hi/lo ----
    mm_frag<4, 2, true, STN, STW>(acc, sH, sL, xH, xL, rw, wn32, lane);
    ln2048_relu(acc, red);
#pragma unroll
    for (int nb = 0; nb < 4; nb++) {
        int c = wn32 + nb * 8 + lc;
        int r0 = rw + lr;
        size_t o0 = bg * 2048 + (size_t)r0 * 64 + c;
        size_t o1 = bg * 2048 + (size_t)(r0 + 8) * 64 + c;
        uint32_t hp, lp;
        split2_pack(acc[nb][0], acc[nb][1], hp, lp);
        *(uint32_t*)(g_FCh + o0) = hp;
        *(uint32_t*)(g_FCl + o0) = lp;
        split2_pack(acc[nb][2], acc[nb][3], hp, lp);
        *(uint32_t*)(g_FCh + o1) = hp;
        *(uint32_t*)(g_FCl + o1) = lp;
    }
}

// ============== residual + split-K reduce + affine LayerNorm ===============
__global__ void __launch_bounds__(256) final_ln(
    const float* __restrict__ qv,
    const float* __restrict__ wA, const float* __restrict__ bA,
    const float* __restrict__ wB, const float* __restrict__ bB,
    float* __restrict__ out)
{
    const int r = blockIdx.x, z = blockIdx.y, c = threadIdx.x;
    const float* w = z ? wB : wA;
    const float* b = z ? bB : bA;
    float x = qv[(size_t)r * 256 + c];
#pragma unroll
    for (int k = 0; k < 8; k++)
        x += g_P[(size_t)(z * 8 + k) * 614400 + (size_t)r * 256 + c];

    __shared__ float sred[16];
    float s = x, q = x * x;
#pragma unroll
    for (int o = 16; o > 0; o >>= 1) {
        s += __shfl_xor_sync(0xffffffffu, s, o);
        q += __shfl_xor_sync(0xffffffffu, q, o);
    }
    int wp = threadIdx.x >> 5;
    if ((threadIdx.x & 31) == 0) { sred[wp] = s; sred[8 + wp] = q; }
    __syncthreads();
    float S = 0.f, Q2 = 0.f;
#pragma unroll
    for (int i = 0; i < 8; i++) { S += sred[i]; Q2 += sred[8 + i]; }
    float mean = S * (1.f / 256.f);
    float var  = Q2 * (1.f / 256.f) - mean * mean;
    float inv  = rsqrtf(var + 1e-5f);
    out[(size_t)z * 614400 + (size_t)r * 256 + c] = (x - mean) * inv * w[c] + b[c];
}

// ================================ launcher =================================
extern "C" void kernel_launch(void* const* d_in, const int* in_sizes, int n_in,
                              void* d_out, int out_size)
{
    const float* feats = (const float*)d_in[0];
    const float* qv    = (const float*)d_in[1];
    const float* m_w   = (const float*)d_in[7];
    const float* m_b   = (const float*)d_in[8];
    const float* s_w   = (const float*)d_in[9];
    const float* s_b   = (const float*)d_in[10];
    const float* q_w   = (const float*)d_in[11];
    const float* q_b   = (const float*)d_in[12];
    const float* v_w   = (const float*)d_in[13];
    const float* v_b   = (const float*)d_in[14];
    const float* k_w   = (const float*)d_in[15];
    const float* k_b   = (const float*)d_in[16];
    const float* Wv_w  = (const float*)d_in[17];
    const float* Wv_b  = (const float*)d_in[18];
    const float* Wv2_w = (const float*)d_in[19];
    const float* Wv2_b = (const float*)d_in[20];
    const float* lnA_w = (const float*)d_in[21];
    const float* lnA_b = (const float*)d_in[22];
    const float* lnB_w = (const float*)d_in[23];
    const float* lnB_b = (const float*)d_in[24];
    float* out = (float*)d_out;

    float* gP;
    cudaGetSymbolAddress((void**)&gP, g_P);
    __nv_bfloat16 *Mh, *Ml, *Vh, *Vl, *Sh, *Sl, *Qh, *Ql;
    cudaGetSymbolAddress((void**)&Mh, g_Mh); cudaGetSymbolAddress((void**)&Ml, g_Ml);
    cudaGetSymbolAddress((void**)&Vh, g_Vh); cudaGetSymbolAddress((void**)&Vl, g_Vl);
    cudaGetSymbolAddress((void**)&Sh, g_Sh); cudaGetSymbolAddress((void**)&Sl, g_Sl);
    cudaGetSymbolAddress((void**)&Qh, g_Qh); cudaGetSymbolAddress((void**)&Ql, g_Ql);
    __nv_bfloat16 *qvh, *qvl, *mwh, *mwl, *vwh, *vwl, *swh, *swl, *qwh, *qwl;
    __nv_bfloat16 *Wvh, *Wvl, *W2h, *W2l, *FMSh, *FMSl, *FCh, *FCl;
    cudaGetSymbolAddress((void**)&qvh, g_qvh);   cudaGetSymbolAddress((void**)&qvl, g_qvl);
    cudaGetSymbolAddress((void**)&mwh, g_mwh);   cudaGetSymbolAddress((void**)&mwl, g_mwl);
    cudaGetSymbolAddress((void**)&vwh, g_vwh);   cudaGetSymbolAddress((void**)&vwl, g_vwl);
    cudaGetSymbolAddress((void**)&swh, g_swh);   cudaGetSymbolAddress((void**)&swl, g_swl);
    cudaGetSymbolAddress((void**)&qwh, g_qwh);   cudaGetSymbolAddress((void**)&qwl, g_qwl);
    cudaGetSymbolAddress((void**)&Wvh, g_Wvh);   cudaGetSymbolAddress((void**)&Wvl, g_Wvl);
    cudaGetSymbolAddress((void**)&W2h, g_W2h);   cudaGetSymbolAddress((void**)&W2l, g_W2l);
    cudaGetSymbolAddress((void**)&FMSh, g_FMSh); cudaGetSymbolAddress((void**)&FMSl, g_FMSl);
    cudaGetSymbolAddress((void**)&FCh, g_FCh);   cudaGetSymbolAddress((void**)&FCl, g_FCl);

    cudaFuncSetAttribute(fused_bg, cudaFuncAttributeMaxDynamicSharedMemorySize, FUSED_SMEM);

    // 0) split fp32 operands into bf16 hi/lo
    split_kernel<<<dim3(4096, 1, 7), 256>>>(qv, m_w, v_w, s_w, q_w, Wv_w, Wv2_w);

    // 1) M / V generators -> bf16 hi/lo outputs
    hmma_gemm<true><<<dim3(128, 19, 2), 256>>>(
        qvh, qvl, mwh, mwl, m_b, nullptr, Mh, Ml,
        qvh, qvl, vwh, vwl, v_b, nullptr, Vh, Vl,
        2400, 16384, 256, 256, 1, 0);

    // 2) S / Q generators -> bf16 hi/lo outputs
    hmma_gemm<true><<<dim3(32, 19, 2), 256>>>(
        qvh, qvl, swh, swl, s_b, nullptr, Sh, Sl,
        qvh, qvl, qwh, qwl, q_b, nullptr, Qh, Ql,
        2400, 4096, 256, 256, 1, 0);

    // 3) fused per-(bn,g) dynamic conv + attention (full HMMA)
    fused_bg<<<dim3(2400, 4), 128, FUSED_SMEM>>>(feats, k_w, k_b);

    // 4) output projections: (2400x8192) @ (256x8192)^T, split-K=8, fp32 out
    hmma_gemm<false><<<dim3(2, 19, 16), 256>>>(
        FMSh, FMSl, Wvh, Wvl, Wv_b, gP, nullptr, nullptr,
        FCh,  FCl,  W2h, W2l, Wv2_b, gP + 8 * 614400, nullptr, nullptr,
        2400, 256, 8192, 1024, 8, 614400);

    // 5) residual + split-K reduce + affine LayerNorm
    final_ln<<<dim3(2400, 2), 256>>>(qv, lnA_w, lnA_b, lnB_w, lnB_b, out);
}

// round 9
// speedup vs baseline: 2.1882x; 1.0049x over previous
#include <cuda_runtime.h>
#include <cuda_bf16.h>
#include <cstdint>

// ============================ problem constants ============================
// B=8, N=300 -> BN=2400; G=4; P=O=32; CG=DG=64; IN_DIM=OUT_DIM=256; TEMPER=8

// ===================== scratch (__device__ globals) ========================
__device__ float g_P[9830400];    // 16 split-K slices of (2400,256)

__device__ __nv_bfloat16 g_Mh[39321600], g_Ml[39321600];  // (bn, g*4096+c*64+d)
__device__ __nv_bfloat16 g_Vh[39321600], g_Vl[39321600];
__device__ __nv_bfloat16 g_Sh[9830400],  g_Sl[9830400];   // (bn, g*1024+o*32+p)
__device__ __nv_bfloat16 g_Qh[9830400],  g_Ql[9830400];

__device__ __nv_bfloat16 g_qvh[614400],  g_qvl[614400];
__device__ __nv_bfloat16 g_mwh[4194304], g_mwl[4194304];
__device__ __nv_bfloat16 g_vwh[4194304], g_vwl[4194304];
__device__ __nv_bfloat16 g_swh[1048576], g_swl[1048576];
__device__ __nv_bfloat16 g_qwh[1048576], g_qwl[1048576];
__device__ __nv_bfloat16 g_Wvh[2097152], g_Wvl[2097152];
__device__ __nv_bfloat16 g_W2h[2097152], g_W2l[2097152];
__device__ __nv_bfloat16 g_FMSh[19660800], g_FMSl[19660800];
__device__ __nv_bfloat16 g_FCh[19660800],  g_FCl[19660800];

// ============================ small helpers ================================
__device__ __forceinline__ uint32_t smem_u32(const void* p) {
    uint32_t a;
    asm("{ .reg .u64 t; cvta.to.shared.u64 t, %1; cvt.u32.u64 %0, t; }"
        : "=r"(a) : "l"(p));
    return a;
}
__device__ __forceinline__ void split_bf16(float x, __nv_bfloat16& h, __nv_bfloat16& l) {
    h = __float2bfloat16(x);
    l = __float2bfloat16(x - __bfloat162float(h));
}
__device__ __forceinline__ void ldmx4(uint32_t r[4], uint32_t addr) {
    asm volatile("ldmatrix.sync.aligned.m8n8.x4.shared.b16 {%0,%1,%2,%3}, [%4];"
                 : "=r"(r[0]), "=r"(r[1]), "=r"(r[2]), "=r"(r[3]) : "r"(addr));
}
__device__ __forceinline__ void ldmx4_t(uint32_t r[4], uint32_t addr) {
    asm volatile("ldmatrix.sync.aligned.m8n8.x4.trans.shared.b16 {%0,%1,%2,%3}, [%4];"
                 : "=r"(r[0]), "=r"(r[1]), "=r"(r[2]), "=r"(r[3]) : "r"(addr));
}
__device__ __forceinline__ void mma_bf16(float d[4], const uint32_t a[4],
                                         const uint32_t b0, const uint32_t b1) {
    asm volatile(
        "mma.sync.aligned.m16n8k16.row.col.f32.bf16.bf16.f32 "
        "{%0,%1,%2,%3}, {%4,%5,%6,%7}, {%8,%9}, {%0,%1,%2,%3};"
        : "+f"(d[0]), "+f"(d[1]), "+f"(d[2]), "+f"(d[3])
        : "r"(a[0]), "r"(a[1]), "r"(a[2]), "r"(a[3]), "r"(b0), "r"(b1));
}
// split two floats: returns hi-pair packed, lo-pair packed
__device__ __forceinline__ void split2_pack(float a, float b, uint32_t& hp, uint32_t& lp) {
    __nv_bfloat16 ha = __float2bfloat16(a), hb = __float2bfloat16(b);
    union { __nv_bfloat16 h[2]; uint32_t u; } H, L;
    H.h[0] = ha; H.h[1] = hb;
    L.h[0] = __float2bfloat16(a - __bfloat162float(ha));
    L.h[1] = __float2bfloat16(b - __bfloat162float(hb));
    hp = H.u; lp = L.u;
}

// ================= operand split prep (fp32 -> bf16 hi/lo) =================
__global__ void __launch_bounds__(256) split_kernel(
    const float* __restrict__ qv, const float* __restrict__ mw,
    const float* __restrict__ vw, const float* __restrict__ sw,
    const float* __restrict__ qw, const float* __restrict__ Wv,
    const float* __restrict__ W2)
{
    const float* src; __nv_bfloat16 *dh, *dl; int n;
    switch (blockIdx.z) {
        case 0: src = qv; dh = g_qvh; dl = g_qvl; n = 614400;  break;
        case 1: src = mw; dh = g_mwh; dl = g_mwl; n = 4194304; break;
        case 2: src = vw; dh = g_vwh; dl = g_vwl; n = 4194304; break;
        case 3: src = sw; dh = g_swh; dl = g_swl; n = 1048576; break;
        case 4: src = qw; dh = g_qwh; dl = g_qwl; n = 1048576; break;
        case 5: src = Wv; dh = g_Wvh; dl = g_Wvl; n = 2097152; break;
        default:src = W2; dh = g_W2h; dl = g_W2l; n = 2097152; break;
    }
    int i = (blockIdx.x * 256 + threadIdx.x) * 4;
    if (i >= n) return;
    float4 v = *(const float4*)(src + i);
    union U { __nv_bfloat16 b[4]; uint2 u; } H, L;
    split_bf16(v.x, H.b[0], L.b[0]);
    split_bf16(v.y, H.b[1], L.b[1]);
    split_bf16(v.z, H.b[2], L.b[2]);
    split_bf16(v.w, H.b[3], L.b[3]);
    *(uint2*)(dh + i) = H.u;
    *(uint2*)(dl + i) = L.u;
}

// ============ HMMA bf16x3 NT GEMM: C[M,Nout] = A@W^T (+bias @ks==0) ========
static constexpr int RS = 40;

template<bool OBF>
__global__ void __launch_bounds__(256) hmma_gemm(
    const __nv_bfloat16* __restrict__ Ah0, const __nv_bfloat16* __restrict__ Al0,
    const __nv_bfloat16* __restrict__ Wh0, const __nv_bfloat16* __restrict__ Wl0,
    const float* __restrict__ b0, float* __restrict__ C0,
    __nv_bfloat16* __restrict__ Ch0, __nv_bfloat16* __restrict__ Cl0,
    const __nv_bfloat16* __restrict__ Ah1, const __nv_bfloat16* __restrict__ Al1,
    const __nv_bfloat16* __restrict__ Wh1, const __nv_bfloat16* __restrict__ Wl1,
    const float* __restrict__ b1, float* __restrict__ C1,
    __nv_bfloat16* __restrict__ Ch1, __nv_bfloat16* __restrict__ Cl1,
    int M, int Nout, int lda, int kPerCta, int splitk, size_t sliceStride)
{
    __shared__ __align__(16) __nv_bfloat16 sAh[128 * RS];
    __shared__ __align__(16) __nv_bfloat16 sAl[128 * RS];
    __shared__ __align__(16) __nv_bfloat16 sBh[128 * RS];
    __shared__ __align__(16) __nv_bfloat16 sBl[128 * RS];

    const int tid = threadIdx.x, wid = tid >> 5, lane = tid & 31;
    const int z  = blockIdx.z / splitk;
    const int ks = blockIdx.z % splitk;
    const __nv_bfloat16* Ah = z ? Ah1 : Ah0;
    const __nv_bfloat16* Al = z ? Al1 : Al0;
    const __nv_bfloat16* Wh = z ? Wh1 : Wh0;
    const __nv_bfloat16* Wl = z ? Wl1 : Wl0;
    const float* bias = z ? b1 : b0;
    float* Cp = (z ? C1 : C0) + (size_t)ks * sliceStride;
    __nv_bfloat16* Chp = z ? Ch1 : Ch0;
    __nv_bfloat16* Clp = z ? Cl1 : Cl0;

    const int m0 = blockIdx.y * 128;
    const int n0 = blockIdx.x * 128;
    const int kBegin = ks * kPerCta;
    const int NC = kPerCta / 32;

    const int wm = (wid & 3) * 32;
    const int wn = (wid >> 2) * 64;

    const int lrow = tid >> 2;
    const int lseg = (tid & 3) * 8;

    float acc[2][8][4];
#pragma unroll
    for (int i = 0; i < 2; i++)
#pragma unroll
        for (int j = 0; j < 8; j++)
#pragma unroll
            for (int q = 0; q < 4; q++) acc[i][j][q] = 0.f;

    uint4 rA[2], rAl[2], rB[2], rBl[2];

    auto load_regs = [&](int c) {
        const int kk = kBegin + c * 32;
#pragma unroll
        for (int j = 0; j < 2; j++) {
            int row = lrow + 64 * j;
            int gm = m0 + row;
            if (gm < M) {
                size_t go = (size_t)gm * lda + kk + lseg;
                rA[j]  = *(const uint4*)(Ah + go);
                rAl[j] = *(const uint4*)(Al + go);
            } else {
                rA[j] = rAl[j] = make_uint4(0u, 0u, 0u, 0u);
            }
            size_t gw = (size_t)(n0 + row) * lda + kk + lseg;
            rB[j]  = *(const uint4*)(Wh + gw);
            rBl[j] = *(const uint4*)(Wl + gw);
        }
    };
    auto store_smem = [&]() {
#pragma unroll
        for (int j = 0; j < 2; j++) {
            int off = (lrow + 64 * j) * RS + lseg;
            *(uint4*)(sAh + off) = rA[j];
            *(uint4*)(sAl + off) = rAl[j];
            *(uint4*)(sBh + off) = rB[j];
            *(uint4*)(sBl + off) = rBl[j];
        }
    };

    const uint32_t uAh = smem_u32(sAh), uAl = smem_u32(sAl);
    const uint32_t uBh = smem_u32(sBh), uBl = smem_u32(sBl);
    const int arow = lane & 15, acol = (lane >> 4) * 8;
    const int bgrp = lane >> 3, brow = lane & 7;
    const int bn_off = (bgrp >> 1) * 8 + brow;
    const int bk_off = (bgrp & 1) * 8;

    load_regs(0);

    for (int c = 0; c < NC; c++) {
        store_smem();
        __syncthreads();
        if (c + 1 < NC) load_regs(c + 1);

#pragma unroll
        for (int ksp = 0; ksp < 2; ksp++) {
            uint32_t fAh[2][4], fAl[2][4], fBh[4][4], fBl[4][4];
#pragma unroll
            for (int mi = 0; mi < 2; mi++) {
                uint32_t off = 2u * ((wm + mi * 16 + arow) * RS + ksp * 16 + acol);
                ldmx4(fAh[mi], uAh + off);
                ldmx4(fAl[mi], uAl + off);
            }
#pragma unroll
            for (int nb = 0; nb < 4; nb++) {
                uint32_t off = 2u * ((wn + nb * 16 + bn_off) * RS + ksp * 16 + bk_off);
                ldmx4(fBh[nb], uBh + off);
                ldmx4(fBl[nb], uBl + off);
            }
#pragma unroll
            for (int mi = 0; mi < 2; mi++)
#pragma unroll
                for (int nf = 0; nf < 8; nf++) {
                    const uint32_t* bh = &fBh[nf >> 1][(nf & 1) * 2];
                    const uint32_t* bl = &fBl[nf >> 1][(nf & 1) * 2];
                    mma_bf16(acc[mi][nf], fAh[mi], bh[0], bh[1]);
                    mma_bf16(acc[mi][nf], fAl[mi], bh[0], bh[1]);
                    mma_bf16(acc[mi][nf], fAh[mi], bl[0], bl[1]);
                }
        }
        __syncthreads();
    }

    const bool addB = (ks == 0);
    const int erow = lane >> 2, ecol = (lane & 3) * 2;
#pragma unroll
    for (int mi = 0; mi < 2; mi++) {
        int r0 = m0 + wm + mi * 16 + erow;
#pragma unroll
        for (int half = 0; half < 2; half++) {
            int r = r0 + half * 8;
            if (r >= M) continue;
#pragma unroll
            for (int nf = 0; nf < 8; nf++) {
                int col = n0 + wn + nf * 8 + ecol;
                float x0 = acc[mi][nf][half * 2 + 0];
                float x1 = acc[mi][nf][half * 2 + 1];
                if (addB) { x0 += __ldg(bias + col); x1 += __ldg(bias + col + 1); }
                if (OBF) {
                    uint32_t hp, lp;
                    split2_pack(x0, x1, hp, lp);
                    size_t o = (size_t)r * Nout + col;
                    *(uint32_t*)(Chp + o) = hp;
                    *(uint32_t*)(Clp + o) = lp;
                } else {
                    *(float2*)(Cp + (size_t)r * Nout + col) = make_float2(x0, x1);
                }
            }
        }
    }
}

// ================== fused per-(bn,g) kernel (full HMMA, 32 KB smem) ========
static constexpr int STW = 72;
static constexpr int STN = 40;

__device__ __forceinline__ void ln2048_relu(float acc[4][4], float* red) {
    float s = 0.f, q = 0.f;
#pragma unroll
    for (int i = 0; i < 4; i++)
#pragma unroll
        for (int j = 0; j < 4; j++) { s += acc[i][j]; q += acc[i][j] * acc[i][j]; }
#pragma unroll
    for (int o = 16; o > 0; o >>= 1) {
        s += __shfl_xor_sync(0xffffffffu, s, o);
        q += __shfl_xor_sync(0xffffffffu, q, o);
    }
    int w = threadIdx.x >> 5;
    __syncthreads();
    if ((threadIdx.x & 31) == 0) { red[w] = s; red[4 + w] = q; }
    __syncthreads();
    s = red[0] + red[1] + red[2] + red[3];
    q = red[4] + red[5] + red[6] + red[7];
    float mean = s * (1.f / 2048.f);
    float var  = q * (1.f / 2048.f) - mean * mean;
    float inv  = rsqrtf(var + 1e-5f);
#pragma unroll
    for (int i = 0; i < 4; i++)
#pragma unroll
        for (int j = 0; j < 4; j++)
            acc[i][j] = fmaxf((acc[i][j] - mean) * inv, 0.f);
}

// ---- A-fragment loaders (fragment layout: a0=(r,k) a1=(r+8,k) a2=(r,k+8) a3=(r+8,k+8),
//      r = rw + lane/4, k = kt*16 + (lane%4)*2) ----
struct ALoadS {      // smem via ldmatrix
    uint32_t addrH, addrL;
    __device__ __forceinline__ void load(int kt, uint32_t aH[4], uint32_t aL[4]) const {
        ldmx4(aH, addrH + kt * 32);
        ldmx4(aL, addrL + kt * 32);
    }
};
struct ALoadGB {     // global bf16 hi/lo
    const __nv_bfloat16 *H, *L; int ld, r0, k0;
    __device__ __forceinline__ void load(int kt, uint32_t aH[4], uint32_t aL[4]) const {
        int k = kt * 16 + k0;
        aH[0] = *(const uint32_t*)(H + r0 * ld + k);
        aH[1] = *(const uint32_t*)(H + (r0 + 8) * ld + k);
        aH[2] = *(const uint32_t*)(H + r0 * ld + k + 8);
        aH[3] = *(const uint32_t*)(H + (r0 + 8) * ld + k + 8);
        aL[0] = *(const uint32_t*)(L + r0 * ld + k);
        aL[1] = *(const uint32_t*)(L + (r0 + 8) * ld + k);
        aL[2] = *(const uint32_t*)(L + r0 * ld + k + 8);
        aL[3] = *(const uint32_t*)(L + (r0 + 8) * ld + k + 8);
    }
};
struct ALoadGF {     // global fp32, split in regs
    const float* A; int ld, r0, k0;
    __device__ __forceinline__ void load(int kt, uint32_t aH[4], uint32_t aL[4]) const {
        int k = kt * 16 + k0;
        float2 v0 = *(const float2*)(A + r0 * ld + k);
        float2 v1 = *(const float2*)(A + (r0 + 8) * ld + k);
        float2 v2 = *(const float2*)(A + r0 * ld + k + 8);
        float2 v3 = *(const float2*)(A + (r0 + 8) * ld + k + 8);
        split2_pack(v0.x, v0.y, aH[0], aL[0]);
        split2_pack(v1.x, v1.y, aH[1], aL[1]);
        split2_pack(v2.x, v2.y, aH[2], aL[2]);
        split2_pack(v3.x, v3.y, aH[3], aL[3]);
    }
};

template<class AL, int NB, int KT, bool TRANS, int SB>
__device__ __forceinline__ void mm_frag2(float acc[NB][4], const AL& al,
    const __nv_bfloat16* BH, const __nv_bfloat16* BL, int wn, int lane)
{
    const int b1 = ((lane >> 4) << 3) + (lane & 7);
    const int b2 = ((lane >> 3) & 1) * 8;
#pragma unroll
    for (int i = 0; i < NB; i++)
#pragma unroll
        for (int j = 0; j < 4; j++) acc[i][j] = 0.f;
#pragma unroll
    for (int kt = 0; kt < KT; kt++) {
        uint32_t aH[4], aL[4];
        al.load(kt, aH, aL);
#pragma unroll
        for (int nt = 0; nt < NB / 2; nt++) {
            uint32_t bH[4], bL[4];
            if (TRANS) {
                ldmx4_t(bH, smem_u32(BH + (kt * 16 + b1) * SB + wn + nt * 16 + b2));
                ldmx4_t(bL, smem_u32(BL + (kt * 16 + b1) * SB + wn + nt * 16 + b2));
            } else {
                ldmx4(bH, smem_u32(BH + (wn + nt * 16 + b1) * SB + kt * 16 + b2));
                ldmx4(bL, smem_u32(BL + (wn + nt * 16 + b1) * SB + kt * 16 + b2));
            }
#pragma unroll
            for (int h = 0; h < 2; h++) {
                int nb = nt * 2 + h;
                uint32_t h0, h1, l0, l1;
                if (TRANS) { h0 = bH[h]; h1 = bH[h + 2]; l0 = bL[h]; l1 = bL[h + 2]; }
                else       { h0 = bH[2 * h]; h1 = bH[2 * h + 1];
                             l0 = bL[2 * h]; l1 = bL[2 * h + 1]; }
                mma_bf16(acc[nb], aH, h0, h1);
                mma_bf16(acc[nb], aL, h0, h1);
                mma_bf16(acc[nb], aH, l0, l1);
            }
        }
    }
}

// bf16 hi/lo global -> smem with padded stride (pure copy)
template<int W, int ST>
__device__ __forceinline__ void load_bf16_smem(const __nv_bfloat16* __restrict__ srcH,
                                               const __nv_bfloat16* __restrict__ srcL,
                                               int n, __nv_bfloat16* dh,
                                               __nv_bfloat16* dl, int tid)
{
#pragma unroll
    for (int idx = tid * 8; idx < n; idx += 1024) {
        int row = idx / W, col = idx % W;
        *(uint4*)(dh + row * ST + col) = *(const uint4*)(srcH + idx);
        *(uint4*)(dl + row * ST + col) = *(const uint4*)(srcL + idx);
    }
}

__global__ void __launch_bounds__(128, 6) fused_bg(
    const float* __restrict__ feats,
    const float* __restrict__ kw_g, const float* __restrict__ kb_g)
{
    // 32,800 B static smem -> 6 CTAs/SM
    __shared__ __align__(16) __nv_bfloat16 wS[2 * 64 * STW];  // M -> Vw (hi|lo)
    __shared__ __align__(16) __nv_bfloat16 xS[2 * 32 * STW];  // fM -> v
    __shared__ __align__(16) __nv_bfloat16 sS[2 * 32 * STN];  // k -> att
    __shared__ float red[8];

    __nv_bfloat16 *wH = wS, *wL = wS + 64 * STW;
    __nv_bfloat16 *xH = xS, *xL = xS + 32 * STW;
    __nv_bfloat16 *sH = sS, *sL = sS + 32 * STN;
    float* sc = (float*)wS;  // overlays dead w region at stage 5+ (4608 B)

    const int bn = blockIdx.x, g = blockIdx.y;
    const int tid = threadIdx.x;
    const int lane = tid & 31, wrp = tid >> 5;
    const int rw   = (wrp & 1) * 16;
    const int wn32 = (wrp >> 1) * 32;
    const int wn16 = (wrp >> 1) * 16;
    const int lr = lane >> 2, lc = 2 * (lane & 3);
    const int fr0 = rw + lr, fk0 = lc;  // A-fragment row/k bases
    const size_t bg = (size_t)bn * 4 + g;

    // ---- stage 0: only M is staged in smem ----
    load_bf16_smem<64, STW>(g_Mh + bg * 4096, g_Ml + bg * 4096, 4096, wH, wL, tid);
    __syncthreads();

    float acc[4][4];
    const ALoadGF af{feats + bg * 2048, 64, fr0, fk0};

    // ---- stage 1: fM = relu(ln2d(f @ M)) -> x ----
    mm_frag2<ALoadGF, 4, 4, true, STW>(acc, af, wH, wL, wn32, lane);
    ln2048_relu(acc, red);
    // w dead (ln barrier passed) -> deposit Vw
    load_bf16_smem<64, STW>(g_Vh + bg * 4096, g_Vl + bg * 4096, 4096, wH, wL, tid);
#pragma unroll
    for (int nb = 0; nb < 4; nb++) {
        int c = wn32 + nb * 8 + lc;
        uint32_t hp, lp;
        split2_pack(acc[nb][0], acc[nb][1], hp, lp);
        *(uint32_t*)(xH + fr0 * STW + c) = hp;
        *(uint32_t*)(xL + fr0 * STW + c) = lp;
        split2_pack(acc[nb][2], acc[nb][3], hp, lp);
        *(uint32_t*)(xH + (fr0 + 8) * STW + c) = hp;
        *(uint32_t*)(xL + (fr0 + 8) * STW + c) = lp;
    }
    __syncthreads();

    // ---- stage 2: fMS = relu(ln2d(S @ fM)) -> global ----
    {
        const ALoadGB as{g_Sh + bg * 1024, g_Sl + bg * 1024, 32, fr0, fk0};
        mm_frag2<ALoadGB, 4, 2, true, STW>(acc, as, xH, xL, wn32, lane);
    }
    ln2048_relu(acc, red);
#pragma unroll
    for (int nb = 0; nb < 4; nb++) {
        int c = wn32 + nb * 8 + lc;
        size_t o0 = bg * 2048 + (size_t)fr0 * 64 + c;
        size_t o1 = o0 + 8 * 64;
        uint32_t hp, lp;
        split2_pack(acc[nb][0], acc[nb][1], hp, lp);
        *(uint32_t*)(g_FMSh + o0) = hp;
        *(uint32_t*)(g_FMSl + o0) = lp;
        split2_pack(acc[nb][2], acc[nb][3], hp, lp);
        *(uint32_t*)(g_FMSh + o1) = hp;
        *(uint32_t*)(g_FMSl + o1) = lp;
    }
    __syncthreads();

    // ---- stage 3: v = relu(ln2d(f @ Vw)) -> x ----
    mm_frag2<ALoadGF, 4, 4, true, STW>(acc, af, wH, wL, wn32, lane);
    ln2048_relu(acc, red);
#pragma unroll
    for (int nb = 0; nb < 4; nb++) {
        int c = wn32 + nb * 8 + lc;
        uint32_t hp, lp;
        split2_pack(acc[nb][0], acc[nb][1], hp, lp);
        *(uint32_t*)(xH + fr0 * STW + c) = hp;
        *(uint32_t*)(xL + fr0 * STW + c) = lp;
        split2_pack(acc[nb][2], acc[nb][3], hp, lp);
        *(uint32_t*)(xH + (fr0 + 8) * STW + c) = hp;
        *(uint32_t*)(xL + (fr0 + 8) * STW + c) = lp;
    }
    __syncthreads();

    float a2[2][4];

    // ---- stage 4: k[i][p] = kw @ v^T + kb -> s region ----
    {
        const ALoadGF akw{kw_g + g * 2048, 64, fr0, fk0};
        mm_frag2<ALoadGF, 2, 4, false, STW>(a2, akw, xH, xL, wn16, lane);
        float b0 = __ldg(kb_g + g * 32 + fr0);
        float b1 = __ldg(kb_g + g * 32 + fr0 + 8);
#pragma unroll
        for (int nb = 0; nb < 2; nb++) {
            int c = wn16 + nb * 8 + lc;
            uint32_t hp, lp;
            split2_pack(a2[nb][0] + b0, a2[nb][1] + b0, hp, lp);
            *(uint32_t*)(sH + fr0 * STN + c) = hp;
            *(uint32_t*)(sL + fr0 * STN + c) = lp;
            split2_pack(a2[nb][2] + b1, a2[nb][3] + b1, hp, lp);
            *(uint32_t*)(sH + (fr0 + 8) * STN + c) = hp;
            *(uint32_t*)(sL + (fr0 + 8) * STN + c) = lp;
        }
    }
    __syncthreads();

    // ---- stage 5: scores = q @ k -> sc (fp32, in dead w region) ----
    {
        const ALoadGB aq{g_Qh + bg * 1024, g_Ql + bg * 1024, 32, fr0, fk0};
        mm_frag2<ALoadGB, 2, 2, true, STN>(a2, aq, sH, sL, wn16, lane);
#pragma unroll
        for (int nb = 0; nb < 2; nb++) {
            int c = wn16 + nb * 8 + lc;
            *(float2*)(sc + fr0 * 36 + c)       = make_float2(a2[nb][0], a2[nb][1]);
            *(float2*)(sc + (fr0 + 8) * 36 + c) = make_float2(a2[nb][2], a2[nb][3]);
        }
    }
    __syncthreads();

    // ---- stage 6: softmax(sc / 8) -> att (over k in s region) ----
    {
        const int tx8 = tid & 7, ty16 = tid >> 3;
#pragma unroll
        for (int i = 0; i < 2; i++) {
            int row = 2 * ty16 + i;
            float v[4];
#pragma unroll
            for (int j = 0; j < 4; j++) v[j] = sc[row * 36 + 4 * tx8 + j];
            float m = fmaxf(fmaxf(v[0], v[1]), fmaxf(v[2], v[3]));
#pragma unroll
            for (int o = 4; o > 0; o >>= 1)
                m = fmaxf(m, __shfl_xor_sync(0xffffffffu, m, o));
            float s = 0.f;
#pragma unroll
            for (int j = 0; j < 4; j++) { v[j] = __expf((v[j] - m) * 0.125f); s += v[j]; }
#pragma unroll
            for (int o = 4; o > 0; o >>= 1)
                s += __shfl_xor_sync(0xffffffffu, s, o);
            float inv = __frcp_rn(s);
#pragma unroll
            for (int j = 0; j < 4; j++) {
                float p = v[j] * inv;
                __nv_bfloat16 h, l;
                split_bf16(p, h, l);
                sH[row * STN + 4 * tx8 + j] = h;
                sL[row * STN + 4 * tx8 + j] = l;
            }
        }
    }
    __syncthreads();

    // ---- stage 7: fc = relu(ln2d(att @ v)) -> global ----
    {
        const ALoadS aatt{
            smem_u32(sH + (rw + (lane & 15)) * STN + (lane >> 4) * 8),
            smem_u32(sL + (rw + (lane & 15)) * STN + (lane >> 4) * 8)};
        mm_frag2<ALoadS, 4, 2, true, STW>(acc, aatt, xH, xL, wn32, lane);
    }
    ln2048_relu(acc, red);
#pragma unroll
    for (int nb = 0; nb < 4; nb++) {
        int c = wn32 + nb * 8 + lc;
        size_t o0 = bg * 2048 + (size_t)fr0 * 64 + c;
        size_t o1 = o0 + 8 * 64;
        uint32_t hp, lp;
        split2_pack(acc[nb][0], acc[nb][1], hp, lp);
        *(uint32_t*)(g_FCh + o0) = hp;
        *(uint32_t*)(g_FCl + o0) = lp;
        split2_pack(acc[nb][2], acc[nb][3], hp, lp);
        *(uint32_t*)(g_FCh + o1) = hp;
        *(uint32_t*)(g_FCl + o1) = lp;
    }
}

// ============== residual + split-K reduce + affine LayerNorm ===============
__global__ void __launch_bounds__(256) final_ln(
    const float* __restrict__ qv,
    const float* __restrict__ wA, const float* __restrict__ bA,
    const float* __restrict__ wB, const float* __restrict__ bB,
    float* __restrict__ out)
{
    const int r = blockIdx.x, z = blockIdx.y, c = threadIdx.x;
    const float* w = z ? wB : wA;
    const float* b = z ? bB : bA;
    float x = qv[(size_t)r * 256 + c];
#pragma unroll
    for (int k = 0; k < 8; k++)
        x += g_P[(size_t)(z * 8 + k) * 614400 + (size_t)r * 256 + c];

    __shared__ float sred[16];
    float s = x, q = x * x;
#pragma unroll
    for (int o = 16; o > 0; o >>= 1) {
        s += __shfl_xor_sync(0xffffffffu, s, o);
        q += __shfl_xor_sync(0xffffffffu, q, o);
    }
    int wp = threadIdx.x >> 5;
    if ((threadIdx.x & 31) == 0) { sred[wp] = s; sred[8 + wp] = q; }
    __syncthreads();
    float S = 0.f, Q2 = 0.f;
#pragma unroll
    for (int i = 0; i < 8; i++) { S += sred[i]; Q2 += sred[8 + i]; }
    float mean = S * (1.f / 256.f);
    float var  = Q2 * (1.f / 256.f) - mean * mean;
    float inv  = rsqrtf(var + 1e-5f);
    out[(size_t)z * 614400 + (size_t)r * 256 + c] = (x - mean) * inv * w[c] + b[c];
}

// ================================ launcher =================================
extern "C" void kernel_launch(void* const* d_in, const int* in_sizes, int n_in,
                              void* d_out, int out_size)
{
    const float* feats = (const float*)d_in[0];
    const float* qv    = (const float*)d_in[1];
    const float* m_w   = (const float*)d_in[7];
    const float* m_b   = (const float*)d_in[8];
    const float* s_w   = (const float*)d_in[9];
    const float* s_b   = (const float*)d_in[10];
    const float* q_w   = (const float*)d_in[11];
    const float* q_b   = (const float*)d_in[12];
    const float* v_w   = (const float*)d_in[13];
    const float* v_b   = (const float*)d_in[14];
    const float* k_w   = (const float*)d_in[15];
    const float* k_b   = (const float*)d_in[16];
    const float* Wv_w  = (const float*)d_in[17];
    const float* Wv_b  = (const float*)d_in[18];
    const float* Wv2_w = (const float*)d_in[19];
    const float* Wv2_b = (const float*)d_in[20];
    const float* lnA_w = (const float*)d_in[21];
    const float* lnA_b = (const float*)d_in[22];
    const float* lnB_w = (const float*)d_in[23];
    const float* lnB_b = (const float*)d_in[24];
    float* out = (float*)d_out;

    float* gP;
    cudaGetSymbolAddress((void**)&gP, g_P);
    __nv_bfloat16 *Mh, *Ml, *Vh, *Vl, *Sh, *Sl, *Qh, *Ql;
    cudaGetSymbolAddress((void**)&Mh, g_Mh); cudaGetSymbolAddress((void**)&Ml, g_Ml);
    cudaGetSymbolAddress((void**)&Vh, g_Vh); cudaGetSymbolAddress((void**)&Vl, g_Vl);
    cudaGetSymbolAddress((void**)&Sh, g_Sh); cudaGetSymbolAddress((void**)&Sl, g_Sl);
    cudaGetSymbolAddress((void**)&Qh, g_Qh); cudaGetSymbolAddress((void**)&Ql, g_Ql);
    __nv_bfloat16 *qvh, *qvl, *mwh, *mwl, *vwh, *vwl, *swh, *swl, *qwh, *qwl;
    __nv_bfloat16 *Wvh, *Wvl, *W2h, *W2l, *FMSh, *FMSl, *FCh, *FCl;
    cudaGetSymbolAddress((void**)&qvh, g_qvh);   cudaGetSymbolAddress((void**)&qvl, g_qvl);
    cudaGetSymbolAddress((void**)&mwh, g_mwh);   cudaGetSymbolAddress((void**)&mwl, g_mwl);
    cudaGetSymbolAddress((void**)&vwh, g_vwh);   cudaGetSymbolAddress((void**)&vwl, g_vwl);
    cudaGetSymbolAddress((void**)&swh, g_swh);   cudaGetSymbolAddress((void**)&swl, g_swl);
    cudaGetSymbolAddress((void**)&qwh, g_qwh);   cudaGetSymbolAddress((void**)&qwl, g_qwl);
    cudaGetSymbolAddress((void**)&Wvh, g_Wvh);   cudaGetSymbolAddress((void**)&Wvl, g_Wvl);
    cudaGetSymbolAddress((void**)&W2h, g_W2h);   cudaGetSymbolAddress((void**)&W2l, g_W2l);
    cudaGetSymbolAddress((void**)&FMSh, g_FMSh); cudaGetSymbolAddress((void**)&FMSl, g_FMSl);
    cudaGetSymbolAddress((void**)&FCh, g_FCh);   cudaGetSymbolAddress((void**)&FCl, g_FCl);

    // 0) split fp32 operands into bf16 hi/lo
    split_kernel<<<dim3(4096, 1, 7), 256>>>(qv, m_w, v_w, s_w, q_w, Wv_w, Wv2_w);

    // 1) M / V generators -> bf16 hi/lo outputs
    hmma_gemm<true><<<dim3(128, 19, 2), 256>>>(
        qvh, qvl, mwh, mwl, m_b, nullptr, Mh, Ml,
        qvh, qvl, vwh, vwl, v_b, nullptr, Vh, Vl,
        2400, 16384, 256, 256, 1, 0);

    // 2) S / Q generators -> bf16 hi/lo outputs
    hmma_gemm<true><<<dim3(32, 19, 2), 256>>>(
        qvh, qvl, swh, swl, s_b, nullptr, Sh, Sl,
        qvh, qvl, qwh, qwl, q_b, nullptr, Qh, Ql,
        2400, 4096, 256, 256, 1, 0);

    // 3) fused per-(bn,g) dynamic conv + attention (32 KB smem, 6 CTAs/SM)
    fused_bg<<<dim3(2400, 4), 128>>>(feats, k_w, k_b);

    // 4) output projections: (2400x8192) @ (256x8192)^T, split-K=8, fp32 out
    hmma_gemm<false><<<dim3(2, 19, 16), 256>>>(
        FMSh, FMSl, Wvh, Wvl, Wv_b, gP, nullptr, nullptr,
        FCh,  FCl,  W2h, W2l, Wv2_b, gP + 8 * 614400, nullptr, nullptr,
        2400, 256, 8192, 1024, 8, 614400);

    // 5) residual + split-K reduce + affine LayerNorm
    final_ln<<<dim3(2400, 2), 256>>>(qv, lnA_w, lnA_b, lnB_w, lnB_b, out);
}

// round 10
// speedup vs baseline: 2.1985x; 1.0047x over previous
#include <cuda_runtime.h>
#include <cuda_bf16.h>
#include <cstdint>

// ============================ problem constants ============================
// B=8, N=300 -> BN=2400; G=4; P=O=32; CG=DG=64; IN_DIM=OUT_DIM=256; TEMPER=8

// ===================== scratch (__device__ globals) ========================
__device__ float g_P[9830400];    // split-K slices of (2400,256)

__device__ __nv_bfloat16 g_Mh[39321600], g_Ml[39321600];  // (bn, g*4096+c*64+d)
__device__ __nv_bfloat16 g_Vh[39321600], g_Vl[39321600];
__device__ __nv_bfloat16 g_Sh[9830400],  g_Sl[9830400];   // (bn, g*1024+o*32+p)
__device__ __nv_bfloat16 g_Qh[9830400],  g_Ql[9830400];

__device__ __nv_bfloat16 g_qvh[614400],  g_qvl[614400];
__device__ __nv_bfloat16 g_mwh[4194304], g_mwl[4194304];
__device__ __nv_bfloat16 g_vwh[4194304], g_vwl[4194304];
__device__ __nv_bfloat16 g_swh[1048576], g_swl[1048576];
__device__ __nv_bfloat16 g_qwh[1048576], g_qwl[1048576];
__device__ __nv_bfloat16 g_Wvh[2097152], g_Wvl[2097152];
__device__ __nv_bfloat16 g_W2h[2097152], g_W2l[2097152];
__device__ __nv_bfloat16 g_FMSh[19660800], g_FMSl[19660800];
__device__ __nv_bfloat16 g_FCh[19660800],  g_FCl[19660800];

// ============================ small helpers ================================
__device__ __forceinline__ uint32_t smem_u32(const void* p) {
    uint32_t a;
    asm("{ .reg .u64 t; cvta.to.shared.u64 t, %1; cvt.u32.u64 %0, t; }"
        : "=r"(a) : "l"(p));
    return a;
}
__device__ __forceinline__ void split_bf16(float x, __nv_bfloat16& h, __nv_bfloat16& l) {
    h = __float2bfloat16(x);
    l = __float2bfloat16(x - __bfloat162float(h));
}
__device__ __forceinline__ void ldmx4(uint32_t r[4], uint32_t addr) {
    asm volatile("ldmatrix.sync.aligned.m8n8.x4.shared.b16 {%0,%1,%2,%3}, [%4];"
                 : "=r"(r[0]), "=r"(r[1]), "=r"(r[2]), "=r"(r[3]) : "r"(addr));
}
__device__ __forceinline__ void ldmx4_t(uint32_t r[4], uint32_t addr) {
    asm volatile("ldmatrix.sync.aligned.m8n8.x4.trans.shared.b16 {%0,%1,%2,%3}, [%4];"
                 : "=r"(r[0]), "=r"(r[1]), "=r"(r[2]), "=r"(r[3]) : "r"(addr));
}
__device__ __forceinline__ void mma_bf16(float d[4], const uint32_t a[4],
                                         const uint32_t b0, const uint32_t b1) {
    asm volatile(
        "mma.sync.aligned.m16n8k16.row.col.f32.bf16.bf16.f32 "
        "{%0,%1,%2,%3}, {%4,%5,%6,%7}, {%8,%9}, {%0,%1,%2,%3};"
        : "+f"(d[0]), "+f"(d[1]), "+f"(d[2]), "+f"(d[3])
        : "r"(a[0]), "r"(a[1]), "r"(a[2]), "r"(a[3]), "r"(b0), "r"(b1));
}
__device__ __forceinline__ void split2_pack(float a, float b, uint32_t& hp, uint32_t& lp) {
    __nv_bfloat16 ha = __float2bfloat16(a), hb = __float2bfloat16(b);
    union { __nv_bfloat16 h[2]; uint32_t u; } H, L;
    H.h[0] = ha; H.h[1] = hb;
    L.h[0] = __float2bfloat16(a - __bfloat162float(ha));
    L.h[1] = __float2bfloat16(b - __bfloat162float(hb));
    hp = H.u; lp = L.u;
}

// ================= operand split prep (fp32 -> bf16 hi/lo) =================
__global__ void __launch_bounds__(256) split_kernel(
    const float* __restrict__ qv, const float* __restrict__ mw,
    const float* __restrict__ vw, const float* __restrict__ sw,
    const float* __restrict__ qw, const float* __restrict__ Wv,
    const float* __restrict__ W2)
{
    const float* src; __nv_bfloat16 *dh, *dl; int n;
    switch (blockIdx.z) {
        case 0: src = qv; dh = g_qvh; dl = g_qvl; n = 614400;  break;
        case 1: src = mw; dh = g_mwh; dl = g_mwl; n = 4194304; break;
        case 2: src = vw; dh = g_vwh; dl = g_vwl; n = 4194304; break;
        case 3: src = sw; dh = g_swh; dl = g_swl; n = 1048576; break;
        case 4: src = qw; dh = g_qwh; dl = g_qwl; n = 1048576; break;
        case 5: src = Wv; dh = g_Wvh; dl = g_Wvl; n = 2097152; break;
        default:src = W2; dh = g_W2h; dl = g_W2l; n = 2097152; break;
    }
    int i = (blockIdx.x * 256 + threadIdx.x) * 4;
    if (i >= n) return;
    float4 v = *(const float4*)(src + i);
    union U { __nv_bfloat16 b[4]; uint2 u; } H, L;
    split_bf16(v.x, H.b[0], L.b[0]);
    split_bf16(v.y, H.b[1], L.b[1]);
    split_bf16(v.z, H.b[2], L.b[2]);
    split_bf16(v.w, H.b[3], L.b[3]);
    *(uint2*)(dh + i) = H.u;
    *(uint2*)(dl + i) = L.u;
}

static constexpr int RS = 40;

// ====== merged generator GEMM (M/V/S/Q), raster-swapped, bf16 hi/lo out ====
// grid (x = m-tile [19], y = n-tile [<=128], z = set 0..3). K=256 fixed.
__global__ void __launch_bounds__(256) gen_gemm(
    const float* __restrict__ mb, const float* __restrict__ vb,
    const float* __restrict__ sb, const float* __restrict__ qb)
{
    __shared__ __align__(16) __nv_bfloat16 sAh[128 * RS];
    __shared__ __align__(16) __nv_bfloat16 sAl[128 * RS];
    __shared__ __align__(16) __nv_bfloat16 sBh[128 * RS];
    __shared__ __align__(16) __nv_bfloat16 sBl[128 * RS];

    const __nv_bfloat16 *Wh, *Wl; const float* bias;
    __nv_bfloat16 *Ch, *Cl; int Nout, nt;
    switch (blockIdx.z) {
        case 0: Wh = g_mwh; Wl = g_mwl; bias = mb; Ch = g_Mh; Cl = g_Ml;
                Nout = 16384; nt = 128; break;
        case 1: Wh = g_vwh; Wl = g_vwl; bias = vb; Ch = g_Vh; Cl = g_Vl;
                Nout = 16384; nt = 128; break;
        case 2: Wh = g_swh; Wl = g_swl; bias = sb; Ch = g_Sh; Cl = g_Sl;
                Nout = 4096;  nt = 32;  break;
        default:Wh = g_qwh; Wl = g_qwl; bias = qb; Ch = g_Qh; Cl = g_Ql;
                Nout = 4096;  nt = 32;  break;
    }
    if ((int)blockIdx.y >= nt) return;

    const int tid = threadIdx.x, wid = tid >> 5, lane = tid & 31;
    const int m0 = blockIdx.x * 128;     // m fastest -> B n-tile shared in L2
    const int n0 = blockIdx.y * 128;
    constexpr int M = 2400, lda = 256, NC = 8;

    const int wm = (wid & 3) * 32;
    const int wn = (wid >> 2) * 64;
    const int lrow = tid >> 2;
    const int lseg = (tid & 3) * 8;

    float acc[2][8][4];
#pragma unroll
    for (int i = 0; i < 2; i++)
#pragma unroll
        for (int j = 0; j < 8; j++)
#pragma unroll
            for (int q = 0; q < 4; q++) acc[i][j][q] = 0.f;

    uint4 rA[2], rAl[2], rB[2], rBl[2];

    auto load_regs = [&](int c) {
        const int kk = c * 32;
#pragma unroll
        for (int j = 0; j < 2; j++) {
            int row = lrow + 64 * j;
            int gm = m0 + row;
            if (gm < M) {
                size_t go = (size_t)gm * lda + kk + lseg;
                rA[j]  = *(const uint4*)(g_qvh + go);
                rAl[j] = *(const uint4*)(g_qvl + go);
            } else {
                rA[j] = rAl[j] = make_uint4(0u, 0u, 0u, 0u);
            }
            size_t gw = (size_t)(n0 + row) * lda + kk + lseg;
            rB[j]  = *(const uint4*)(Wh + gw);
            rBl[j] = *(const uint4*)(Wl + gw);
        }
    };
    auto store_smem = [&]() {
#pragma unroll
        for (int j = 0; j < 2; j++) {
            int off = (lrow + 64 * j) * RS + lseg;
            *(uint4*)(sAh + off) = rA[j];
            *(uint4*)(sAl + off) = rAl[j];
            *(uint4*)(sBh + off) = rB[j];
            *(uint4*)(sBl + off) = rBl[j];
        }
    };

    const uint32_t uAh = smem_u32(sAh), uAl = smem_u32(sAl);
    const uint32_t uBh = smem_u32(sBh), uBl = smem_u32(sBl);
    const int arow = lane & 15, acol = (lane >> 4) * 8;
    const int bgrp = lane >> 3, brow = lane & 7;
    const int bn_off = (bgrp >> 1) * 8 + brow;
    const int bk_off = (bgrp & 1) * 8;

    load_regs(0);

    for (int c = 0; c < NC; c++) {
        store_smem();
        __syncthreads();
        if (c + 1 < NC) load_regs(c + 1);

#pragma unroll
        for (int ksp = 0; ksp < 2; ksp++) {
            uint32_t fAh[2][4], fAl[2][4], fBh[4][4], fBl[4][4];
#pragma unroll
            for (int mi = 0; mi < 2; mi++) {
                uint32_t off = 2u * ((wm + mi * 16 + arow) * RS + ksp * 16 + acol);
                ldmx4(fAh[mi], uAh + off);
                ldmx4(fAl[mi], uAl + off);
            }
#pragma unroll
            for (int nb = 0; nb < 4; nb++) {
                uint32_t off = 2u * ((wn + nb * 16 + bn_off) * RS + ksp * 16 + bk_off);
                ldmx4(fBh[nb], uBh + off);
                ldmx4(fBl[nb], uBl + off);
            }
#pragma unroll
            for (int mi = 0; mi < 2; mi++)
#pragma unroll
                for (int nf = 0; nf < 8; nf++) {
                    const uint32_t* bh = &fBh[nf >> 1][(nf & 1) * 2];
                    const uint32_t* bl = &fBl[nf >> 1][(nf & 1) * 2];
                    mma_bf16(acc[mi][nf], fAh[mi], bh[0], bh[1]);
                    mma_bf16(acc[mi][nf], fAl[mi], bh[0], bh[1]);
                    mma_bf16(acc[mi][nf], fAh[mi], bl[0], bl[1]);
                }
        }
        __syncthreads();
    }

    const int erow = lane >> 2, ecol = (lane & 3) * 2;
#pragma unroll
    for (int mi = 0; mi < 2; mi++) {
        int r0 = m0 + wm + mi * 16 + erow;
#pragma unroll
        for (int half = 0; half < 2; half++) {
            int r = r0 + half * 8;
            if (r >= M) continue;
#pragma unroll
            for (int nf = 0; nf < 8; nf++) {
                int col = n0 + wn + nf * 8 + ecol;
                float x0 = acc[mi][nf][half * 2 + 0] + __ldg(bias + col);
                float x1 = acc[mi][nf][half * 2 + 1] + __ldg(bias + col + 1);
                uint32_t hp, lp;
                split2_pack(x0, x1, hp, lp);
                size_t o = (size_t)r * Nout + col;
                *(uint32_t*)(Ch + o) = hp;
                *(uint32_t*)(Cl + o) = lp;
            }
        }
    }
}

// ============ HMMA bf16x3 NT GEMM, fp32 out (output projections) ===========
__global__ void __launch_bounds__(256) hmma_gemm(
    const __nv_bfloat16* __restrict__ Ah0, const __nv_bfloat16* __restrict__ Al0,
    const __nv_bfloat16* __restrict__ Wh0, const __nv_bfloat16* __restrict__ Wl0,
    const float* __restrict__ b0, float* __restrict__ C0,
    const __nv_bfloat16* __restrict__ Ah1, const __nv_bfloat16* __restrict__ Al1,
    const __nv_bfloat16* __restrict__ Wh1, const __nv_bfloat16* __restrict__ Wl1,
    const float* __restrict__ b1, float* __restrict__ C1,
    int M, int Nout, int lda, int kPerCta, int splitk, size_t sliceStride)
{
    __shared__ __align__(16) __nv_bfloat16 sAh[128 * RS];
    __shared__ __align__(16) __nv_bfloat16 sAl[128 * RS];
    __shared__ __align__(16) __nv_bfloat16 sBh[128 * RS];
    __shared__ __align__(16) __nv_bfloat16 sBl[128 * RS];

    const int tid = threadIdx.x, wid = tid >> 5, lane = tid & 31;
    const int z  = blockIdx.z / splitk;
    const int ks = blockIdx.z % splitk;
    const __nv_bfloat16* Ah = z ? Ah1 : Ah0;
    const __nv_bfloat16* Al = z ? Al1 : Al0;
    const __nv_bfloat16* Wh = z ? Wh1 : Wh0;
    const __nv_bfloat16* Wl = z ? Wl1 : Wl0;
    const float* bias = z ? b1 : b0;
    float* Cp = (z ? C1 : C0) + (size_t)ks * sliceStride;

    const int m0 = blockIdx.y * 128;
    const int n0 = blockIdx.x * 128;
    const int kBegin = ks * kPerCta;
    const int NC = kPerCta / 32;

    const int wm = (wid & 3) * 32;
    const int wn = (wid >> 2) * 64;
    const int lrow = tid >> 2;
    const int lseg = (tid & 3) * 8;

    float acc[2][8][4];
#pragma unroll
    for (int i = 0; i < 2; i++)
#pragma unroll
        for (int j = 0; j < 8; j++)
#pragma unroll
            for (int q = 0; q < 4; q++) acc[i][j][q] = 0.f;

    uint4 rA[2], rAl[2], rB[2], rBl[2];

    auto load_regs = [&](int c) {
        const int kk = kBegin + c * 32;
#pragma unroll
        for (int j = 0; j < 2; j++) {
            int row = lrow + 64 * j;
            int gm = m0 + row;
            if (gm < M) {
                size_t go = (size_t)gm * lda + kk + lseg;
                rA[j]  = *(const uint4*)(Ah + go);
                rAl[j] = *(const uint4*)(Al + go);
            } else {
                rA[j] = rAl[j] = make_uint4(0u, 0u, 0u, 0u);
            }
            size_t gw = (size_t)(n0 + row) * lda + kk + lseg;
            rB[j]  = *(const uint4*)(Wh + gw);
            rBl[j] = *(const uint4*)(Wl + gw);
        }
    };
    auto store_smem = [&]() {
#pragma unroll
        for (int j = 0; j < 2; j++) {
            int off = (lrow + 64 * j) * RS + lseg;
            *(uint4*)(sAh + off) = rA[j];
            *(uint4*)(sAl + off) = rAl[j];
            *(uint4*)(sBh + off) = rB[j];
            *(uint4*)(sBl + off) = rBl[j];
        }
    };

    const uint32_t uAh = smem_u32(sAh), uAl = smem_u32(sAl);
    const uint32_t uBh = smem_u32(sBh), uBl = smem_u32(sBl);
    const int arow = lane & 15, acol = (lane >> 4) * 8;
    const int bgrp = lane >> 3, brow = lane & 7;
    const int bn_off = (bgrp >> 1) * 8 + brow;
    const int bk_off = (bgrp & 1) * 8;

    load_regs(0);

    for (int c = 0; c < NC; c++) {
        store_smem();
        __syncthreads();
        if (c + 1 < NC) load_regs(c + 1);

#pragma unroll
        for (int ksp = 0; ksp < 2; ksp++) {
            uint32_t fAh[2][4], fAl[2][4], fBh[4][4], fBl[4][4];
#pragma unroll
            for (int mi = 0; mi < 2; mi++) {
                uint32_t off = 2u * ((wm + mi * 16 + arow) * RS + ksp * 16 + acol);
                ldmx4(fAh[mi], uAh + off);
                ldmx4(fAl[mi], uAl + off);
            }
#pragma unroll
            for (int nb = 0; nb < 4; nb++) {
                uint32_t off = 2u * ((wn + nb * 16 + bn_off) * RS + ksp * 16 + bk_off);
                ldmx4(fBh[nb], uBh + off);
                ldmx4(fBl[nb], uBl + off);
            }
#pragma unroll
            for (int mi = 0; mi < 2; mi++)
#pragma unroll
                for (int nf = 0; nf < 8; nf++) {
                    const uint32_t* bh = &fBh[nf >> 1][(nf & 1) * 2];
                    const uint32_t* bl = &fBl[nf >> 1][(nf & 1) * 2];
                    mma_bf16(acc[mi][nf], fAh[mi], bh[0], bh[1]);
                    mma_bf16(acc[mi][nf], fAl[mi], bh[0], bh[1]);
                    mma_bf16(acc[mi][nf], fAh[mi], bl[0], bl[1]);
                }
        }
        __syncthreads();
    }

    const bool addB = (ks == 0);
    const int erow = lane >> 2, ecol = (lane & 3) * 2;
#pragma unroll
    for (int mi = 0; mi < 2; mi++) {
        int r0 = m0 + wm + mi * 16 + erow;
#pragma unroll
        for (int half = 0; half < 2; half++) {
            int r = r0 + half * 8;
            if (r >= M) continue;
#pragma unroll
            for (int nf = 0; nf < 8; nf++) {
                int col = n0 + wn + nf * 8 + ecol;
                float x0 = acc[mi][nf][half * 2 + 0];
                float x1 = acc[mi][nf][half * 2 + 1];
                if (addB) { x0 += __ldg(bias + col); x1 += __ldg(bias + col + 1); }
                *(float2*)(Cp + (size_t)r * Nout + col) = make_float2(x0, x1);
            }
        }
    }
}

// ================== fused per-(bn,g) kernel (full HMMA, 32 KB smem) ========
static constexpr int STW = 72;
static constexpr int STN = 40;

__device__ __forceinline__ void ln2048_relu(float acc[4][4], float* red) {
    float s = 0.f, q = 0.f;
#pragma unroll
    for (int i = 0; i < 4; i++)
#pragma unroll
        for (int j = 0; j < 4; j++) { s += acc[i][j]; q += acc[i][j] * acc[i][j]; }
#pragma unroll
    for (int o = 16; o > 0; o >>= 1) {
        s += __shfl_xor_sync(0xffffffffu, s, o);
        q += __shfl_xor_sync(0xffffffffu, q, o);
    }
    int w = threadIdx.x >> 5;
    __syncthreads();
    if ((threadIdx.x & 31) == 0) { red[w] = s; red[4 + w] = q; }
    __syncthreads();
    s = red[0] + red[1] + red[2] + red[3];
    q = red[4] + red[5] + red[6] + red[7];
    float mean = s * (1.f / 2048.f);
    float var  = q * (1.f / 2048.f) - mean * mean;
    float inv  = rsqrtf(var + 1e-5f);
#pragma unroll
    for (int i = 0; i < 4; i++)
#pragma unroll
        for (int j = 0; j < 4; j++)
            acc[i][j] = fmaxf((acc[i][j] - mean) * inv, 0.f);
}

struct ALoadS {
    uint32_t addrH, addrL;
    __device__ __forceinline__ void load(int kt, uint32_t aH[4], uint32_t aL[4]) const {
        ldmx4(aH, addrH + kt * 32);
        ldmx4(aL, addrL + kt * 32);
    }
};
struct ALoadGB {
    const __nv_bfloat16 *H, *L; int ld, r0, k0;
    __device__ __forceinline__ void load(int kt, uint32_t aH[4], uint32_t aL[4]) const {
        int k = kt * 16 + k0;
        aH[0] = *(const uint32_t*)(H + r0 * ld + k);
        aH[1] = *(const uint32_t*)(H + (r0 + 8) * ld + k);
        aH[2] = *(const uint32_t*)(H + r0 * ld + k + 8);
        aH[3] = *(const uint32_t*)(H + (r0 + 8) * ld + k + 8);
        aL[0] = *(const uint32_t*)(L + r0 * ld + k);
        aL[1] = *(const uint32_t*)(L + (r0 + 8) * ld + k);
        aL[2] = *(const uint32_t*)(L + r0 * ld + k + 8);
        aL[3] = *(const uint32_t*)(L + (r0 + 8) * ld + k + 8);
    }
};
struct ALoadGF {
    const float* A; int ld, r0, k0;
    __device__ __forceinline__ void load(int kt, uint32_t aH[4], uint32_t aL[4]) const {
        int k = kt * 16 + k0;
        float2 v0 = *(const float2*)(A + r0 * ld + k);
        float2 v1 = *(const float2*)(A + (r0 + 8) * ld + k);
        float2 v2 = *(const float2*)(A + r0 * ld + k + 8);
        float2 v3 = *(const float2*)(A + (r0 + 8) * ld + k + 8);
        split2_pack(v0.x, v0.y, aH[0], aL[0]);
        split2_pack(v1.x, v1.y, aH[1], aL[1]);
        split2_pack(v2.x, v2.y, aH[2], aL[2]);
        split2_pack(v3.x, v3.y, aH[3], aL[3]);
    }
};

template<class AL, int NB, int KT, bool TRANS, int SB>
__device__ __forceinline__ void mm_frag2(float acc[NB][4], const AL& al,
    const __nv_bfloat16* BH, const __nv_bfloat16* BL, int wn, int lane)
{
    const int b1 = ((lane >> 4) << 3) + (lane & 7);
    const int b2 = ((lane >> 3) & 1) * 8;
#pragma unroll
    for (int i = 0; i < NB; i++)
#pragma unroll
        for (int j = 0; j < 4; j++) acc[i][j] = 0.f;
#pragma unroll
    for (int kt = 0; kt < KT; kt++) {
        uint32_t aH[4], aL[4];
        al.load(kt, aH, aL);
#pragma unroll
        for (int nt = 0; nt < NB / 2; nt++) {
            uint32_t bH[4], bL[4];
            if (TRANS) {
                ldmx4_t(bH, smem_u32(BH + (kt * 16 + b1) * SB + wn + nt * 16 + b2));
                ldmx4_t(bL, smem_u32(BL + (kt * 16 + b1) * SB + wn + nt * 16 + b2));
            } else {
                ldmx4(bH, smem_u32(BH + (wn + nt * 16 + b1) * SB + kt * 16 + b2));
                ldmx4(bL, smem_u32(BL + (wn + nt * 16 + b1) * SB + kt * 16 + b2));
            }
#pragma unroll
            for (int h = 0; h < 2; h++) {
                int nb = nt * 2 + h;
                uint32_t h0, h1, l0, l1;
                if (TRANS) { h0 = bH[h]; h1 = bH[h + 2]; l0 = bL[h]; l1 = bL[h + 2]; }
                else       { h0 = bH[2 * h]; h1 = bH[2 * h + 1];
                             l0 = bL[2 * h]; l1 = bL[2 * h + 1]; }
                mma_bf16(acc[nb], aH, h0, h1);
                mma_bf16(acc[nb], aL, h0, h1);
                mma_bf16(acc[nb], aH, l0, l1);
            }
        }
    }
}

template<int W, int ST>
__device__ __forceinline__ void load_bf16_smem(const __nv_bfloat16* __restrict__ srcH,
                                               const __nv_bfloat16* __restrict__ srcL,
                                               int n, __nv_bfloat16* dh,
                                               __nv_bfloat16* dl, int tid)
{
#pragma unroll
    for (int idx = tid * 8; idx < n; idx += 1024) {
        int row = idx / W, col = idx % W;
        *(uint4*)(dh + row * ST + col) = *(const uint4*)(srcH + idx);
        *(uint4*)(dl + row * ST + col) = *(const uint4*)(srcL + idx);
    }
}

__global__ void __launch_bounds__(128, 6) fused_bg(
    const float* __restrict__ feats,
    const float* __restrict__ kw_g, const float* __restrict__ kb_g)
{
    __shared__ __align__(16) __nv_bfloat16 wS[2 * 64 * STW];
    __shared__ __align__(16) __nv_bfloat16 xS[2 * 32 * STW];
    __shared__ __align__(16) __nv_bfloat16 sS[2 * 32 * STN];
    __shared__ float red[8];

    __nv_bfloat16 *wH = wS, *wL = wS + 64 * STW;
    __nv_bfloat16 *xH = xS, *xL = xS + 32 * STW;
    __nv_bfloat16 *sH = sS, *sL = sS + 32 * STN;
    float* sc = (float*)wS;

    const int bn = blockIdx.x, g = blockIdx.y;
    const int tid = threadIdx.x;
    const int lane = tid & 31, wrp = tid >> 5;
    const int rw   = (wrp & 1) * 16;
    const int wn32 = (wrp >> 1) * 32;
    const int wn16 = (wrp >> 1) * 16;
    const int lr = lane >> 2, lc = 2 * (lane & 3);
    const int fr0 = rw + lr, fk0 = lc;
    const size_t bg = (size_t)bn * 4 + g;

    load_bf16_smem<64, STW>(g_Mh + bg * 4096, g_Ml + bg * 4096, 4096, wH, wL, tid);
    __syncthreads();

    float acc[4][4];
    const ALoadGF af{feats + bg * 2048, 64, fr0, fk0};

    // stage 1: fM = relu(ln2d(f @ M)) -> x
    mm_frag2<ALoadGF, 4, 4, true, STW>(acc, af, wH, wL, wn32, lane);
    ln2048_relu(acc, red);
    load_bf16_smem<64, STW>(g_Vh + bg * 4096, g_Vl + bg * 4096, 4096, wH, wL, tid);
#pragma unroll
    for (int nb = 0; nb < 4; nb++) {
        int c = wn32 + nb * 8 + lc;
        uint32_t hp, lp;
        split2_pack(acc[nb][0], acc[nb][1], hp, lp);
        *(uint32_t*)(xH + fr0 * STW + c) = hp;
        *(uint32_t*)(xL + fr0 * STW + c) = lp;
        split2_pack(acc[nb][2], acc[nb][3], hp, lp);
        *(uint32_t*)(xH + (fr0 + 8) * STW + c) = hp;
        *(uint32_t*)(xL + (fr0 + 8) * STW + c) = lp;
    }
    __syncthreads();

    // stage 2: fMS = relu(ln2d(S @ fM)) -> global
    {
        const ALoadGB as{g_Sh + bg * 1024, g_Sl + bg * 1024, 32, fr0, fk0};
        mm_frag2<ALoadGB, 4, 2, true, STW>(acc, as, xH, xL, wn32, lane);
    }
    ln2048_relu(acc, red);
#pragma unroll
    for (int nb = 0; nb < 4; nb++) {
        int c = wn32 + nb * 8 + lc;
        size_t o0 = bg * 2048 + (size_t)fr0 * 64 + c;
        size_t o1 = o0 + 8 * 64;
        uint32_t hp, lp;
        split2_pack(acc[nb][0], acc[nb][1], hp, lp);
        *(uint32_t*)(g_FMSh + o0) = hp;
        *(uint32_t*)(g_FMSl + o0) = lp;
        split2_pack(acc[nb][2], acc[nb][3], hp, lp);
        *(uint32_t*)(g_FMSh + o1) = hp;
        *(uint32_t*)(g_FMSl + o1) = lp;
    }
    __syncthreads();

    // stage 3: v = relu(ln2d(f @ Vw)) -> x
    mm_frag2<ALoadGF, 4, 4, true, STW>(acc, af, wH, wL, wn32, lane);
    ln2048_relu(acc, red);
#pragma unroll
    for (int nb = 0; nb < 4; nb++) {
        int c = wn32 + nb * 8 + lc;
        uint32_t hp, lp;
        split2_pack(acc[nb][0], acc[nb][1], hp, lp);
        *(uint32_t*)(xH + fr0 * STW + c) = hp;
        *(uint32_t*)(xL + fr0 * STW + c) = lp;
        split2_pack(acc[nb][2], acc[nb][3], hp, lp);
        *(uint32_t*)(xH + (fr0 + 8) * STW + c) = hp;
        *(uint32_t*)(xL + (fr0 + 8) * STW + c) = lp;
    }
    __syncthreads();

    float a2[2][4];

    // stage 4: k[i][p] = kw @ v^T + kb -> s region
    {
        const ALoadGF akw{kw_g + g * 2048, 64, fr0, fk0};
        mm_frag2<ALoadGF, 2, 4, false, STW>(a2, akw, xH, xL, wn16, lane);
        float b0 = __ldg(kb_g + g * 32 + fr0);
        float b1 = __ldg(kb_g + g * 32 + fr0 + 8);
#pragma unroll
        for (int nb = 0; nb < 2; nb++) {
            int c = wn16 + nb * 8 + lc;
            uint32_t hp, lp;
            split2_pack(a2[nb][0] + b0, a2[nb][1] + b0, hp, lp);
            *(uint32_t*)(sH + fr0 * STN + c) = hp;
            *(uint32_t*)(sL + fr0 * STN + c) = lp;
            split2_pack(a2[nb][2] + b1, a2[nb][3] + b1, hp, lp);
            *(uint32_t*)(sH + (fr0 + 8) * STN + c) = hp;
            *(uint32_t*)(sL + (fr0 + 8) * STN + c) = lp;
        }
    }
    __syncthreads();

    // stage 5: scores = q @ k -> sc
    {
        const ALoadGB aq{g_Qh + bg * 1024, g_Ql + bg * 1024, 32, fr0, fk0};
        mm_frag2<ALoadGB, 2, 2, true, STN>(a2, aq, sH, sL, wn16, lane);
#pragma unroll
        for (int nb = 0; nb < 2; nb++) {
            int c = wn16 + nb * 8 + lc;
            *(float2*)(sc + fr0 * 36 + c)       = make_float2(a2[nb][0], a2[nb][1]);
            *(float2*)(sc + (fr0 + 8) * 36 + c) = make_float2(a2[nb][2], a2[nb][3]);
        }
    }
    __syncthreads();

    // stage 6: softmax
    {
        const int tx8 = tid & 7, ty16 = tid >> 3;
#pragma unroll
        for (int i = 0; i < 2; i++) {
            int row = 2 * ty16 + i;
            float v[4];
#pragma unroll
            for (int j = 0; j < 4; j++) v[j] = sc[row * 36 + 4 * tx8 + j];
            float m = fmaxf(fmaxf(v[0], v[1]), fmaxf(v[2], v[3]));
#pragma unroll
            for (int o = 4; o > 0; o >>= 1)
                m = fmaxf(m, __shfl_xor_sync(0xffffffffu, m, o));
            float s = 0.f;
#pragma unroll
            for (int j = 0; j < 4; j++) { v[j] = __expf((v[j] - m) * 0.125f); s += v[j]; }
#pragma unroll
            for (int o = 4; o > 0; o >>= 1)
                s += __shfl_xor_sync(0xffffffffu, s, o);
            float inv = __frcp_rn(s);
#pragma unroll
            for (int j = 0; j < 4; j++) {
                float p = v[j] * inv;
                __nv_bfloat16 h, l;
                split_bf16(p, h, l);
                sH[row * STN + 4 * tx8 + j] = h;
                sL[row * STN + 4 * tx8 + j] = l;
            }
        }
    }
    __syncthreads();

    // stage 7: fc = relu(ln2d(att @ v)) -> global
    {
        const ALoadS aatt{
            smem_u32(sH + (rw + (lane & 15)) * STN + (lane >> 4) * 8),
            smem_u32(sL + (rw + (lane & 15)) * STN + (lane >> 4) * 8)};
        mm_frag2<ALoadS, 4, 2, true, STW>(acc, aatt, xH, xL, wn32, lane);
    }
    ln2048_relu(acc, red);
#pragma unroll
    for (int nb = 0; nb < 4; nb++) {
        int c = wn32 + nb * 8 + lc;
        size_t o0 = bg * 2048 + (size_t)fr0 * 64 + c;
        size_t o1 = o0 + 8 * 64;
        uint32_t hp, lp;
        split2_pack(acc[nb][0], acc[nb][1], hp, lp);
        *(uint32_t*)(g_FCh + o0) = hp;
        *(uint32_t*)(g_FCl + o0) = lp;
        split2_pack(acc[nb][2], acc[nb][3], hp, lp);
        *(uint32_t*)(g_FCh + o1) = hp;
        *(uint32_t*)(g_FCl + o1) = lp;
    }
}

// ============== residual + split-K reduce + affine LayerNorm ===============
__global__ void __launch_bounds__(256) final_ln(
    const float* __restrict__ qv,
    const float* __restrict__ wA, const float* __restrict__ bA,
    const float* __restrict__ wB, const float* __restrict__ bB,
    float* __restrict__ out)
{
    const int r = blockIdx.x, z = blockIdx.y, c = threadIdx.x;
    const float* w = z ? wB : wA;
    const float* b = z ? bB : bA;
    float x = qv[(size_t)r * 256 + c];
#pragma unroll
    for (int k = 0; k < 4; k++)
        x += g_P[(size_t)(z * 4 + k) * 614400 + (size_t)r * 256 + c];

    __shared__ float sred[16];
    float s = x, q = x * x;
#pragma unroll
    for (int o = 16; o > 0; o >>= 1) {
        s += __shfl_xor_sync(0xffffffffu, s, o);
        q += __shfl_xor_sync(0xffffffffu, q, o);
    }
    int wp = threadIdx.x >> 5;
    if ((threadIdx.x & 31) == 0) { sred[wp] = s; sred[8 + wp] = q; }
    __syncthreads();
    float S = 0.f, Q2 = 0.f;
#pragma unroll
    for (int i = 0; i < 8; i++) { S += sred[i]; Q2 += sred[8 + i]; }
    float mean = S * (1.f / 256.f);
    float var  = Q2 * (1.f / 256.f) - mean * mean;
    float inv  = rsqrtf(var + 1e-5f);
    out[(size_t)z * 614400 + (size_t)r * 256 + c] = (x - mean) * inv * w[c] + b[c];
}

// ================================ launcher =================================
extern "C" void kernel_launch(void* const* d_in, const int* in_sizes, int n_in,
                              void* d_out, int out_size)
{
    const float* feats = (const float*)d_in[0];
    const float* qv    = (const float*)d_in[1];
    const float* m_w   = (const float*)d_in[7];
    const float* m_b   = (const float*)d_in[8];
    const float* s_w   = (const float*)d_in[9];
    const float* s_b   = (const float*)d_in[10];
    const float* q_w   = (const float*)d_in[11];
    const float* q_b   = (const float*)d_in[12];
    const float* v_w   = (const float*)d_in[13];
    const float* v_b   = (const float*)d_in[14];
    const float* k_w   = (const float*)d_in[15];
    const float* k_b   = (const float*)d_in[16];
    const float* Wv_w  = (const float*)d_in[17];
    const float* Wv_b  = (const float*)d_in[18];
    const float* Wv2_w = (const float*)d_in[19];
    const float* Wv2_b = (const float*)d_in[20];
    const float* lnA_w = (const float*)d_in[21];
    const float* lnA_b = (const float*)d_in[22];
    const float* lnB_w = (const float*)d_in[23];
    const float* lnB_b = (const float*)d_in[24];
    float* out = (float*)d_out;

    float* gP;
    cudaGetSymbolAddress((void**)&gP, g_P);
    __nv_bfloat16 *Wvh, *Wvl, *W2h, *W2l, *FMSh, *FMSl, *FCh, *FCl;
    cudaGetSymbolAddress((void**)&Wvh, g_Wvh);   cudaGetSymbolAddress((void**)&Wvl, g_Wvl);
    cudaGetSymbolAddress((void**)&W2h, g_W2h);   cudaGetSymbolAddress((void**)&W2l, g_W2l);
    cudaGetSymbolAddress((void**)&FMSh, g_FMSh); cudaGetSymbolAddress((void**)&FMSl, g_FMSl);
    cudaGetSymbolAddress((void**)&FCh, g_FCh);   cudaGetSymbolAddress((void**)&FCl, g_FCl);

    // 0) split fp32 operands into bf16 hi/lo
    split_kernel<<<dim3(4096, 1, 7), 256>>>(qv, m_w, v_w, s_w, q_w, Wv_w, Wv2_w);

    // 1) merged M/V/S/Q generators (m-fastest raster for L2 B-reuse)
    gen_gemm<<<dim3(19, 128, 4), 256>>>(m_b, v_b, s_b, q_b);

    // 2) fused per-(bn,g) dynamic conv + attention
    fused_bg<<<dim3(2400, 4), 128>>>(feats, k_w, k_b);

    // 3) output projections: (2400x8192) @ (256x8192)^T, split-K=4, fp32 out
    hmma_gemm<<<dim3(2, 19, 8), 256>>>(
        FMSh, FMSl, Wvh, Wvl, Wv_b, gP,
        FCh,  FCl,  W2h, W2l, Wv2_b, gP + 4 * 614400,
        2400, 256, 8192, 2048, 4, 614400);

    // 4) residual + split-K reduce + affine LayerNorm
    final_ln<<<dim3(2400, 2), 256>>>(qv, lnA_w, lnA_b, lnB_w, lnB_b, out);
}

// round 11
// speedup vs baseline: 2.5172x; 1.1449x over previous
#include <cuda_runtime.h>
#include <cuda_bf16.h>
#include <cstdint>

// ============================ problem constants ============================
// B=8, N=300 -> BN=2400; G=4; P=O=32; CG=DG=64; IN_DIM=OUT_DIM=256; TEMPER=8

// ===================== scratch (__device__ globals) ========================
__device__ float g_P[9830400];    // split-K slices of (2400,256)

__device__ __nv_bfloat16 g_Mh[39321600], g_Ml[39321600];  // (bn, g*4096+c*64+d)
__device__ __nv_bfloat16 g_Vh[39321600], g_Vl[39321600];
__device__ __nv_bfloat16 g_Sh[9830400],  g_Sl[9830400];   // (bn, g*1024+o*32+p)
__device__ __nv_bfloat16 g_Qh[9830400],  g_Ql[9830400];

__device__ __nv_bfloat16 g_qvh[614400],  g_qvl[614400];
__device__ __nv_bfloat16 g_mwh[4194304], g_mwl[4194304];
__device__ __nv_bfloat16 g_vwh[4194304], g_vwl[4194304];
__device__ __nv_bfloat16 g_swh[1048576], g_swl[1048576];
__device__ __nv_bfloat16 g_qwh[1048576], g_qwl[1048576];
__device__ __nv_bfloat16 g_Wvh[2097152], g_Wvl[2097152];
__device__ __nv_bfloat16 g_W2h[2097152], g_W2l[2097152];
__device__ __nv_bfloat16 g_FMSh[19660800], g_FMSl[19660800];
__device__ __nv_bfloat16 g_FCh[19660800],  g_FCl[19660800];

// ============================ small helpers ================================
__device__ __forceinline__ uint32_t smem_u32(const void* p) {
    uint32_t a;
    asm("{ .reg .u64 t; cvta.to.shared.u64 t, %1; cvt.u32.u64 %0, t; }"
        : "=r"(a) : "l"(p));
    return a;
}
__device__ __forceinline__ void split_bf16(float x, __nv_bfloat16& h, __nv_bfloat16& l) {
    h = __float2bfloat16(x);
    l = __float2bfloat16(x - __bfloat162float(h));
}
__device__ __forceinline__ void ldmx4(uint32_t r[4], uint32_t addr) {
    asm volatile("ldmatrix.sync.aligned.m8n8.x4.shared.b16 {%0,%1,%2,%3}, [%4];"
                 : "=r"(r[0]), "=r"(r[1]), "=r"(r[2]), "=r"(r[3]) : "r"(addr));
}
__device__ __forceinline__ void ldmx4_t(uint32_t r[4], uint32_t addr) {
    asm volatile("ldmatrix.sync.aligned.m8n8.x4.trans.shared.b16 {%0,%1,%2,%3}, [%4];"
                 : "=r"(r[0]), "=r"(r[1]), "=r"(r[2]), "=r"(r[3]) : "r"(addr));
}
__device__ __forceinline__ void mma_bf16(float d[4], const uint32_t a[4],
                                         const uint32_t b0, const uint32_t b1) {
    asm volatile(
        "mma.sync.aligned.m16n8k16.row.col.f32.bf16.bf16.f32 "
        "{%0,%1,%2,%3}, {%4,%5,%6,%7}, {%8,%9}, {%0,%1,%2,%3};"
        : "+f"(d[0]), "+f"(d[1]), "+f"(d[2]), "+f"(d[3])
        : "r"(a[0]), "r"(a[1]), "r"(a[2]), "r"(a[3]), "r"(b0), "r"(b1));
}
__device__ __forceinline__ void split2_pack(float a, float b, uint32_t& hp, uint32_t& lp) {
    __nv_bfloat16 ha = __float2bfloat16(a), hb = __float2bfloat16(b);
    union { __nv_bfloat16 h[2]; uint32_t u; } H, L;
    H.h[0] = ha; H.h[1] = hb;
    L.h[0] = __float2bfloat16(a - __bfloat162float(ha));
    L.h[1] = __float2bfloat16(b - __bfloat162float(hb));
    hp = H.u; lp = L.u;
}
// cp.async helpers
__device__ __forceinline__ void cp_async16(uint32_t saddr, const void* g) {
    asm volatile("cp.async.cg.shared.global [%0], [%1], 16;"
                 :: "r"(saddr), "l"(g));
}
__device__ __forceinline__ void cp_async16p(uint32_t saddr, const void* g, bool v) {
    int sz = v ? 16 : 0;
    asm volatile("cp.async.cg.shared.global [%0], [%1], 16, %2;"
                 :: "r"(saddr), "l"(g), "r"(sz));
}
__device__ __forceinline__ void cp_commit() {
    asm volatile("cp.async.commit_group;" ::: "memory");
}
__device__ __forceinline__ void cp_wait0() {
    asm volatile("cp.async.wait_group 0;" ::: "memory");
}

// ================= operand split prep (fp32 -> bf16 hi/lo) =================
__global__ void __launch_bounds__(256) split_kernel(
    const float* __restrict__ qv, const float* __restrict__ mw,
    const float* __restrict__ vw, const float* __restrict__ sw,
    const float* __restrict__ qw, const float* __restrict__ Wv,
    const float* __restrict__ W2)
{
    const float* src; __nv_bfloat16 *dh, *dl; int n;
    switch (blockIdx.z) {
        case 0: src = qv; dh = g_qvh; dl = g_qvl; n = 614400;  break;
        case 1: src = mw; dh = g_mwh; dl = g_mwl; n = 4194304; break;
        case 2: src = vw; dh = g_vwh; dl = g_vwl; n = 4194304; break;
        case 3: src = sw; dh = g_swh; dl = g_swl; n = 1048576; break;
        case 4: src = qw; dh = g_qwh; dl = g_qwl; n = 1048576; break;
        case 5: src = Wv; dh = g_Wvh; dl = g_Wvl; n = 2097152; break;
        default:src = W2; dh = g_W2h; dl = g_W2l; n = 2097152; break;
    }
    int i = (blockIdx.x * 256 + threadIdx.x) * 4;
    if (i >= n) return;
    float4 v = *(const float4*)(src + i);
    union U { __nv_bfloat16 b[4]; uint2 u; } H, L;
    split_bf16(v.x, H.b[0], L.b[0]);
    split_bf16(v.y, H.b[1], L.b[1]);
    split_bf16(v.z, H.b[2], L.b[2]);
    split_bf16(v.w, H.b[3], L.b[3]);
    *(uint2*)(dh + i) = H.u;
    *(uint2*)(dl + i) = L.u;
}

// ================= shared GEMM core (cp.async 2-stage pipeline) ============
static constexpr int RS = 40;                       // smem row stride (bf16)
static constexpr int BUF = 128 * RS * 2;            // one operand buffer, bytes
static constexpr int STAGE_BYTES = 4 * BUF;         // Ah|Al|Bh|Bl = 40960 B
static constexpr int GEMM_SMEM = 2 * STAGE_BYTES;   // 81920 B

__device__ __forceinline__ void gemm_core(
    float acc[2][8][4],
    const __nv_bfloat16* __restrict__ Ah, const __nv_bfloat16* __restrict__ Al,
    const __nv_bfloat16* __restrict__ Wh, const __nv_bfloat16* __restrict__ Wl,
    char* sm, int m0, int n0, int M, int lda, int kBegin, int NC)
{
    const int tid = threadIdx.x, wid = tid >> 5, lane = tid & 31;
    const int wm = (wid & 3) * 32;
    const int wn = (wid >> 2) * 64;
    const int lrow = tid >> 2;
    const int lseg = (tid & 3) * 8;
    const uint32_t smb = smem_u32(sm);

    const int arow = lane & 15, acol = (lane >> 4) * 8;
    const int bgrp = lane >> 3, brow = lane & 7;
    const int bn_off = (bgrp >> 1) * 8 + brow;
    const int bk_off = (bgrp & 1) * 8;

#pragma unroll
    for (int i = 0; i < 2; i++)
#pragma unroll
        for (int j = 0; j < 8; j++)
#pragma unroll
            for (int q = 0; q < 4; q++) acc[i][j][q] = 0.f;

    auto issue = [&](int c, int s) {
        const int kk = kBegin + c * 32;
        const uint32_t sb = smb + s * STAGE_BYTES;
#pragma unroll
        for (int j = 0; j < 2; j++) {
            int row = lrow + 64 * j;
            int gm = m0 + row;
            bool va = (gm < M);
            int gmc = va ? gm : (M - 1);
            uint32_t off = (uint32_t)(row * RS + lseg) * 2;
            cp_async16p(sb + off,           Ah + (size_t)gmc * lda + kk + lseg, va);
            cp_async16p(sb + BUF + off,     Al + (size_t)gmc * lda + kk + lseg, va);
            size_t gw = (size_t)(n0 + row) * lda + kk + lseg;
            cp_async16(sb + 2 * BUF + off, Wh + gw);
            cp_async16(sb + 3 * BUF + off, Wl + gw);
        }
    };

    issue(0, 0);
    cp_commit();

    for (int c = 0; c < NC; c++) {
        cp_wait0();
        __syncthreads();
        if (c + 1 < NC) { issue(c + 1, (c + 1) & 1); cp_commit(); }

        const uint32_t uAh = smb + (c & 1) * STAGE_BYTES;
        const uint32_t uAl = uAh + BUF;
        const uint32_t uBh = uAh + 2 * BUF;
        const uint32_t uBl = uAh + 3 * BUF;
#pragma unroll
        for (int ksp = 0; ksp < 2; ksp++) {
            uint32_t fAh[2][4], fAl[2][4], fBh[4][4], fBl[4][4];
#pragma unroll
            for (int mi = 0; mi < 2; mi++) {
                uint32_t off = 2u * ((wm + mi * 16 + arow) * RS + ksp * 16 + acol);
                ldmx4(fAh[mi], uAh + off);
                ldmx4(fAl[mi], uAl + off);
            }
#pragma unroll
            for (int nb = 0; nb < 4; nb++) {
                uint32_t off = 2u * ((wn + nb * 16 + bn_off) * RS + ksp * 16 + bk_off);
                ldmx4(fBh[nb], uBh + off);
                ldmx4(fBl[nb], uBl + off);
            }
#pragma unroll
            for (int mi = 0; mi < 2; mi++)
#pragma unroll
                for (int nf = 0; nf < 8; nf++) {
                    const uint32_t* bh = &fBh[nf >> 1][(nf & 1) * 2];
                    const uint32_t* bl = &fBl[nf >> 1][(nf & 1) * 2];
                    mma_bf16(acc[mi][nf], fAh[mi], bh[0], bh[1]);
                    mma_bf16(acc[mi][nf], fAl[mi], bh[0], bh[1]);
                    mma_bf16(acc[mi][nf], fAh[mi], bl[0], bl[1]);
                }
        }
        __syncthreads();
    }
}

// ====== merged generator GEMM (M/V/S/Q), m-fastest raster, bf16 out ========
__global__ void __launch_bounds__(256, 2) gen_gemm(
    const float* __restrict__ mb, const float* __restrict__ vb,
    const float* __restrict__ sb, const float* __restrict__ qb)
{
    extern __shared__ char sm[];

    const __nv_bfloat16 *Wh, *Wl; const float* bias;
    __nv_bfloat16 *Ch, *Cl; int Nout, nt;
    switch (blockIdx.z) {
        case 0: Wh = g_mwh; Wl = g_mwl; bias = mb; Ch = g_Mh; Cl = g_Ml;
                Nout = 16384; nt = 128; break;
        case 1: Wh = g_vwh; Wl = g_vwl; bias = vb; Ch = g_Vh; Cl = g_Vl;
                Nout = 16384; nt = 128; break;
        case 2: Wh = g_swh; Wl = g_swl; bias = sb; Ch = g_Sh; Cl = g_Sl;
                Nout = 4096;  nt = 32;  break;
        default:Wh = g_qwh; Wl = g_qwl; bias = qb; Ch = g_Qh; Cl = g_Ql;
                Nout = 4096;  nt = 32;  break;
    }
    if ((int)blockIdx.y >= nt) return;

    const int m0 = blockIdx.x * 128;
    const int n0 = blockIdx.y * 128;

    float acc[2][8][4];
    gemm_core(acc, g_qvh, g_qvl, Wh, Wl, sm, m0, n0, 2400, 256, 0, 8);

    const int lane = threadIdx.x & 31, wid = threadIdx.x >> 5;
    const int wm = (wid & 3) * 32, wn = (wid >> 2) * 64;
    const int erow = lane >> 2, ecol = (lane & 3) * 2;
#pragma unroll
    for (int mi = 0; mi < 2; mi++) {
        int r0 = m0 + wm + mi * 16 + erow;
#pragma unroll
        for (int half = 0; half < 2; half++) {
            int r = r0 + half * 8;
            if (r >= 2400) continue;
#pragma unroll
            for (int nf = 0; nf < 8; nf++) {
                int col = n0 + wn + nf * 8 + ecol;
                float x0 = acc[mi][nf][half * 2 + 0] + __ldg(bias + col);
                float x1 = acc[mi][nf][half * 2 + 1] + __ldg(bias + col + 1);
                uint32_t hp, lp;
                split2_pack(x0, x1, hp, lp);
                size_t o = (size_t)r * Nout + col;
                *(uint32_t*)(Ch + o) = hp;
                *(uint32_t*)(Cl + o) = lp;
            }
        }
    }
}

// ============ output-projection GEMM (split-K, fp32 out) ===================
__global__ void __launch_bounds__(256, 2) hmma_gemm(
    const __nv_bfloat16* __restrict__ Ah0, const __nv_bfloat16* __restrict__ Al0,
    const __nv_bfloat16* __restrict__ Wh0, const __nv_bfloat16* __restrict__ Wl0,
    const float* __restrict__ b0, float* __restrict__ C0,
    const __nv_bfloat16* __restrict__ Ah1, const __nv_bfloat16* __restrict__ Al1,
    const __nv_bfloat16* __restrict__ Wh1, const __nv_bfloat16* __restrict__ Wl1,
    const float* __restrict__ b1, float* __restrict__ C1,
    int M, int Nout, int lda, int kPerCta, int splitk, size_t sliceStride)
{
    extern __shared__ char sm[];

    const int z  = blockIdx.z / splitk;
    const int ks = blockIdx.z % splitk;
    const __nv_bfloat16* Ah = z ? Ah1 : Ah0;
    const __nv_bfloat16* Al = z ? Al1 : Al0;
    const __nv_bfloat16* Wh = z ? Wh1 : Wh0;
    const __nv_bfloat16* Wl = z ? Wl1 : Wl0;
    const float* bias = z ? b1 : b0;
    float* Cp = (z ? C1 : C0) + (size_t)ks * sliceStride;

    const int m0 = blockIdx.y * 128;
    const int n0 = blockIdx.x * 128;

    float acc[2][8][4];
    gemm_core(acc, Ah, Al, Wh, Wl, sm, m0, n0, M, lda, ks * kPerCta, kPerCta / 32);

    const bool addB = (ks == 0);
    const int lane = threadIdx.x & 31, wid = threadIdx.x >> 5;
    const int wm = (wid & 3) * 32, wn = (wid >> 2) * 64;
    const int erow = lane >> 2, ecol = (lane & 3) * 2;
#pragma unroll
    for (int mi = 0; mi < 2; mi++) {
        int r0 = m0 + wm + mi * 16 + erow;
#pragma unroll
        for (int half = 0; half < 2; half++) {
            int r = r0 + half * 8;
            if (r >= M) continue;
#pragma unroll
            for (int nf = 0; nf < 8; nf++) {
                int col = n0 + wn + nf * 8 + ecol;
                float x0 = acc[mi][nf][half * 2 + 0];
                float x1 = acc[mi][nf][half * 2 + 1];
                if (addB) { x0 += __ldg(bias + col); x1 += __ldg(bias + col + 1); }
                *(float2*)(Cp + (size_t)r * Nout + col) = make_float2(x0, x1);
            }
        }
    }
}

// ================== fused per-(bn,g) kernel (full HMMA, 32 KB smem) ========
static constexpr int STW = 72;
static constexpr int STN = 40;

__device__ __forceinline__ void ln2048_relu(float acc[4][4], float* red) {
    float s = 0.f, q = 0.f;
#pragma unroll
    for (int i = 0; i < 4; i++)
#pragma unroll
        for (int j = 0; j < 4; j++) { s += acc[i][j]; q += acc[i][j] * acc[i][j]; }
#pragma unroll
    for (int o = 16; o > 0; o >>= 1) {
        s += __shfl_xor_sync(0xffffffffu, s, o);
        q += __shfl_xor_sync(0xffffffffu, q, o);
    }
    int w = threadIdx.x >> 5;
    __syncthreads();
    if ((threadIdx.x & 31) == 0) { red[w] = s; red[4 + w] = q; }
    __syncthreads();
    s = red[0] + red[1] + red[2] + red[3];
    q = red[4] + red[5] + red[6] + red[7];
    float mean = s * (1.f / 2048.f);
    float var  = q * (1.f / 2048.f) - mean * mean;
    float inv  = rsqrtf(var + 1e-5f);
#pragma unroll
    for (int i = 0; i < 4; i++)
#pragma unroll
        for (int j = 0; j < 4; j++)
            acc[i][j] = fmaxf((acc[i][j] - mean) * inv, 0.f);
}

struct ALoadS {
    uint32_t addrH, addrL;
    __device__ __forceinline__ void load(int kt, uint32_t aH[4], uint32_t aL[4]) const {
        ldmx4(aH, addrH + kt * 32);
        ldmx4(aL, addrL + kt * 32);
    }
};
struct ALoadGB {
    const __nv_bfloat16 *H, *L; int ld, r0, k0;
    __device__ __forceinline__ void load(int kt, uint32_t aH[4], uint32_t aL[4]) const {
        int k = kt * 16 + k0;
        aH[0] = *(const uint32_t*)(H + r0 * ld + k);
        aH[1] = *(const uint32_t*)(H + (r0 + 8) * ld + k);
        aH[2] = *(const uint32_t*)(H + r0 * ld + k + 8);
        aH[3] = *(const uint32_t*)(H + (r0 + 8) * ld + k + 8);
        aL[0] = *(const uint32_t*)(L + r0 * ld + k);
        aL[1] = *(const uint32_t*)(L + (r0 + 8) * ld + k);
        aL[2] = *(const uint32_t*)(L + r0 * ld + k + 8);
        aL[3] = *(const uint32_t*)(L + (r0 + 8) * ld + k + 8);
    }
};
struct ALoadGF {
    const float* A; int ld, r0, k0;
    __device__ __forceinline__ void load(int kt, uint32_t aH[4], uint32_t aL[4]) const {
        int k = kt * 16 + k0;
        float2 v0 = *(const float2*)(A + r0 * ld + k);
        float2 v1 = *(const float2*)(A + (r0 + 8) * ld + k);
        float2 v2 = *(const float2*)(A + r0 * ld + k + 8);
        float2 v3 = *(const float2*)(A + (r0 + 8) * ld + k + 8);
        split2_pack(v0.x, v0.y, aH[0], aL[0]);
        split2_pack(v1.x, v1.y, aH[1], aL[1]);
        split2_pack(v2.x, v2.y, aH[2], aL[2]);
        split2_pack(v3.x, v3.y, aH[3], aL[3]);
    }
};

template<class AL, int NB, int KT, bool TRANS, int SB>
__device__ __forceinline__ void mm_frag2(float acc[NB][4], const AL& al,
    const __nv_bfloat16* BH, const __nv_bfloat16* BL, int wn, int lane)
{
    const int b1 = ((lane >> 4) << 3) + (lane & 7);
    const int b2 = ((lane >> 3) & 1) * 8;
#pragma unroll
    for (int i = 0; i < NB; i++)
#pragma unroll
        for (int j = 0; j < 4; j++) acc[i][j] = 0.f;
#pragma unroll
    for (int kt = 0; kt < KT; kt++) {
        uint32_t aH[4], aL[4];
        al.load(kt, aH, aL);
#pragma unroll
        for (int nt = 0; nt < NB / 2; nt++) {
            uint32_t bH[4], bL[4];
            if (TRANS) {
                ldmx4_t(bH, smem_u32(BH + (kt * 16 + b1) * SB + wn + nt * 16 + b2));
                ldmx4_t(bL, smem_u32(BL + (kt * 16 + b1) * SB + wn + nt * 16 + b2));
            } else {
                ldmx4(bH, smem_u32(BH + (wn + nt * 16 + b1) * SB + kt * 16 + b2));
                ldmx4(bL, smem_u32(BL + (wn + nt * 16 + b1) * SB + kt * 16 + b2));
            }
#pragma unroll
            for (int h = 0; h < 2; h++) {
                int nb = nt * 2 + h;
                uint32_t h0, h1, l0, l1;
                if (TRANS) { h0 = bH[h]; h1 = bH[h + 2]; l0 = bL[h]; l1 = bL[h + 2]; }
                else       { h0 = bH[2 * h]; h1 = bH[2 * h + 1];
                             l0 = bL[2 * h]; l1 = bL[2 * h + 1]; }
                mma_bf16(acc[nb], aH, h0, h1);
                mma_bf16(acc[nb], aL, h0, h1);
                mma_bf16(acc[nb], aH, l0, l1);
            }
        }
    }
}

template<int W, int ST>
__device__ __forceinline__ void load_bf16_smem(const __nv_bfloat16* __restrict__ srcH,
                                               const __nv_bfloat16* __restrict__ srcL,
                                               int n, __nv_bfloat16* dh,
                                               __nv_bfloat16* dl, int tid)
{
#pragma unroll
    for (int idx = tid * 8; idx < n; idx += 1024) {
        int row = idx / W, col = idx % W;
        *(uint4*)(dh + row * ST + col) = *(const uint4*)(srcH + idx);
        *(uint4*)(dl + row * ST + col) = *(const uint4*)(srcL + idx);
    }
}

__global__ void __launch_bounds__(128, 6) fused_bg(
    const float* __restrict__ feats,
    const float* __restrict__ kw_g, const float* __restrict__ kb_g)
{
    __shared__ __align__(16) __nv_bfloat16 wS[2 * 64 * STW];
    __shared__ __align__(16) __nv_bfloat16 xS[2 * 32 * STW];
    __shared__ __align__(16) __nv_bfloat16 sS[2 * 32 * STN];
    __shared__ float red[8];

    __nv_bfloat16 *wH = wS, *wL = wS + 64 * STW;
    __nv_bfloat16 *xH = xS, *xL = xS + 32 * STW;
    __nv_bfloat16 *sH = sS, *sL = sS + 32 * STN;
    float* sc = (float*)wS;

    const int bn = blockIdx.x, g = blockIdx.y;
    const int tid = threadIdx.x;
    const int lane = tid & 31, wrp = tid >> 5;
    const int rw   = (wrp & 1) * 16;
    const int wn32 = (wrp >> 1) * 32;
    const int wn16 = (wrp >> 1) * 16;
    const int lr = lane >> 2, lc = 2 * (lane & 3);
    const int fr0 = rw + lr, fk0 = lc;
    const size_t bg = (size_t)bn * 4 + g;

    load_bf16_smem<64, STW>(g_Mh + bg * 4096, g_Ml + bg * 4096, 4096, wH, wL, tid);
    __syncthreads();

    float acc[4][4];
    const ALoadGF af{feats + bg * 2048, 64, fr0, fk0};

    // stage 1: fM = relu(ln2d(f @ M)) -> x
    mm_frag2<ALoadGF, 4, 4, true, STW>(acc, af, wH, wL, wn32, lane);
    ln2048_relu(acc, red);
    load_bf16_smem<64, STW>(g_Vh + bg * 4096, g_Vl + bg * 4096, 4096, wH, wL, tid);
#pragma unroll
    for (int nb = 0; nb < 4; nb++) {
        int c = wn32 + nb * 8 + lc;
        uint32_t hp, lp;
        split2_pack(acc[nb][0], acc[nb][1], hp, lp);
        *(uint32_t*)(xH + fr0 * STW + c) = hp;
        *(uint32_t*)(xL + fr0 * STW + c) = lp;
        split2_pack(acc[nb][2], acc[nb][3], hp, lp);
        *(uint32_t*)(xH + (fr0 + 8) * STW + c) = hp;
        *(uint32_t*)(xL + (fr0 + 8) * STW + c) = lp;
    }
    __syncthreads();

    // stage 2: fMS = relu(ln2d(S @ fM)) -> global
    {
        const ALoadGB as{g_Sh + bg * 1024, g_Sl + bg * 1024, 32, fr0, fk0};
        mm_frag2<ALoadGB, 4, 2, true, STW>(acc, as, xH, xL, wn32, lane);
    }
    ln2048_relu(acc, red);
#pragma unroll
    for (int nb = 0; nb < 4; nb++) {
        int c = wn32 + nb * 8 + lc;
        size_t o0 = bg * 2048 + (size_t)fr0 * 64 + c;
        size_t o1 = o0 + 8 * 64;
        uint32_t hp, lp;
        split2_pack(acc[nb][0], acc[nb][1], hp, lp);
        *(uint32_t*)(g_FMSh + o0) = hp;
        *(uint32_t*)(g_FMSl + o0) = lp;
        split2_pack(acc[nb][2], acc[nb][3], hp, lp);
        *(uint32_t*)(g_FMSh + o1) = hp;
        *(uint32_t*)(g_FMSl + o1) = lp;
    }
    __syncthreads();

    // stage 3: v = relu(ln2d(f @ Vw)) -> x
    mm_frag2<ALoadGF, 4, 4, true, STW>(acc, af, wH, wL, wn32, lane);
    ln2048_relu(acc, red);
#pragma unroll
    for (int nb = 0; nb < 4; nb++) {
        int c = wn32 + nb * 8 + lc;
        uint32_t hp, lp;
        split2_pack(acc[nb][0], acc[nb][1], hp, lp);
        *(uint32_t*)(xH + fr0 * STW + c) = hp;
        *(uint32_t*)(xL + fr0 * STW + c) = lp;
        split2_pack(acc[nb][2], acc[nb][3], hp, lp);
        *(uint32_t*)(xH + (fr0 + 8) * STW + c) = hp;
        *(uint32_t*)(xL + (fr0 + 8) * STW + c) = lp;
    }
    __syncthreads();

    float a2[2][4];

    // stage 4: k[i][p] = kw @ v^T + kb -> s region
    {
        const ALoadGF akw{kw_g + g * 2048, 64, fr0, fk0};
        mm_frag2<ALoadGF, 2, 4, false, STW>(a2, akw, xH, xL, wn16, lane);
        float b0 = __ldg(kb_g + g * 32 + fr0);
        float b1 = __ldg(kb_g + g * 32 + fr0 + 8);
#pragma unroll
        for (int nb = 0; nb < 2; nb++) {
            int c = wn16 + nb * 8 + lc;
            uint32_t hp, lp;
            split2_pack(a2[nb][0] + b0, a2[nb][1] + b0, hp, lp);
            *(uint32_t*)(sH + fr0 * STN + c) = hp;
            *(uint32_t*)(sL + fr0 * STN + c) = lp;
            split2_pack(a2[nb][2] + b1, a2[nb][3] + b1, hp, lp);
            *(uint32_t*)(sH + (fr0 + 8) * STN + c) = hp;
            *(uint32_t*)(sL + (fr0 + 8) * STN + c) = lp;
        }
    }
    __syncthreads();

    // stage 5: scores = q @ k -> sc
    {
        const ALoadGB aq{g_Qh + bg * 1024, g_Ql + bg * 1024, 32, fr0, fk0};
        mm_frag2<ALoadGB, 2, 2, true, STN>(a2, aq, sH, sL, wn16, lane);
#pragma unroll
        for (int nb = 0; nb < 2; nb++) {
            int c = wn16 + nb * 8 + lc;
            *(float2*)(sc + fr0 * 36 + c)       = make_float2(a2[nb][0], a2[nb][1]);
            *(float2*)(sc + (fr0 + 8) * 36 + c) = make_float2(a2[nb][2], a2[nb][3]);
        }
    }
    __syncthreads();

    // stage 6: softmax
    {
        const int tx8 = tid & 7, ty16 = tid >> 3;
#pragma unroll
        for (int i = 0; i < 2; i++) {
            int row = 2 * ty16 + i;
            float v[4];
#pragma unroll
            for (int j = 0; j < 4; j++) v[j] = sc[row * 36 + 4 * tx8 + j];
            float m = fmaxf(fmaxf(v[0], v[1]), fmaxf(v[2], v[3]));
#pragma unroll
            for (int o = 4; o > 0; o >>= 1)
                m = fmaxf(m, __shfl_xor_sync(0xffffffffu, m, o));
            float s = 0.f;
#pragma unroll
            for (int j = 0; j < 4; j++) { v[j] = __expf((v[j] - m) * 0.125f); s += v[j]; }
#pragma unroll
            for (int o = 4; o > 0; o >>= 1)
                s += __shfl_xor_sync(0xffffffffu, s, o);
            float inv = __frcp_rn(s);
#pragma unroll
            for (int j = 0; j < 4; j++) {
                float p = v[j] * inv;
                __nv_bfloat16 h, l;
                split_bf16(p, h, l);
                sH[row * STN + 4 * tx8 + j] = h;
                sL[row * STN + 4 * tx8 + j] = l;
            }
        }
    }
    __syncthreads();

    // stage 7: fc = relu(ln2d(att @ v)) -> global
    {
        const ALoadS aatt{
            smem_u32(sH + (rw + (lane & 15)) * STN + (lane >> 4) * 8),
            smem_u32(sL + (rw + (lane & 15)) * STN + (lane >> 4) * 8)};
        mm_frag2<ALoadS, 4, 2, true, STW>(acc, aatt, xH, xL, wn32, lane);
    }
    ln2048_relu(acc, red);
#pragma unroll
    for (int nb = 0; nb < 4; nb++) {
        int c = wn32 + nb * 8 + lc;
        size_t o0 = bg * 2048 + (size_t)fr0 * 64 + c;
        size_t o1 = o0 + 8 * 64;
        uint32_t hp, lp;
        split2_pack(acc[nb][0], acc[nb][1], hp, lp);
        *(uint32_t*)(g_FCh + o0) = hp;
        *(uint32_t*)(g_FCl + o0) = lp;
        split2_pack(acc[nb][2], acc[nb][3], hp, lp);
        *(uint32_t*)(g_FCh + o1) = hp;
        *(uint32_t*)(g_FCl + o1) = lp;
    }
}

// ============== residual + split-K reduce + affine LayerNorm ===============
__global__ void __launch_bounds__(256) final_ln(
    const float* __restrict__ qv,
    const float* __restrict__ wA, const float* __restrict__ bA,
    const float* __restrict__ wB, const float* __restrict__ bB,
    float* __restrict__ out)
{
    const int r = blockIdx.x, z = blockIdx.y, c = threadIdx.x;
    const float* w = z ? wB : wA;
    const float* b = z ? bB : bA;
    float x = qv[(size_t)r * 256 + c];
#pragma unroll
    for (int k = 0; k < 4; k++)
        x += g_P[(size_t)(z * 4 + k) * 614400 + (size_t)r * 256 + c];

    __shared__ float sred[16];
    float s = x, q = x * x;
#pragma unroll
    for (int o = 16; o > 0; o >>= 1) {
        s += __shfl_xor_sync(0xffffffffu, s, o);
        q += __shfl_xor_sync(0xffffffffu, q, o);
    }
    int wp = threadIdx.x >> 5;
    if ((threadIdx.x & 31) == 0) { sred[wp] = s; sred[8 + wp] = q; }
    __syncthreads();
    float S = 0.f, Q2 = 0.f;
#pragma unroll
    for (int i = 0; i < 8; i++) { S += sred[i]; Q2 += sred[8 + i]; }
    float mean = S * (1.f / 256.f);
    float var  = Q2 * (1.f / 256.f) - mean * mean;
    float inv  = rsqrtf(var + 1e-5f);
    out[(size_t)z * 614400 + (size_t)r * 256 + c] = (x - mean) * inv * w[c] + b[c];
}

// ================================ launcher =================================
extern "C" void kernel_launch(void* const* d_in, const int* in_sizes, int n_in,
                              void* d_out, int out_size)
{
    const float* feats = (const float*)d_in[0];
    const float* qv    = (const float*)d_in[1];
    const float* m_w   = (const float*)d_in[7];
    const float* m_b   = (const float*)d_in[8];
    const float* s_w   = (const float*)d_in[9];
    const float* s_b   = (const float*)d_in[10];
    const float* q_w   = (const float*)d_in[11];
    const float* q_b   = (const float*)d_in[12];
    const float* v_w   = (const float*)d_in[13];
    const float* v_b   = (const float*)d_in[14];
    const float* k_w   = (const float*)d_in[15];
    const float* k_b   = (const float*)d_in[16];
    const float* Wv_w  = (const float*)d_in[17];
    const float* Wv_b  = (const float*)d_in[18];
    const float* Wv2_w = (const float*)d_in[19];
    const float* Wv2_b = (const float*)d_in[20];
    const float* lnA_w = (const float*)d_in[21];
    const float* lnA_b = (const float*)d_in[22];
    const float* lnB_w = (const float*)d_in[23];
    const float* lnB_b = (const float*)d_in[24];
    float* out = (float*)d_out;

    float* gP;
    cudaGetSymbolAddress((void**)&gP, g_P);
    __nv_bfloat16 *Wvh, *Wvl, *W2h, *W2l, *FMSh, *FMSl, *FCh, *FCl;
    cudaGetSymbolAddress((void**)&Wvh, g_Wvh);   cudaGetSymbolAddress((void**)&Wvl, g_Wvl);
    cudaGetSymbolAddress((void**)&W2h, g_W2h);   cudaGetSymbolAddress((void**)&W2l, g_W2l);
    cudaGetSymbolAddress((void**)&FMSh, g_FMSh); cudaGetSymbolAddress((void**)&FMSl, g_FMSl);
    cudaGetSymbolAddress((void**)&FCh, g_FCh);   cudaGetSymbolAddress((void**)&FCl, g_FCl);

    cudaFuncSetAttribute(gen_gemm, cudaFuncAttributeMaxDynamicSharedMemorySize, GEMM_SMEM);
    cudaFuncSetAttribute(hmma_gemm, cudaFuncAttributeMaxDynamicSharedMemorySize, GEMM_SMEM);

    // 0) split fp32 operands into bf16 hi/lo
    split_kernel<<<dim3(4096, 1, 7), 256>>>(qv, m_w, v_w, s_w, q_w, Wv_w, Wv2_w);

    // 1) merged M/V/S/Q generators (m-fastest raster, cp.async pipeline)
    gen_gemm<<<dim3(19, 128, 4), 256, GEMM_SMEM>>>(m_b, v_b, s_b, q_b);

    // 2) fused per-(bn,g) dynamic conv + attention
    fused_bg<<<dim3(2400, 4), 128>>>(feats, k_w, k_b);

    // 3) output projections: (2400x8192) @ (256x8192)^T, split-K=4
    hmma_gemm<<<dim3(2, 19, 8), 256, GEMM_SMEM>>>(
        FMSh, FMSl, Wvh, Wvl, Wv_b, gP,
        FCh,  FCl,  W2h, W2l, Wv2_b, gP + 4 * 614400,
        2400, 256, 8192, 2048, 4, 614400);

    // 4) residual + split-K reduce + affine LayerNorm
    final_ln<<<dim3(2400, 2), 256>>>(qv, lnA_w, lnA_b, lnB_w, lnB_b, out);
}

// round 12
// speedup vs baseline: 3.0661x; 1.2181x over previous
#include <cuda_runtime.h>
#include <cuda_fp16.h>
#include <cstdint>

// ============================ problem constants ============================
// B=8, N=300 -> BN=2400; G=4; P=O=32; CG=DG=64; IN_DIM=OUT_DIM=256; TEMPER=8

// ===================== scratch (__device__ globals) ========================
__device__ float g_P[9830400];    // split-K slices of (2400,256)

__device__ __half g_Mh[39321600], g_Ml[39321600];  // (bn, g*4096+c*64+d)
__device__ __half g_Vh[39321600], g_Vl[39321600];
__device__ __half g_Sh[9830400],  g_Sl[9830400];   // (bn, g*1024+o*32+p)
__device__ __half g_Qh[9830400],  g_Ql[9830400];

__device__ __half g_qvh[614400],  g_qvl[614400];
__device__ __half g_mwh[4194304], g_mwl[4194304];
__device__ __half g_vwh[4194304], g_vwl[4194304];
__device__ __half g_swh[1048576], g_swl[1048576];
__device__ __half g_qwh[1048576], g_qwl[1048576];
__device__ __half g_Wvh[2097152], g_Wvl[2097152];
__device__ __half g_W2h[2097152], g_W2l[2097152];
__device__ __half g_FMSh[19660800], g_FMSl[19660800];
__device__ __half g_FCh[19660800],  g_FCl[19660800];

// ============================ small helpers ================================
__device__ __forceinline__ uint32_t smem_u32(const void* p) {
    uint32_t a;
    asm("{ .reg .u64 t; cvta.to.shared.u64 t, %1; cvt.u32.u64 %0, t; }"
        : "=r"(a) : "l"(p));
    return a;
}
__device__ __forceinline__ void split_h(float x, __half& h, __half& l) {
    h = __float2half_rn(x);
    l = __float2half_rn(x - __half2float(h));
}
__device__ __forceinline__ void ldmx4(uint32_t r[4], uint32_t addr) {
    asm volatile("ldmatrix.sync.aligned.m8n8.x4.shared.b16 {%0,%1,%2,%3}, [%4];"
                 : "=r"(r[0]), "=r"(r[1]), "=r"(r[2]), "=r"(r[3]) : "r"(addr));
}
__device__ __forceinline__ void ldmx4_t(uint32_t r[4], uint32_t addr) {
    asm volatile("ldmatrix.sync.aligned.m8n8.x4.trans.shared.b16 {%0,%1,%2,%3}, [%4];"
                 : "=r"(r[0]), "=r"(r[1]), "=r"(r[2]), "=r"(r[3]) : "r"(addr));
}
__device__ __forceinline__ void mma_f16(float d[4], const uint32_t a[4],
                                        const uint32_t b0, const uint32_t b1) {
    asm volatile(
        "mma.sync.aligned.m16n8k16.row.col.f32.f16.f16.f32 "
        "{%0,%1,%2,%3}, {%4,%5,%6,%7}, {%8,%9}, {%0,%1,%2,%3};"
        : "+f"(d[0]), "+f"(d[1]), "+f"(d[2]), "+f"(d[3])
        : "r"(a[0]), "r"(a[1]), "r"(a[2]), "r"(a[3]), "r"(b0), "r"(b1));
}
__device__ __forceinline__ void split2_pack(float a, float b, uint32_t& hp, uint32_t& lp) {
    __half ha = __float2half_rn(a), hb = __float2half_rn(b);
    union { __half h[2]; uint32_t u; } H, L;
    H.h[0] = ha; H.h[1] = hb;
    L.h[0] = __float2half_rn(a - __half2float(ha));
    L.h[1] = __float2half_rn(b - __half2float(hb));
    hp = H.u; lp = L.u;
}
// cp.async helpers
__device__ __forceinline__ void cp_async16(uint32_t saddr, const void* g) {
    asm volatile("cp.async.cg.shared.global [%0], [%1], 16;"
                 :: "r"(saddr), "l"(g));
}
__device__ __forceinline__ void cp_async16p(uint32_t saddr, const void* g, bool v) {
    int sz = v ? 16 : 0;
    asm volatile("cp.async.cg.shared.global [%0], [%1], 16, %2;"
                 :: "r"(saddr), "l"(g), "r"(sz));
}
__device__ __forceinline__ void cp_commit() {
    asm volatile("cp.async.commit_group;" ::: "memory");
}
__device__ __forceinline__ void cp_wait0() {
    asm volatile("cp.async.wait_group 0;" ::: "memory");
}
__device__ __forceinline__ void cp_wait1() {
    asm volatile("cp.async.wait_group 1;" ::: "memory");
}

// ================= operand split prep (fp32 -> fp16 hi/lo) =================
__global__ void __launch_bounds__(256) split_kernel(
    const float* __restrict__ qv, const float* __restrict__ mw,
    const float* __restrict__ vw, const float* __restrict__ sw,
    const float* __restrict__ qw, const float* __restrict__ Wv,
    const float* __restrict__ W2)
{
    const float* src; __half *dh, *dl; int n;
    switch (blockIdx.z) {
        case 0: src = qv; dh = g_qvh; dl = g_qvl; n = 614400;  break;
        case 1: src = mw; dh = g_mwh; dl = g_mwl; n = 4194304; break;
        case 2: src = vw; dh = g_vwh; dl = g_vwl; n = 4194304; break;
        case 3: src = sw; dh = g_swh; dl = g_swl; n = 1048576; break;
        case 4: src = qw; dh = g_qwh; dl = g_qwl; n = 1048576; break;
        case 5: src = Wv; dh = g_Wvh; dl = g_Wvl; n = 2097152; break;
        default:src = W2; dh = g_W2h; dl = g_W2l; n = 2097152; break;
    }
    int i = (blockIdx.x * 256 + threadIdx.x) * 4;
    if (i >= n) return;
    float4 v = *(const float4*)(src + i);
    union U { __half b[4]; uint2 u; } H, L;
    split_h(v.x, H.b[0], L.b[0]);
    split_h(v.y, H.b[1], L.b[1]);
    split_h(v.z, H.b[2], L.b[2]);
    split_h(v.w, H.b[3], L.b[3]);
    *(uint2*)(dh + i) = H.u;
    *(uint2*)(dl + i) = L.u;
}

// ====== shared GEMM core: fp16x2 (2-pass), cp.async 3-stage pipeline =======
static constexpr int RS = 40;                       // smem row stride (fp16)
static constexpr int BUF = 128 * RS * 2;            // one operand buffer, bytes
static constexpr int STAGE_BYTES = 3 * BUF;         // Ah|Al|Bh = 30720 B
static constexpr int NSTAGE = 3;
static constexpr int GEMM_SMEM = NSTAGE * STAGE_BYTES;  // 92160 B

__device__ __forceinline__ void gemm_core(
    float acc[2][8][4],
    const __half* __restrict__ Ah, const __half* __restrict__ Al,
    const __half* __restrict__ Wh,
    char* sm, int m0, int n0, int M, int lda, int kBegin, int NC)
{
    const int tid = threadIdx.x, wid = tid >> 5, lane = tid & 31;
    const int wm = (wid & 3) * 32;
    const int wn = (wid >> 2) * 64;
    const int lrow = tid >> 2;
    const int lseg = (tid & 3) * 8;
    const uint32_t smb = smem_u32(sm);

    const int arow = lane & 15, acol = (lane >> 4) * 8;
    const int bgrp = lane >> 3, brow = lane & 7;
    const int bn_off = (bgrp >> 1) * 8 + brow;
    const int bk_off = (bgrp & 1) * 8;

#pragma unroll
    for (int i = 0; i < 2; i++)
#pragma unroll
        for (int j = 0; j < 8; j++)
#pragma unroll
            for (int q = 0; q < 4; q++) acc[i][j][q] = 0.f;

    auto issue = [&](int c, int s) {
        const int kk = kBegin + c * 32;
        const uint32_t sb = smb + s * STAGE_BYTES;
#pragma unroll
        for (int j = 0; j < 2; j++) {
            int row = lrow + 64 * j;
            int gm = m0 + row;
            bool va = (gm < M);
            int gmc = va ? gm : (M - 1);
            uint32_t off = (uint32_t)(row * RS + lseg) * 2;
            cp_async16p(sb + off,       Ah + (size_t)gmc * lda + kk + lseg, va);
            cp_async16p(sb + BUF + off, Al + (size_t)gmc * lda + kk + lseg, va);
            cp_async16(sb + 2 * BUF + off, Wh + (size_t)(n0 + row) * lda + kk + lseg);
        }
    };

    issue(0, 0); cp_commit();
    if (NC > 1) { issue(1, 1); cp_commit(); }

    for (int c = 0; c < NC; c++) {
        if (c + 1 < NC) cp_wait1(); else cp_wait0();
        __syncthreads();
        if (c + 2 < NC) { issue(c + 2, (c + 2) % 3); cp_commit(); }

        const uint32_t uAh = smb + (c % 3) * STAGE_BYTES;
        const uint32_t uAl = uAh + BUF;
        const uint32_t uBh = uAh + 2 * BUF;
#pragma unroll
        for (int ksp = 0; ksp < 2; ksp++) {
            uint32_t fAh[2][4], fAl[2][4], fBh[4][4];
#pragma unroll
            for (int mi = 0; mi < 2; mi++) {
                uint32_t off = 2u * ((wm + mi * 16 + arow) * RS + ksp * 16 + acol);
                ldmx4(fAh[mi], uAh + off);
                ldmx4(fAl[mi], uAl + off);
            }
#pragma unroll
            for (int nb = 0; nb < 4; nb++) {
                uint32_t off = 2u * ((wn + nb * 16 + bn_off) * RS + ksp * 16 + bk_off);
                ldmx4(fBh[nb], uBh + off);
            }
#pragma unroll
            for (int mi = 0; mi < 2; mi++)
#pragma unroll
                for (int nf = 0; nf < 8; nf++) {
                    const uint32_t* bh = &fBh[nf >> 1][(nf & 1) * 2];
                    mma_f16(acc[mi][nf], fAh[mi], bh[0], bh[1]);
                    mma_f16(acc[mi][nf], fAl[mi], bh[0], bh[1]);
                }
        }
        // buffer (c%3) is re-written only at iter c+1's issue, after its sync
    }
}

// ====== merged generator GEMM (M/V/S/Q), m-fastest raster, fp16 out ========
__global__ void __launch_bounds__(256, 2) gen_gemm(
    const float* __restrict__ mb, const float* __restrict__ vb,
    const float* __restrict__ sb, const float* __restrict__ qb)
{
    extern __shared__ char sm[];

    const __half* Wh; const float* bias;
    __half *Ch, *Cl; int Nout, nt;
    switch (blockIdx.z) {
        case 0: Wh = g_mwh; bias = mb; Ch = g_Mh; Cl = g_Ml; Nout = 16384; nt = 128; break;
        case 1: Wh = g_vwh; bias = vb; Ch = g_Vh; Cl = g_Vl; Nout = 16384; nt = 128; break;
        case 2: Wh = g_swh; bias = sb; Ch = g_Sh; Cl = g_Sl; Nout = 4096;  nt = 32;  break;
        default:Wh = g_qwh; bias = qb; Ch = g_Qh; Cl = g_Ql; Nout = 4096;  nt = 32;  break;
    }
    if ((int)blockIdx.y >= nt) return;

    const int m0 = blockIdx.x * 128;
    const int n0 = blockIdx.y * 128;

    float acc[2][8][4];
    gemm_core(acc, g_qvh, g_qvl, Wh, sm, m0, n0, 2400, 256, 0, 8);

    const int lane = threadIdx.x & 31, wid = threadIdx.x >> 5;
    const int wm = (wid & 3) * 32, wn = (wid >> 2) * 64;
    const int erow = lane >> 2, ecol = (lane & 3) * 2;
#pragma unroll
    for (int mi = 0; mi < 2; mi++) {
        int r0 = m0 + wm + mi * 16 + erow;
#pragma unroll
        for (int half = 0; half < 2; half++) {
            int r = r0 + half * 8;
            if (r >= 2400) continue;
#pragma unroll
            for (int nf = 0; nf < 8; nf++) {
                int col = n0 + wn + nf * 8 + ecol;
                float x0 = acc[mi][nf][half * 2 + 0] + __ldg(bias + col);
                float x1 = acc[mi][nf][half * 2 + 1] + __ldg(bias + col + 1);
                uint32_t hp, lp;
                split2_pack(x0, x1, hp, lp);
                size_t o = (size_t)r * Nout + col;
                *(uint32_t*)(Ch + o) = hp;
                *(uint32_t*)(Cl + o) = lp;
            }
        }
    }
}

// ============ output-projection GEMM (split-K, fp32 out) ===================
__global__ void __launch_bounds__(256, 2) hmma_gemm(
    const __half* __restrict__ Ah0, const __half* __restrict__ Al0,
    const __half* __restrict__ Wh0,
    const float* __restrict__ b0, float* __restrict__ C0,
    const __half* __restrict__ Ah1, const __half* __restrict__ Al1,
    const __half* __restrict__ Wh1,
    const float* __restrict__ b1, float* __restrict__ C1,
    int M, int Nout, int lda, int kPerCta, int splitk, size_t sliceStride)
{
    extern __shared__ char sm[];

    const int z  = blockIdx.z / splitk;
    const int ks = blockIdx.z % splitk;
    const __half* Ah = z ? Ah1 : Ah0;
    const __half* Al = z ? Al1 : Al0;
    const __half* Wh = z ? Wh1 : Wh0;
    const float* bias = z ? b1 : b0;
    float* Cp = (z ? C1 : C0) + (size_t)ks * sliceStride;

    const int m0 = blockIdx.y * 128;
    const int n0 = blockIdx.x * 128;

    float acc[2][8][4];
    gemm_core(acc, Ah, Al, Wh, sm, m0, n0, M, lda, ks * kPerCta, kPerCta / 32);

    const bool addB = (ks == 0);
    const int lane = threadIdx.x & 31, wid = threadIdx.x >> 5;
    const int wm = (wid & 3) * 32, wn = (wid >> 2) * 64;
    const int erow = lane >> 2, ecol = (lane & 3) * 2;
#pragma unroll
    for (int mi = 0; mi < 2; mi++) {
        int r0 = m0 + wm + mi * 16 + erow;
#pragma unroll
        for (int half = 0; half < 2; half++) {
            int r = r0 + half * 8;
            if (r >= M) continue;
#pragma unroll
            for (int nf = 0; nf < 8; nf++) {
                int col = n0 + wn + nf * 8 + ecol;
                float x0 = acc[mi][nf][half * 2 + 0];
                float x1 = acc[mi][nf][half * 2 + 1];
                if (addB) { x0 += __ldg(bias + col); x1 += __ldg(bias + col + 1); }
                *(float2*)(Cp + (size_t)r * Nout + col) = make_float2(x0, x1);
            }
        }
    }
}

// ========= fused per-(bn,g) kernel (full HMMA fp16x3, 32 KB smem) ==========
static constexpr int STW = 72;
static constexpr int STN = 40;

__device__ __forceinline__ void ln2048_relu(float acc[4][4], float* red) {
    float s = 0.f, q = 0.f;
#pragma unroll
    for (int i = 0; i < 4; i++)
#pragma unroll
        for (int j = 0; j < 4; j++) { s += acc[i][j]; q += acc[i][j] * acc[i][j]; }
#pragma unroll
    for (int o = 16; o > 0; o >>= 1) {
        s += __shfl_xor_sync(0xffffffffu, s, o);
        q += __shfl_xor_sync(0xffffffffu, q, o);
    }
    int w = threadIdx.x >> 5;
    __syncthreads();
    if ((threadIdx.x & 31) == 0) { red[w] = s; red[4 + w] = q; }
    __syncthreads();
    s = red[0] + red[1] + red[2] + red[3];
    q = red[4] + red[5] + red[6] + red[7];
    float mean = s * (1.f / 2048.f);
    float var  = q * (1.f / 2048.f) - mean * mean;
    float inv  = rsqrtf(var + 1e-5f);
#pragma unroll
    for (int i = 0; i < 4; i++)
#pragma unroll
        for (int j = 0; j < 4; j++)
            acc[i][j] = fmaxf((acc[i][j] - mean) * inv, 0.f);
}

struct ALoadS {
    uint32_t addrH, addrL;
    __device__ __forceinline__ void load(int kt, uint32_t aH[4], uint32_t aL[4]) const {
        ldmx4(aH, addrH + kt * 32);
        ldmx4(aL, addrL + kt * 32);
    }
};
struct ALoadGB {
    const __half *H, *L; int ld, r0, k0;
    __device__ __forceinline__ void load(int kt, uint32_t aH[4], uint32_t aL[4]) const {
        int k = kt * 16 + k0;
        aH[0] = *(const uint32_t*)(H + r0 * ld + k);
        aH[1] = *(const uint32_t*)(H + (r0 + 8) * ld + k);
        aH[2] = *(const uint32_t*)(H + r0 * ld + k + 8);
        aH[3] = *(const uint32_t*)(H + (r0 + 8) * ld + k + 8);
        aL[0] = *(const uint32_t*)(L + r0 * ld + k);
        aL[1] = *(const uint32_t*)(L + (r0 + 8) * ld + k);
        aL[2] = *(const uint32_t*)(L + r0 * ld + k + 8);
        aL[3] = *(const uint32_t*)(L + (r0 + 8) * ld + k + 8);
    }
};
struct ALoadGF {
    const float* A; int ld, r0, k0;
    __device__ __forceinline__ void load(int kt, uint32_t aH[4], uint32_t aL[4]) const {
        int k = kt * 16 + k0;
        float2 v0 = *(const float2*)(A + r0 * ld + k);
        float2 v1 = *(const float2*)(A + (r0 + 8) * ld + k);
        float2 v2 = *(const float2*)(A + r0 * ld + k + 8);
        float2 v3 = *(const float2*)(A + (r0 + 8) * ld + k + 8);
        split2_pack(v0.x, v0.y, aH[0], aL[0]);
        split2_pack(v1.x, v1.y, aH[1], aL[1]);
        split2_pack(v2.x, v2.y, aH[2], aL[2]);
        split2_pack(v3.x, v3.y, aH[3], aL[3]);
    }
};

template<class AL, int NB, int KT, bool TRANS, int SB>
__device__ __forceinline__ void mm_frag2(float acc[NB][4], const AL& al,
    const __half* BH, const __half* BL, int wn, int lane)
{
    const int b1 = ((lane >> 4) << 3) + (lane & 7);
    const int b2 = ((lane >> 3) & 1) * 8;
#pragma unroll
    for (int i = 0; i < NB; i++)
#pragma unroll
        for (int j = 0; j < 4; j++) acc[i][j] = 0.f;
#pragma unroll
    for (int kt = 0; kt < KT; kt++) {
        uint32_t aH[4], aL[4];
        al.load(kt, aH, aL);
#pragma unroll
        for (int nt = 0; nt < NB / 2; nt++) {
            uint32_t bH[4], bL[4];
            if (TRANS) {
                ldmx4_t(bH, smem_u32(BH + (kt * 16 + b1) * SB + wn + nt * 16 + b2));
                ldmx4_t(bL, smem_u32(BL + (kt * 16 + b1) * SB + wn + nt * 16 + b2));
            } else {
                ldmx4(bH, smem_u32(BH + (wn + nt * 16 + b1) * SB + kt * 16 + b2));
                ldmx4(bL, smem_u32(BL + (wn + nt * 16 + b1) * SB + kt * 16 + b2));
            }
#pragma unroll
            for (int h = 0; h < 2; h++) {
                int nb = nt * 2 + h;
                uint32_t h0, h1, l0, l1;
                if (TRANS) { h0 = bH[h]; h1 = bH[h + 2]; l0 = bL[h]; l1 = bL[h + 2]; }
                else       { h0 = bH[2 * h]; h1 = bH[2 * h + 1];
                             l0 = bL[2 * h]; l1 = bL[2 * h + 1]; }
                mma_f16(acc[nb], aH, h0, h1);
                mma_f16(acc[nb], aL, h0, h1);
                mma_f16(acc[nb], aH, l0, l1);
            }
        }
    }
}

template<int W, int ST>
__device__ __forceinline__ void load_h_smem(const __half* __restrict__ srcH,
                                            const __half* __restrict__ srcL,
                                            int n, __half* dh, __half* dl, int tid)
{
#pragma unroll
    for (int idx = tid * 8; idx < n; idx += 1024) {
        int row = idx / W, col = idx % W;
        *(uint4*)(dh + row * ST + col) = *(const uint4*)(srcH + idx);
        *(uint4*)(dl + row * ST + col) = *(const uint4*)(srcL + idx);
    }
}

__global__ void __launch_bounds__(128, 6) fused_bg(
    const float* __restrict__ feats,
    const float* __restrict__ kw_g, const float* __restrict__ kb_g)
{
    __shared__ __align__(16) __half wS[2 * 64 * STW];
    __shared__ __align__(16) __half xS[2 * 32 * STW];
    __shared__ __align__(16) __half sS[2 * 32 * STN];
    __shared__ float red[8];

    __half *wH = wS, *wL = wS + 64 * STW;
    __half *xH = xS, *xL = xS + 32 * STW;
    __half *sH = sS, *sL = sS + 32 * STN;
    float* sc = (float*)wS;

    const int bn = blockIdx.x, g = blockIdx.y;
    const int tid = threadIdx.x;
    const int lane = tid & 31, wrp = tid >> 5;
    const int rw   = (wrp & 1) * 16;
    const int wn32 = (wrp >> 1) * 32;
    const int wn16 = (wrp >> 1) * 16;
    const int lr = lane >> 2, lc = 2 * (lane & 3);
    const int fr0 = rw + lr, fk0 = lc;
    const size_t bg = (size_t)bn * 4 + g;

    load_h_smem<64, STW>(g_Mh + bg * 4096, g_Ml + bg * 4096, 4096, wH, wL, tid);
    __syncthreads();

    float acc[4][4];
    const ALoadGF af{feats + bg * 2048, 64, fr0, fk0};

    // stage 1: fM = relu(ln2d(f @ M)) -> x
    mm_frag2<ALoadGF, 4, 4, true, STW>(acc, af, wH, wL, wn32, lane);
    ln2048_relu(acc, red);
    load_h_smem<64, STW>(g_Vh + bg * 4096, g_Vl + bg * 4096, 4096, wH, wL, tid);
#pragma unroll
    for (int nb = 0; nb < 4; nb++) {
        int c = wn32 + nb * 8 + lc;
        uint32_t hp, lp;
        split2_pack(acc[nb][0], acc[nb][1], hp, lp);
        *(uint32_t*)(xH + fr0 * STW + c) = hp;
        *(uint32_t*)(xL + fr0 * STW + c) = lp;
        split2_pack(acc[nb][2], acc[nb][3], hp, lp);
        *(uint32_t*)(xH + (fr0 + 8) * STW + c) = hp;
        *(uint32_t*)(xL + (fr0 + 8) * STW + c) = lp;
    }
    __syncthreads();

    // stage 2: fMS = relu(ln2d(S @ fM)) -> global
    {
        const ALoadGB as{g_Sh + bg * 1024, g_Sl + bg * 1024, 32, fr0, fk0};
        mm_frag2<ALoadGB, 4, 2, true, STW>(acc, as, xH, xL, wn32, lane);
    }
    ln2048_relu(acc, red);
#pragma unroll
    for (int nb = 0; nb < 4; nb++) {
        int c = wn32 + nb * 8 + lc;
        size_t o0 = bg * 2048 + (size_t)fr0 * 64 + c;
        size_t o1 = o0 + 8 * 64;
        uint32_t hp, lp;
        split2_pack(acc[nb][0], acc[nb][1], hp, lp);
        *(uint32_t*)(g_FMSh + o0) = hp;
        *(uint32_t*)(g_FMSl + o0) = lp;
        split2_pack(acc[nb][2], acc[nb][3], hp, lp);
        *(uint32_t*)(g_FMSh + o1) = hp;
        *(uint32_t*)(g_FMSl + o1) = lp;
    }
    __syncthreads();

    // stage 3: v = relu(ln2d(f @ Vw)) -> x
    mm_frag2<ALoadGF, 4, 4, true, STW>(acc, af, wH, wL, wn32, lane);
    ln2048_relu(acc, red);
#pragma unroll
    for (int nb = 0; nb < 4; nb++) {
        int c = wn32 + nb * 8 + lc;
        uint32_t hp, lp;
        split2_pack(acc[nb][0], acc[nb][1], hp, lp);
        *(uint32_t*)(xH + fr0 * STW + c) = hp;
        *(uint32_t*)(xL + fr0 * STW + c) = lp;
        split2_pack(acc[nb][2], acc[nb][3], hp, lp);
        *(uint32_t*)(xH + (fr0 + 8) * STW + c) = hp;
        *(uint32_t*)(xL + (fr0 + 8) * STW + c) = lp;
    }
    __syncthreads();

    float a2[2][4];

    // stage 4: k[i][p] = kw @ v^T + kb -> s region
    {
        const ALoadGF akw{kw_g + g * 2048, 64, fr0, fk0};
        mm_frag2<ALoadGF, 2, 4, false, STW>(a2, akw, xH, xL, wn16, lane);
        float b0 = __ldg(kb_g + g * 32 + fr0);
        float b1 = __ldg(kb_g + g * 32 + fr0 + 8);
#pragma unroll
        for (int nb = 0; nb < 2; nb++) {
            int c = wn16 + nb * 8 + lc;
            uint32_t hp, lp;
            split2_pack(a2[nb][0] + b0, a2[nb][1] + b0, hp, lp);
            *(uint32_t*)(sH + fr0 * STN + c) = hp;
            *(uint32_t*)(sL + fr0 * STN + c) = lp;
            split2_pack(a2[nb][2] + b1, a2[nb][3] + b1, hp, lp);
            *(uint32_t*)(sH + (fr0 + 8) * STN + c) = hp;
            *(uint32_t*)(sL + (fr0 + 8) * STN + c) = lp;
        }
    }
    __syncthreads();

    // stage 5: scores = q @ k -> sc
    {
        const ALoadGB aq{g_Qh + bg * 1024, g_Ql + bg * 1024, 32, fr0, fk0};
        mm_frag2<ALoadGB, 2, 2, true, STN>(a2, aq, sH, sL, wn16, lane);
#pragma unroll
        for (int nb = 0; nb < 2; nb++) {
            int c = wn16 + nb * 8 + lc;
            *(float2*)(sc + fr0 * 36 + c)       = make_float2(a2[nb][0], a2[nb][1]);
            *(float2*)(sc + (fr0 + 8) * 36 + c) = make_float2(a2[nb][2], a2[nb][3]);
        }
    }
    __syncthreads();

    // stage 6: softmax
    {
        const int tx8 = tid & 7, ty16 = tid >> 3;
#pragma unroll
        for (int i = 0; i < 2; i++) {
            int row = 2 * ty16 + i;
            float v[4];
#pragma unroll
            for (int j = 0; j < 4; j++) v[j] = sc[row * 36 + 4 * tx8 + j];
            float m = fmaxf(fmaxf(v[0], v[1]), fmaxf(v[2], v[3]));
#pragma unroll
            for (int o = 4; o > 0; o >>= 1)
                m = fmaxf(m, __shfl_xor_sync(0xffffffffu, m, o));
            float s = 0.f;
#pragma unroll
            for (int j = 0; j < 4; j++) { v[j] = __expf((v[j] - m) * 0.125f); s += v[j]; }
#pragma unroll
            for (int o = 4; o > 0; o >>= 1)
                s += __shfl_xor_sync(0xffffffffu, s, o);
            float inv = __frcp_rn(s);
#pragma unroll
            for (int j = 0; j < 4; j++) {
                float p = v[j] * inv;
                __half h, l;
                split_h(p, h, l);
                sH[row * STN + 4 * tx8 + j] = h;
                sL[row * STN + 4 * tx8 + j] = l;
            }
        }
    }
    __syncthreads();

    // stage 7: fc = relu(ln2d(att @ v)) -> global
    {
        const ALoadS aatt{
            smem_u32(sH + (rw + (lane & 15)) * STN + (lane >> 4) * 8),
            smem_u32(sL + (rw + (lane & 15)) * STN + (lane >> 4) * 8)};
        mm_frag2<ALoadS, 4, 2, true, STW>(acc, aatt, xH, xL, wn32, lane);
    }
    ln2048_relu(acc, red);
#pragma unroll
    for (int nb = 0; nb < 4; nb++) {
        int c = wn32 + nb * 8 + lc;
        size_t o0 = bg * 2048 + (size_t)fr0 * 64 + c;
        size_t o1 = o0 + 8 * 64;
        uint32_t hp, lp;
        split2_pack(acc[nb][0], acc[nb][1], hp, lp);
        *(uint32_t*)(g_FCh + o0) = hp;
        *(uint32_t*)(g_FCl + o0) = lp;
        split2_pack(acc[nb][2], acc[nb][3], hp, lp);
        *(uint32_t*)(g_FCh + o1) = hp;
        *(uint32_t*)(g_FCl + o1) = lp;
    }
}

// ============== residual + split-K reduce + affine LayerNorm ===============
__global__ void __launch_bounds__(256) final_ln(
    const float* __restrict__ qv,
    const float* __restrict__ wA, const float* __restrict__ bA,
    const float* __restrict__ wB, const float* __restrict__ bB,
    float* __restrict__ out)
{
    const int r = blockIdx.x, z = blockIdx.y, c = threadIdx.x;
    const float* w = z ? wB : wA;
    const float* b = z ? bB : bA;
    float x = qv[(size_t)r * 256 + c];
#pragma unroll
    for (int k = 0; k < 4; k++)
        x += g_P[(size_t)(z * 4 + k) * 614400 + (size_t)r * 256 + c];

    __shared__ float sred[16];
    float s = x, q = x * x;
#pragma unroll
    for (int o = 16; o > 0; o >>= 1) {
        s += __shfl_xor_sync(0xffffffffu, s, o);
        q += __shfl_xor_sync(0xffffffffu, q, o);
    }
    int wp = threadIdx.x >> 5;
    if ((threadIdx.x & 31) == 0) { sred[wp] = s; sred[8 + wp] = q; }
    __syncthreads();
    float S = 0.f, Q2 = 0.f;
#pragma unroll
    for (int i = 0; i < 8; i++) { S += sred[i]; Q2 += sred[8 + i]; }
    float mean = S * (1.f / 256.f);
    float var  = Q2 * (1.f / 256.f) - mean * mean;
    float inv  = rsqrtf(var + 1e-5f);
    out[(size_t)z * 614400 + (size_t)r * 256 + c] = (x - mean) * inv * w[c] + b[c];
}

// ================================ launcher =================================
extern "C" void kernel_launch(void* const* d_in, const int* in_sizes, int n_in,
                              void* d_out, int out_size)
{
    const float* feats = (const float*)d_in[0];
    const float* qv    = (const float*)d_in[1];
    const float* m_w   = (const float*)d_in[7];
    const float* m_b   = (const float*)d_in[8];
    const float* s_w   = (const float*)d_in[9];
    const float* s_b   = (const float*)d_in[10];
    const float* q_w   = (const float*)d_in[11];
    const float* q_b   = (const float*)d_in[12];
    const float* v_w   = (const float*)d_in[13];
    const float* v_b   = (const float*)d_in[14];
    const float* k_w   = (const float*)d_in[15];
    const float* k_b   = (const float*)d_in[16];
    const float* Wv_w  = (const float*)d_in[17];
    const float* Wv_b  = (const float*)d_in[18];
    const float* Wv2_w = (const float*)d_in[19];
    const float* Wv2_b = (const float*)d_in[20];
    const float* lnA_w = (const float*)d_in[21];
    const float* lnA_b = (const float*)d_in[22];
    const float* lnB_w = (const float*)d_in[23];
    const float* lnB_b = (const float*)d_in[24];
    float* out = (float*)d_out;

    float* gP;
    cudaGetSymbolAddress((void**)&gP, g_P);
    __half *Wvh, *W2h, *FMSh, *FMSl, *FCh, *FCl;
    cudaGetSymbolAddress((void**)&Wvh, g_Wvh);
    cudaGetSymbolAddress((void**)&W2h, g_W2h);
    cudaGetSymbolAddress((void**)&FMSh, g_FMSh); cudaGetSymbolAddress((void**)&FMSl, g_FMSl);
    cudaGetSymbolAddress((void**)&FCh, g_FCh);   cudaGetSymbolAddress((void**)&FCl, g_FCl);

    cudaFuncSetAttribute(gen_gemm, cudaFuncAttributeMaxDynamicSharedMemorySize, GEMM_SMEM);
    cudaFuncSetAttribute(hmma_gemm, cudaFuncAttributeMaxDynamicSharedMemorySize, GEMM_SMEM);

    // 0) split fp32 operands into fp16 hi/lo
    split_kernel<<<dim3(4096, 1, 7), 256>>>(qv, m_w, v_w, s_w, q_w, Wv_w, Wv2_w);

    // 1) merged M/V/S/Q generators (fp16x2, 3-stage cp.async pipeline)
    gen_gemm<<<dim3(19, 128, 4), 256, GEMM_SMEM>>>(m_b, v_b, s_b, q_b);

    // 2) fused per-(bn,g) dynamic conv + attention (fp16x3)
    fused_bg<<<dim3(2400, 4), 128>>>(feats, k_w, k_b);

    // 3) output projections: (2400x8192) @ (256x8192)^T, split-K=4, fp16x2
    hmma_gemm<<<dim3(2, 19, 8), 256, GEMM_SMEM>>>(
        FMSh, FMSl, Wvh, Wv_b, gP,
        FCh,  FCl,  W2h, Wv2_b, gP + 4 * 614400,
        2400, 256, 8192, 2048, 4, 614400);

    // 4) residual + split-K reduce + affine LayerNorm
    final_ln<<<dim3(2400, 2), 256>>>(qv, lnA_w, lnA_b, lnB_w, lnB_b, out);
}

// round 14
// speedup vs baseline: 3.4842x; 1.1364x over previous
#include <cuda_runtime.h>
#include <cuda_fp16.h>
#include <cstdint>

// ============================ problem constants ============================
// B=8, N=300 -> BN=2400; G=4; P=O=32; CG=DG=64; IN_DIM=OUT_DIM=256; TEMPER=8

// ===================== scratch (__device__ globals) ========================
__device__ float g_P[9830400];    // split-K slices of (2400,256)

__device__ __half g_Mh[39321600];                 // hi only (B operand)
__device__ __half g_Vh[39321600];
__device__ __half g_Sh[9830400],  g_Sl[9830400];  // A operand: hi+lo
__device__ __half g_Qh[9830400],  g_Ql[9830400];

__device__ __half g_qvh[614400],  g_qvl[614400];  // A operand: hi+lo
__device__ __half g_mwh[4194304];                 // B operands: hi only
__device__ __half g_vwh[4194304];
__device__ __half g_swh[1048576];
__device__ __half g_qwh[1048576];
__device__ __half g_Wvh[2097152];
__device__ __half g_W2h[2097152];
__device__ __half g_FMSh[19660800], g_FMSl[19660800];  // A operand: hi+lo
__device__ __half g_FCh[19660800],  g_FCl[19660800];

// ============================ small helpers ================================
__device__ __forceinline__ uint32_t smem_u32(const void* p) {
    uint32_t a;
    asm("{ .reg .u64 t; cvta.to.shared.u64 t, %1; cvt.u32.u64 %0, t; }"
        : "=r"(a) : "l"(p));
    return a;
}
__device__ __forceinline__ void split_h(float x, __half& h, __half& l) {
    h = __float2half_rn(x);
    l = __float2half_rn(x - __half2float(h));
}
__device__ __forceinline__ void ldmx4(uint32_t r[4], uint32_t addr) {
    asm volatile("ldmatrix.sync.aligned.m8n8.x4.shared.b16 {%0,%1,%2,%3}, [%4];"
                 : "=r"(r[0]), "=r"(r[1]), "=r"(r[2]), "=r"(r[3]) : "r"(addr));
}
__device__ __forceinline__ void ldmx4_t(uint32_t r[4], uint32_t addr) {
    asm volatile("ldmatrix.sync.aligned.m8n8.x4.trans.shared.b16 {%0,%1,%2,%3}, [%4];"
                 : "=r"(r[0]), "=r"(r[1]), "=r"(r[2]), "=r"(r[3]) : "r"(addr));
}
__device__ __forceinline__ void mma_f16(float d[4], const uint32_t a[4],
                                        const uint32_t b0, const uint32_t b1) {
    asm volatile(
        "mma.sync.aligned.m16n8k16.row.col.f32.f16.f16.f32 "
        "{%0,%1,%2,%3}, {%4,%5,%6,%7}, {%8,%9}, {%0,%1,%2,%3};"
        : "+f"(d[0]), "+f"(d[1]), "+f"(d[2]), "+f"(d[3])
        : "r"(a[0]), "r"(a[1]), "r"(a[2]), "r"(a[3]), "r"(b0), "r"(b1));
}
__device__ __forceinline__ void split2_pack(float a, float b, uint32_t& hp, uint32_t& lp) {
    __half ha = __float2half_rn(a), hb = __float2half_rn(b);
    union { __half h[2]; uint32_t u; } H, L;
    H.h[0] = ha; H.h[1] = hb;
    L.h[0] = __float2half_rn(a - __half2float(ha));
    L.h[1] = __float2half_rn(b - __half2float(hb));
    hp = H.u; lp = L.u;
}
__device__ __forceinline__ uint32_t pack2h(float a, float b) {
    union { __half h[2]; uint32_t u; } U;
    U.h[0] = __float2half_rn(a); U.h[1] = __float2half_rn(b);
    return U.u;
}
// cp.async helpers
__device__ __forceinline__ void cp_async16(uint32_t saddr, const void* g) {
    asm volatile("cp.async.cg.shared.global [%0], [%1], 16;"
                 :: "r"(saddr), "l"(g));
}
__device__ __forceinline__ void cp_async16p(uint32_t saddr, const void* g, bool v) {
    int sz = v ? 16 : 0;
    asm volatile("cp.async.cg.shared.global [%0], [%1], 16, %2;"
                 :: "r"(saddr), "l"(g), "r"(sz));
}
__device__ __forceinline__ void cp_commit() {
    asm volatile("cp.async.commit_group;" ::: "memory");
}
__device__ __forceinline__ void cp_wait0() {
    asm volatile("cp.async.wait_group 0;" ::: "memory");
}
__device__ __forceinline__ void cp_wait1() {
    asm volatile("cp.async.wait_group 1;" ::: "memory");
}

// ================= operand split prep (fp32 -> fp16) =======================
// z==0 (qv): hi+lo. z>=1 (weights, B operands): hi only.
__global__ void __launch_bounds__(256) split_kernel(
    const float* __restrict__ qv, const float* __restrict__ mw,
    const float* __restrict__ vw, const float* __restrict__ sw,
    const float* __restrict__ qw, const float* __restrict__ Wv,
    const float* __restrict__ W2)
{
    const float* src; __half *dh, *dl = nullptr; int n;
    switch (blockIdx.z) {
        case 0: src = qv; dh = g_qvh; dl = g_qvl; n = 614400;  break;
        case 1: src = mw; dh = g_mwh; n = 4194304; break;
        case 2: src = vw; dh = g_vwh; n = 4194304; break;
        case 3: src = sw; dh = g_swh; n = 1048576; break;
        case 4: src = qw; dh = g_qwh; n = 1048576; break;
        case 5: src = Wv; dh = g_Wvh; n = 2097152; break;
        default:src = W2; dh = g_W2h; n = 2097152; break;
    }
    int i = (blockIdx.x * 256 + threadIdx.x) * 4;
    if (i >= n) return;
    float4 v = *(const float4*)(src + i);
    union U { __half b[4]; uint2 u; } H, L;
    split_h(v.x, H.b[0], L.b[0]);
    split_h(v.y, H.b[1], L.b[1]);
    split_h(v.z, H.b[2], L.b[2]);
    split_h(v.w, H.b[3], L.b[3]);
    *(uint2*)(dh + i) = H.u;
    if (dl) *(uint2*)(dl + i) = L.u;
}

// ====== shared GEMM core: fp16x2 (2-pass), cp.async 3-stage pipeline =======
static constexpr int RS = 40;
static constexpr int BUF = 128 * RS * 2;
static constexpr int STAGE_BYTES = 3 * BUF;         // Ah|Al|Bh
static constexpr int GEMM_SMEM = 3 * STAGE_BYTES;   // 92160 B

__device__ __forceinline__ void gemm_core(
    float acc[2][8][4],
    const __half* __restrict__ Ah, const __half* __restrict__ Al,
    const __half* __restrict__ Wh,
    char* sm, int m0, int n0, int M, int lda, int kBegin, int NC)
{
    const int tid = threadIdx.x, wid = tid >> 5, lane = tid & 31;
    const int wm = (wid & 3) * 32;
    const int wn = (wid >> 2) * 64;
    const int lrow = tid >> 2;
    const int lseg = (tid & 3) * 8;
    const uint32_t smb = smem_u32(sm);

    const int arow = lane & 15, acol = (lane >> 4) * 8;
    const int bgrp = lane >> 3, brow = lane & 7;
    const int bn_off = (bgrp >> 1) * 8 + brow;
    const int bk_off = (bgrp & 1) * 8;

#pragma unroll
    for (int i = 0; i < 2; i++)
#pragma unroll
        for (int j = 0; j < 8; j++)
#pragma unroll
            for (int q = 0; q < 4; q++) acc[i][j][q] = 0.f;

    auto issue = [&](int c, int s) {
        const int kk = kBegin + c * 32;
        const uint32_t sb = smb + s * STAGE_BYTES;
#pragma unroll
        for (int j = 0; j < 2; j++) {
            int row = lrow + 64 * j;
            int gm = m0 + row;
            bool va = (gm < M);
            int gmc = va ? gm : (M - 1);
            uint32_t off = (uint32_t)(row * RS + lseg) * 2;
            cp_async16p(sb + off,       Ah + (size_t)gmc * lda + kk + lseg, va);
            cp_async16p(sb + BUF + off, Al + (size_t)gmc * lda + kk + lseg, va);
            cp_async16(sb + 2 * BUF + off, Wh + (size_t)(n0 + row) * lda + kk + lseg);
        }
    };

    issue(0, 0); cp_commit();
    if (NC > 1) { issue(1, 1); cp_commit(); }

    for (int c = 0; c < NC; c++) {
        if (c + 1 < NC) cp_wait1(); else cp_wait0();
        __syncthreads();
        if (c + 2 < NC) { issue(c + 2, (c + 2) % 3); cp_commit(); }

        const uint32_t uAh = smb + (c % 3) * STAGE_BYTES;
        const uint32_t uAl = uAh + BUF;
        const uint32_t uBh = uAh + 2 * BUF;
#pragma unroll
        for (int ksp = 0; ksp < 2; ksp++) {
            uint32_t fAh[2][4], fAl[2][4], fBh[4][4];
#pragma unroll
            for (int mi = 0; mi < 2; mi++) {
                uint32_t off = 2u * ((wm + mi * 16 + arow) * RS + ksp * 16 + acol);
                ldmx4(fAh[mi], uAh + off);
                ldmx4(fAl[mi], uAl + off);
            }
#pragma unroll
            for (int nb = 0; nb < 4; nb++) {
                uint32_t off = 2u * ((wn + nb * 16 + bn_off) * RS + ksp * 16 + bk_off);
                ldmx4(fBh[nb], uBh + off);
            }
#pragma unroll
            for (int mi = 0; mi < 2; mi++)
#pragma unroll
                for (int nf = 0; nf < 8; nf++) {
                    const uint32_t* bh = &fBh[nf >> 1][(nf & 1) * 2];
                    mma_f16(acc[mi][nf], fAh[mi], bh[0], bh[1]);
                    mma_f16(acc[mi][nf], fAl[mi], bh[0], bh[1]);
                }
        }
    }
}

// ====== merged generator GEMM (M/V/S/Q), m-fastest raster, fp16 out ========
__global__ void __launch_bounds__(256, 2) gen_gemm(
    const float* __restrict__ mb, const float* __restrict__ vb,
    const float* __restrict__ sb, const float* __restrict__ qb)
{
    extern __shared__ char sm[];

    const __half* Wh; const float* bias;
    __half *Ch, *Cl; int Nout, nt;
    switch (blockIdx.z) {
        case 0: Wh = g_mwh; bias = mb; Ch = g_Mh; Cl = nullptr; Nout = 16384; nt = 128; break;
        case 1: Wh = g_vwh; bias = vb; Ch = g_Vh; Cl = nullptr; Nout = 16384; nt = 128; break;
        case 2: Wh = g_swh; bias = sb; Ch = g_Sh; Cl = g_Sl;    Nout = 4096;  nt = 32;  break;
        default:Wh = g_qwh; bias = qb; Ch = g_Qh; Cl = g_Ql;    Nout = 4096;  nt = 32;  break;
    }
    if ((int)blockIdx.y >= nt) return;

    const int m0 = blockIdx.x * 128;
    const int n0 = blockIdx.y * 128;

    float acc[2][8][4];
    gemm_core(acc, g_qvh, g_qvl, Wh, sm, m0, n0, 2400, 256, 0, 8);

    const int lane = threadIdx.x & 31, wid = threadIdx.x >> 5;
    const int wm = (wid & 3) * 32, wn = (wid >> 2) * 64;
    const int erow = lane >> 2, ecol = (lane & 3) * 2;
    const bool wantLo = (Cl != nullptr);
#pragma unroll
    for (int mi = 0; mi < 2; mi++) {
        int r0 = m0 + wm + mi * 16 + erow;
#pragma unroll
        for (int half = 0; half < 2; half++) {
            int r = r0 + half * 8;
            if (r >= 2400) continue;
#pragma unroll
            for (int nf = 0; nf < 8; nf++) {
                int col = n0 + wn + nf * 8 + ecol;
                float x0 = acc[mi][nf][half * 2 + 0] + __ldg(bias + col);
                float x1 = acc[mi][nf][half * 2 + 1] + __ldg(bias + col + 1);
                size_t o = (size_t)r * Nout + col;
                if (wantLo) {
                    uint32_t hp, lp;
                    split2_pack(x0, x1, hp, lp);
                    *(uint32_t*)(Ch + o) = hp;
                    *(uint32_t*)(Cl + o) = lp;
                } else {
                    *(uint32_t*)(Ch + o) = pack2h(x0, x1);
                }
            }
        }
    }
}

// ============ output-projection GEMM (split-K, fp32 out) ===================
__global__ void __launch_bounds__(256, 2) hmma_gemm(
    const __half* __restrict__ Ah0, const __half* __restrict__ Al0,
    const __half* __restrict__ Wh0,
    const float* __restrict__ b0, float* __restrict__ C0,
    const __half* __restrict__ Ah1, const __half* __restrict__ Al1,
    const __half* __restrict__ Wh1,
    const float* __restrict__ b1, float* __restrict__ C1,
    int M, int Nout, int lda, int kPerCta, int splitk, size_t sliceStride)
{
    extern __shared__ char sm[];

    const int z  = blockIdx.z / splitk;
    const int ks = blockIdx.z % splitk;
    const __half* Ah = z ? Ah1 : Ah0;
    const __half* Al = z ? Al1 : Al0;
    const __half* Wh = z ? Wh1 : Wh0;
    const float* bias = z ? b1 : b0;
    float* Cp = (z ? C1 : C0) + (size_t)ks * sliceStride;

    const int m0 = blockIdx.y * 128;
    const int n0 = blockIdx.x * 128;

    float acc[2][8][4];
    gemm_core(acc, Ah, Al, Wh, sm, m0, n0, M, lda, ks * kPerCta, kPerCta / 32);

    const bool addB = (ks == 0);
    const int lane = threadIdx.x & 31, wid = threadIdx.x >> 5;
    const int wm = (wid & 3) * 32, wn = (wid >> 2) * 64;
    const int erow = lane >> 2, ecol = (lane & 3) * 2;
#pragma unroll
    for (int mi = 0; mi < 2; mi++) {
        int r0 = m0 + wm + mi * 16 + erow;
#pragma unroll
        for (int half = 0; half < 2; half++) {
            int r = r0 + half * 8;
            if (r >= M) continue;
#pragma unroll
            for (int nf = 0; nf < 8; nf++) {
                int col = n0 + wn + nf * 8 + ecol;
                float x0 = acc[mi][nf][half * 2 + 0];
                float x1 = acc[mi][nf][half * 2 + 1];
                if (addB) { x0 += __ldg(bias + col); x1 += __ldg(bias + col + 1); }
                *(float2*)(Cp + (size_t)r * Nout + col) = make_float2(x0, x1);
            }
        }
    }
}

// ========= fused per-(bn,g) kernel (HMMA, mixed 2/3-pass, ~24 KB smem) =====
static constexpr int STW = 72;
static constexpr int STN = 40;

__device__ __forceinline__ void ln2048_relu(float acc[4][4], float* red) {
    float s = 0.f, q = 0.f;
#pragma unroll
    for (int i = 0; i < 4; i++)
#pragma unroll
        for (int j = 0; j < 4; j++) { s += acc[i][j]; q += acc[i][j] * acc[i][j]; }
#pragma unroll
    for (int o = 16; o > 0; o >>= 1) {
        s += __shfl_xor_sync(0xffffffffu, s, o);
        q += __shfl_xor_sync(0xffffffffu, q, o);
    }
    int w = threadIdx.x >> 5;
    __syncthreads();
    if ((threadIdx.x & 31) == 0) { red[w] = s; red[4 + w] = q; }
    __syncthreads();
    s = red[0] + red[1] + red[2] + red[3];
    q = red[4] + red[5] + red[6] + red[7];
    float mean = s * (1.f / 2048.f);
    float var  = q * (1.f / 2048.f) - mean * mean;
    float inv  = rsqrtf(var + 1e-5f);
#pragma unroll
    for (int i = 0; i < 4; i++)
#pragma unroll
        for (int j = 0; j < 4; j++)
            acc[i][j] = fmaxf((acc[i][j] - mean) * inv, 0.f);
}

struct ALoadS {
    uint32_t addrH, addrL;
    __device__ __forceinline__ void load(int kt, uint32_t aH[4], uint32_t aL[4]) const {
        ldmx4(aH, addrH + kt * 32);
        ldmx4(aL, addrL + kt * 32);
    }
};
struct ALoadGB {
    const __half *H, *L; int ld, r0, k0;
    __device__ __forceinline__ void load(int kt, uint32_t aH[4], uint32_t aL[4]) const {
        int k = kt * 16 + k0;
        aH[0] = *(const uint32_t*)(H + r0 * ld + k);
        aH[1] = *(const uint32_t*)(H + (r0 + 8) * ld + k);
        aH[2] = *(const uint32_t*)(H + r0 * ld + k + 8);
        aH[3] = *(const uint32_t*)(H + (r0 + 8) * ld + k + 8);
        aL[0] = *(const uint32_t*)(L + r0 * ld + k);
        aL[1] = *(const uint32_t*)(L + (r0 + 8) * ld + k);
        aL[2] = *(const uint32_t*)(L + r0 * ld + k + 8);
        aL[3] = *(const uint32_t*)(L + (r0 + 8) * ld + k + 8);
    }
};
struct ALoadGF {
    const float* A; int ld, r0, k0;
    __device__ __forceinline__ void load(int kt, uint32_t aH[4], uint32_t aL[4]) const {
        int k = kt * 16 + k0;
        float2 v0 = *(const float2*)(A + r0 * ld + k);
        float2 v1 = *(const float2*)(A + (r0 + 8) * ld + k);
        float2 v2 = *(const float2*)(A + r0 * ld + k + 8);
        float2 v3 = *(const float2*)(A + (r0 + 8) * ld + k + 8);
        split2_pack(v0.x, v0.y, aH[0], aL[0]);
        split2_pack(v1.x, v1.y, aH[1], aL[1]);
        split2_pack(v2.x, v2.y, aH[2], aL[2]);
        split2_pack(v3.x, v3.y, aH[3], aL[3]);
    }
};

// 2-pass: B hi only
template<class AL, int NB, int KT, bool TRANS, int SB>
__device__ __forceinline__ void mm2p(float acc[NB][4], const AL& al,
    const __half* BH, int wn, int lane)
{
    const int b1 = ((lane >> 4) << 3) + (lane & 7);
    const int b2 = ((lane >> 3) & 1) * 8;
#pragma unroll
    for (int i = 0; i < NB; i++)
#pragma unroll
        for (int j = 0; j < 4; j++) acc[i][j] = 0.f;
#pragma unroll
    for (int kt = 0; kt < KT; kt++) {
        uint32_t aH[4], aL[4];
        al.load(kt, aH, aL);
#pragma unroll
        for (int nt = 0; nt < NB / 2; nt++) {
            uint32_t bH[4];
            if (TRANS) ldmx4_t(bH, smem_u32(BH + (kt * 16 + b1) * SB + wn + nt * 16 + b2));
            else       ldmx4(bH, smem_u32(BH + (wn + nt * 16 + b1) * SB + kt * 16 + b2));
#pragma unroll
            for (int h = 0; h < 2; h++) {
                int nb = nt * 2 + h;
                uint32_t h0, h1;
                if (TRANS) { h0 = bH[h]; h1 = bH[h + 2]; }
                else       { h0 = bH[2 * h]; h1 = bH[2 * h + 1]; }
                mma_f16(acc[nb], aH, h0, h1);
                mma_f16(acc[nb], aL, h0, h1);
            }
        }
    }
}

// 3-pass: B hi+lo
template<class AL, int NB, int KT, bool TRANS, int SB>
__device__ __forceinline__ void mm3p(float acc[NB][4], const AL& al,
    const __half* BH, const __half* BL, int wn, int lane)
{
    const int b1 = ((lane >> 4) << 3) + (lane & 7);
    const int b2 = ((lane >> 3) & 1) * 8;
#pragma unroll
    for (int i = 0; i < NB; i++)
#pragma unroll
        for (int j = 0; j < 4; j++) acc[i][j] = 0.f;
#pragma unroll
    for (int kt = 0; kt < KT; kt++) {
        uint32_t aH[4], aL[4];
        al.load(kt, aH, aL);
#pragma unroll
        for (int nt = 0; nt < NB / 2; nt++) {
            uint32_t bH[4], bL[4];
            if (TRANS) {
                ldmx4_t(bH, smem_u32(BH + (kt * 16 + b1) * SB + wn + nt * 16 + b2));
                ldmx4_t(bL, smem_u32(BL + (kt * 16 + b1) * SB + wn + nt * 16 + b2));
            } else {
                ldmx4(bH, smem_u32(BH + (wn + nt * 16 + b1) * SB + kt * 16 + b2));
                ldmx4(bL, smem_u32(BL + (wn + nt * 16 + b1) * SB + kt * 16 + b2));
            }
#pragma unroll
            for (int h = 0; h < 2; h++) {
                int nb = nt * 2 + h;
                uint32_t h0, h1, l0, l1;
                if (TRANS) { h0 = bH[h]; h1 = bH[h + 2]; l0 = bL[h]; l1 = bL[h + 2]; }
                else       { h0 = bH[2 * h]; h1 = bH[2 * h + 1];
                             l0 = bL[2 * h]; l1 = bL[2 * h + 1]; }
                mma_f16(acc[nb], aH, h0, h1);
                mma_f16(acc[nb], aL, h0, h1);
                mma_f16(acc[nb], aH, l0, l1);
            }
        }
    }
}

// hi-only global -> smem copy with padded stride
template<int W, int ST>
__device__ __forceinline__ void load_h1_smem(const __half* __restrict__ srcH,
                                             int n, __half* dh, int tid)
{
#pragma unroll
    for (int idx = tid * 8; idx < n; idx += 1024) {
        int row = idx / W, col = idx % W;
        *(uint4*)(dh + row * ST + col) = *(const uint4*)(srcH + idx);
    }
}

__global__ void __launch_bounds__(128, 6) fused_bg(
    const float* __restrict__ feats,
    const float* __restrict__ kw_g, const float* __restrict__ kb_g)
{
    // w: 64x72 hi (9216 B) ; x: 32x72 hi+lo (9216 B) ; s: 32x40 hi+lo (5120 B)
    __shared__ __align__(16) __half wS[64 * STW];
    __shared__ __align__(16) __half xS[2 * 32 * STW];
    __shared__ __align__(16) __half sS[2 * 32 * STN];
    __shared__ float red[8];

    __half *wH = wS;
    __half *xH = xS, *xL = xS + 32 * STW;
    __half *sH = sS, *sL = sS + 32 * STN;
    float* sc = (float*)wS;   // overlays dead w region at stage 5+ (4608 B)

    const int bn = blockIdx.x, g = blockIdx.y;
    const int tid = threadIdx.x;
    const int lane = tid & 31, wrp = tid >> 5;
    const int rw   = (wrp & 1) * 16;
    const int wn32 = (wrp >> 1) * 32;
    const int wn16 = (wrp >> 1) * 16;
    const int lr = lane >> 2, lc = 2 * (lane & 3);
    const int fr0 = rw + lr, fk0 = lc;
    const size_t bg = (size_t)bn * 4 + g;

    load_h1_smem<64, STW>(g_Mh + bg * 4096, 4096, wH, tid);
    __syncthreads();

    float acc[4][4];
    const ALoadGF af{feats + bg * 2048, 64, fr0, fk0};

    // stage 1: fM = relu(ln2d(f @ M)) -> x (2-pass; x stored hi+lo)
    mm2p<ALoadGF, 4, 4, true, STW>(acc, af, wH, wn32, lane);
    ln2048_relu(acc, red);
    load_h1_smem<64, STW>(g_Vh + bg * 4096, 4096, wH, tid);   // w dead -> Vw
#pragma unroll
    for (int nb = 0; nb < 4; nb++) {
        int c = wn32 + nb * 8 + lc;
        uint32_t hp, lp;
        split2_pack(acc[nb][0], acc[nb][1], hp, lp);
        *(uint32_t*)(xH + fr0 * STW + c) = hp;
        *(uint32_t*)(xL + fr0 * STW + c) = lp;
        split2_pack(acc[nb][2], acc[nb][3], hp, lp);
        *(uint32_t*)(xH + (fr0 + 8) * STW + c) = hp;
        *(uint32_t*)(xL + (fr0 + 8) * STW + c) = lp;
    }
    __syncthreads();

    // stage 2: fMS = relu(ln2d(S @ fM)) -> global (3-pass on x)
    {
        const ALoadGB as{g_Sh + bg * 1024, g_Sl + bg * 1024, 32, fr0, fk0};
        mm3p<ALoadGB, 4, 2, true, STW>(acc, as, xH, xL, wn32, lane);
    }
    ln2048_relu(acc, red);
#pragma unroll
    for (int nb = 0; nb < 4; nb++) {
        int c = wn32 + nb * 8 + lc;
        size_t o0 = bg * 2048 + (size_t)fr0 * 64 + c;
        size_t o1 = o0 + 8 * 64;
        uint32_t hp, lp;
        split2_pack(acc[nb][0], acc[nb][1], hp, lp);
        *(uint32_t*)(g_FMSh + o0) = hp;
        *(uint32_t*)(g_FMSl + o0) = lp;
        split2_pack(acc[nb][2], acc[nb][3], hp, lp);
        *(uint32_t*)(g_FMSh + o1) = hp;
        *(uint32_t*)(g_FMSl + o1) = lp;
    }
    __syncthreads();

    // stage 3: v = relu(ln2d(f @ Vw)) -> x (2-pass)
    mm2p<ALoadGF, 4, 4, true, STW>(acc, af, wH, wn32, lane);
    ln2048_relu(acc, red);
#pragma unroll
    for (int nb = 0; nb < 4; nb++) {
        int c = wn32 + nb * 8 + lc;
        uint32_t hp, lp;
        split2_pack(acc[nb][0], acc[nb][1], hp, lp);
        *(uint32_t*)(xH + fr0 * STW + c) = hp;
        *(uint32_t*)(xL + fr0 * STW + c) = lp;
        split2_pack(acc[nb][2], acc[nb][3], hp, lp);
        *(uint32_t*)(xH + (fr0 + 8) * STW + c) = hp;
        *(uint32_t*)(xL + (fr0 + 8) * STW + c) = lp;
    }
    __syncthreads();

    float a2[2][4];

    // stage 4: k = kw @ v^T + kb -> sH (3-pass on x; k stored hi only)
    {
        const ALoadGF akw{kw_g + g * 2048, 64, fr0, fk0};
        mm3p<ALoadGF, 2, 4, false, STW>(a2, akw, xH, xL, wn16, lane);
        float b0 = __ldg(kb_g + g * 32 + fr0);
        float b1 = __ldg(kb_g + g * 32 + fr0 + 8);
#pragma unroll
        for (int nb = 0; nb < 2; nb++) {
            int c = wn16 + nb * 8 + lc;
            *(uint32_t*)(sH + fr0 * STN + c)       = pack2h(a2[nb][0] + b0, a2[nb][1] + b0);
            *(uint32_t*)(sH + (fr0 + 8) * STN + c) = pack2h(a2[nb][2] + b1, a2[nb][3] + b1);
        }
    }
    __syncthreads();

    // stage 5: scores = q @ k -> sc (2-pass; k hi only)
    {
        const ALoadGB aq{g_Qh + bg * 1024, g_Ql + bg * 1024, 32, fr0, fk0};
        mm2p<ALoadGB, 2, 2, true, STN>(a2, aq, sH, wn16, lane);
#pragma unroll
        for (int nb = 0; nb < 2; nb++) {
            int c = wn16 + nb * 8 + lc;
            *(float2*)(sc + fr0 * 36 + c)       = make_float2(a2[nb][0], a2[nb][1]);
            *(float2*)(sc + (fr0 + 8) * 36 + c) = make_float2(a2[nb][2], a2[nb][3]);
        }
    }
    __syncthreads();

    // stage 6: softmax(sc / 8) -> att hi/lo in s buffers
    {
        const int tx8 = tid & 7, ty16 = tid >> 3;
#pragma unroll
        for (int i = 0; i < 2; i++) {
            int row = 2 * ty16 + i;
            float v[4];
#pragma unroll
            for (int j = 0; j < 4; j++) v[j] = sc[row * 36 + 4 * tx8 + j];
            float m = fmaxf(fmaxf(v[0], v[1]), fmaxf(v[2], v[3]));
#pragma unroll
            for (int o = 4; o > 0; o >>= 1)
                m = fmaxf(m, __shfl_xor_sync(0xffffffffu, m, o));
            float s = 0.f;
#pragma unroll
            for (int j = 0; j < 4; j++) { v[j] = __expf((v[j] - m) * 0.125f); s += v[j]; }
#pragma unroll
            for (int o = 4; o > 0; o >>= 1)
                s += __shfl_xor_sync(0xffffffffu, s, o);
            float inv = __frcp_rn(s);
#pragma unroll
            for (int j = 0; j < 4; j++) {
                float p = v[j] * inv;
                __half h, l;
                split_h(p, h, l);
                sH[row * STN + 4 * tx8 + j] = h;
                sL[row * STN + 4 * tx8 + j] = l;
            }
        }
    }
    __syncthreads();

    // stage 7: fc = relu(ln2d(att @ v)) -> global (3-pass on x)
    {
        const ALoadS aatt{
            smem_u32(sH + (rw + (lane & 15)) * STN + (lane >> 4) * 8),
            smem_u32(sL + (rw + (lane & 15)) * STN + (lane >> 4) * 8)};
        mm3p<ALoadS, 4, 2, true, STW>(acc, aatt, xH, xL, wn32, lane);
    }
    ln2048_relu(acc, red);
#pragma unroll
    for (int nb = 0; nb < 4; nb++) {
        int c = wn32 + nb * 8 + lc;
        size_t o0 = bg * 2048 + (size_t)fr0 * 64 + c;
        size_t o1 = o0 + 8 * 64;
        uint32_t hp, lp;
        split2_pack(acc[nb][0], acc[nb][1], hp, lp);
        *(uint32_t*)(g_FCh + o0) = hp;
        *(uint32_t*)(g_FCl + o0) = lp;
        split2_pack(acc[nb][2], acc[nb][3], hp, lp);
        *(uint32_t*)(g_FCh + o1) = hp;
        *(uint32_t*)(g_FCl + o1) = lp;
    }
}

// ============== residual + split-K reduce + affine LayerNorm ===============
__global__ void __launch_bounds__(256) final_ln(
    const float* __restrict__ qv,
    const float* __restrict__ wA, const float* __restrict__ bA,
    const float* __restrict__ wB, const float* __restrict__ bB,
    float* __restrict__ out)
{
    const int r = blockIdx.x, z = blockIdx.y, c = threadIdx.x;
    const float* w = z ? wB : wA;
    const float* b = z ? bB : bA;
    float x = qv[(size_t)r * 256 + c];
#pragma unroll
    for (int k = 0; k < 4; k++)
        x += g_P[(size_t)(z * 4 + k) * 614400 + (size_t)r * 256 + c];

    __shared__ float sred[16];
    float s = x, q = x * x;
#pragma unroll
    for (int o = 16; o > 0; o >>= 1) {
        s += __shfl_xor_sync(0xffffffffu, s, o);
        q += __shfl_xor_sync(0xffffffffu, q, o);
    }
    int wp = threadIdx.x >> 5;
    if ((threadIdx.x & 31) == 0) { sred[wp] = s; sred[8 + wp] = q; }
    __syncthreads();
    float S = 0.f, Q2 = 0.f;
#pragma unroll
    for (int i = 0; i < 8; i++) { S += sred[i]; Q2 += sred[8 + i]; }
    float mean = S * (1.f / 256.f);
    float var  = Q2 * (1.f / 256.f) - mean * mean;
    float inv  = rsqrtf(var + 1e-5f);
    out[(size_t)z * 614400 + (size_t)r * 256 + c] = (x - mean) * inv * w[c] + b[c];
}

// ================================ launcher =================================
extern "C" void kernel_launch(void* const* d_in, const int* in_sizes, int n_in,
                              void* d_out, int out_size)
{
    const float* feats = (const float*)d_in[0];
    const float* qv    = (const float*)d_in[1];
    const float* m_w   = (const float*)d_in[7];
    const float* m_b   = (const float*)d_in[8];
    const float* s_w   = (const float*)d_in[9];
    const float* s_b   = (const float*)d_in[10];
    const float* q_w   = (const float*)d_in[11];
    const float* q_b   = (const float*)d_in[12];
    const float* v_w   = (const float*)d_in[13];
    const float* v_b   = (const float*)d_in[14];
    const float* k_w   = (const float*)d_in[15];
    const float* k_b   = (const float*)d_in[16];
    const float* Wv_w  = (const float*)d_in[17];
    const float* Wv_b  = (const float*)d_in[18];
    const float* Wv2_w = (const float*)d_in[19];
    const float* Wv2_b = (const float*)d_in[20];
    const float* lnA_w = (const float*)d_in[21];
    const float* lnA_b = (const float*)d_in[22];
    const float* lnB_w = (const float*)d_in[23];
    const float* lnB_b = (const float*)d_in[24];
    float* out = (float*)d_out;

    float* gP;
    cudaGetSymbolAddress((void**)&gP, g_P);
    __half *Wvh, *W2h, *FMSh, *FMSl, *FCh, *FCl;
    cudaGetSymbolAddress((void**)&Wvh, g_Wvh);
    cudaGetSymbolAddress((void**)&W2h, g_W2h);
    cudaGetSymbolAddress((void**)&FMSh, g_FMSh); cudaGetSymbolAddress((void**)&FMSl, g_FMSl);
    cudaGetSymbolAddress((void**)&FCh, g_FCh);   cudaGetSymbolAddress((void**)&FCl, g_FCl);

    cudaFuncSetAttribute(gen_gemm, cudaFuncAttributeMaxDynamicSharedMemorySize, GEMM_SMEM);
    cudaFuncSetAttribute(hmma_gemm, cudaFuncAttributeMaxDynamicSharedMemorySize, GEMM_SMEM);

    // 0) split fp32 operands into fp16 (qv hi+lo, weights hi only)
    split_kernel<<<dim3(4096, 1, 7), 256>>>(qv, m_w, v_w, s_w, q_w, Wv_w, Wv2_w);

    // 1) merged M/V/S/Q generators (fp16x2; M/V hi-only outputs)
    gen_gemm<<<dim3(19, 128, 4), 256, GEMM_SMEM>>>(m_b, v_b, s_b, q_b);

    // 2) fused per-(bn,g) dynamic conv + attention (mixed 2/3-pass)
    fused_bg<<<dim3(2400, 4), 128>>>(feats, k_w, k_b);

    // 3) output projections: (2400x8192) @ (256x8192)^T, split-K=4, fp16x2
    hmma_gemm<<<dim3(2, 19, 8), 256, GEMM_SMEM>>>(
        FMSh, FMSl, Wvh, Wv_b, gP,
        FCh,  FCl,  W2h, Wv2_b, gP + 4 * 614400,
        2400, 256, 8192, 2048, 4, 614400);

    // 4) residual + split-K reduce + affine LayerNorm
    final_ln<<<dim3(2400, 2), 256>>>(qv, lnA_w, lnA_b, lnB_w, lnB_b, out);
}

// round 15
// speedup vs baseline: 3.9130x; 1.1231x over previous
#include <cuda_runtime.h>
#include <cuda_fp16.h>
#include <cstdint>

// ============================ problem constants ============================
// B=8, N=300 -> BN=2400; G=4; P=O=32; CG=DG=64; IN_DIM=OUT_DIM=256; TEMPER=8

// ===================== scratch (__device__ globals) ========================
__device__ float g_P[9830400];    // split-K slices of (2400,256)

__device__ __half g_Mh[39321600];                 // hi only (B operand)
__device__ __half g_Vh[39321600];
__device__ __half g_Sh[9830400],  g_Sl[9830400];  // A operand: hi+lo
__device__ __half g_Qh[9830400],  g_Ql[9830400];

__device__ __half g_qvh[614400],  g_qvl[614400];  // A operand: hi+lo
__device__ __half g_mwh[4194304];                 // B operands: hi only
__device__ __half g_vwh[4194304];
__device__ __half g_swh[1048576];
__device__ __half g_qwh[1048576];
__device__ __half g_Wvh[2097152];
__device__ __half g_W2h[2097152];
__device__ __half g_FMSh[19660800], g_FMSl[19660800];  // A operand: hi+lo
__device__ __half g_FCh[19660800],  g_FCl[19660800];

// ============================ small helpers ================================
__device__ __forceinline__ uint32_t smem_u32(const void* p) {
    uint32_t a;
    asm("{ .reg .u64 t; cvta.to.shared.u64 t, %1; cvt.u32.u64 %0, t; }"
        : "=r"(a) : "l"(p));
    return a;
}
__device__ __forceinline__ void split_h(float x, __half& h, __half& l) {
    h = __float2half_rn(x);
    l = __float2half_rn(x - __half2float(h));
}
__device__ __forceinline__ void ldmx4(uint32_t r[4], uint32_t addr) {
    asm volatile("ldmatrix.sync.aligned.m8n8.x4.shared.b16 {%0,%1,%2,%3}, [%4];"
                 : "=r"(r[0]), "=r"(r[1]), "=r"(r[2]), "=r"(r[3]) : "r"(addr));
}
__device__ __forceinline__ void ldmx4_t(uint32_t r[4], uint32_t addr) {
    asm volatile("ldmatrix.sync.aligned.m8n8.x4.trans.shared.b16 {%0,%1,%2,%3}, [%4];"
                 : "=r"(r[0]), "=r"(r[1]), "=r"(r[2]), "=r"(r[3]) : "r"(addr));
}
__device__ __forceinline__ void mma_f16(float d[4], const uint32_t a[4],
                                        const uint32_t b0, const uint32_t b1) {
    asm volatile(
        "mma.sync.aligned.m16n8k16.row.col.f32.f16.f16.f32 "
        "{%0,%1,%2,%3}, {%4,%5,%6,%7}, {%8,%9}, {%0,%1,%2,%3};"
        : "+f"(d[0]), "+f"(d[1]), "+f"(d[2]), "+f"(d[3])
        : "r"(a[0]), "r"(a[1]), "r"(a[2]), "r"(a[3]), "r"(b0), "r"(b1));
}
__device__ __forceinline__ void split2_pack(float a, float b, uint32_t& hp, uint32_t& lp) {
    __half ha = __float2half_rn(a), hb = __float2half_rn(b);
    union { __half h[2]; uint32_t u; } H, L;
    H.h[0] = ha; H.h[1] = hb;
    L.h[0] = __float2half_rn(a - __half2float(ha));
    L.h[1] = __float2half_rn(b - __half2float(hb));
    hp = H.u; lp = L.u;
}
__device__ __forceinline__ uint32_t pack2h(float a, float b) {
    union { __half h[2]; uint32_t u; } U;
    U.h[0] = __float2half_rn(a); U.h[1] = __float2half_rn(b);
    return U.u;
}
// cp.async helpers
__device__ __forceinline__ void cp_async16(uint32_t saddr, const void* g) {
    asm volatile("cp.async.cg.shared.global [%0], [%1], 16;"
                 :: "r"(saddr), "l"(g));
}
__device__ __forceinline__ void cp_async16p(uint32_t saddr, const void* g, bool v) {
    int sz = v ? 16 : 0;
    asm volatile("cp.async.cg.shared.global [%0], [%1], 16, %2;"
                 :: "r"(saddr), "l"(g), "r"(sz));
}
__device__ __forceinline__ void cp_commit() {
    asm volatile("cp.async.commit_group;" ::: "memory");
}
__device__ __forceinline__ void cp_wait0() {
    asm volatile("cp.async.wait_group 0;" ::: "memory");
}
__device__ __forceinline__ void cp_wait1() {
    asm volatile("cp.async.wait_group 1;" ::: "memory");
}

// ================= operand split prep (fp32 -> fp16) =======================
// z==0 (qv): hi+lo. z>=1 (weights, B operands): hi only.
__global__ void __launch_bounds__(256) split_kernel(
    const float* __restrict__ qv, const float* __restrict__ mw,
    const float* __restrict__ vw, const float* __restrict__ sw,
    const float* __restrict__ qw, const float* __restrict__ Wv,
    const float* __restrict__ W2)
{
    const float* src; __half *dh, *dl = nullptr; int n;
    switch (blockIdx.z) {
        case 0: src = qv; dh = g_qvh; dl = g_qvl; n = 614400;  break;
        case 1: src = mw; dh = g_mwh; n = 4194304; break;
        case 2: src = vw; dh = g_vwh; n = 4194304; break;
        case 3: src = sw; dh = g_swh; n = 1048576; break;
        case 4: src = qw; dh = g_qwh; n = 1048576; break;
        case 5: src = Wv; dh = g_Wvh; n = 2097152; break;
        default:src = W2; dh = g_W2h; n = 2097152; break;
    }
    int i = (blockIdx.x * 256 + threadIdx.x) * 4;
    if (i >= n) return;
    float4 v = *(const float4*)(src + i);
    union U { __half b[4]; uint2 u; } H, L;
    split_h(v.x, H.b[0], L.b[0]);
    split_h(v.y, H.b[1], L.b[1]);
    split_h(v.z, H.b[2], L.b[2]);
    split_h(v.w, H.b[3], L.b[3]);
    *(uint2*)(dh + i) = H.u;
    if (dl) *(uint2*)(dl + i) = L.u;
}

// ====== shared GEMM core: fp16, NP passes, cp.async 3-stage pipeline =======
static constexpr int RS = 40;
static constexpr int BUF = 128 * RS * 2;
static constexpr int STAGE_BYTES = 3 * BUF;         // Ah|Al|Bh
static constexpr int GEMM_SMEM = 3 * STAGE_BYTES;   // 92160 B

template<int NP>
__device__ __forceinline__ void gemm_core(
    float acc[2][8][4],
    const __half* __restrict__ Ah, const __half* __restrict__ Al,
    const __half* __restrict__ Wh,
    char* sm, int m0, int n0, int M, int lda, int kBegin, int NC)
{
    const int tid = threadIdx.x, wid = tid >> 5, lane = tid & 31;
    const int wm = (wid & 3) * 32;
    const int wn = (wid >> 2) * 64;
    const int lrow = tid >> 2;
    const int lseg = (tid & 3) * 8;
    const uint32_t smb = smem_u32(sm);

    const int arow = lane & 15, acol = (lane >> 4) * 8;
    const int bgrp = lane >> 3, brow = lane & 7;
    const int bn_off = (bgrp >> 1) * 8 + brow;
    const int bk_off = (bgrp & 1) * 8;

#pragma unroll
    for (int i = 0; i < 2; i++)
#pragma unroll
        for (int j = 0; j < 8; j++)
#pragma unroll
            for (int q = 0; q < 4; q++) acc[i][j][q] = 0.f;

    auto issue = [&](int c, int s) {
        const int kk = kBegin + c * 32;
        const uint32_t sb = smb + s * STAGE_BYTES;
#pragma unroll
        for (int j = 0; j < 2; j++) {
            int row = lrow + 64 * j;
            int gm = m0 + row;
            bool va = (gm < M);
            int gmc = va ? gm : (M - 1);
            uint32_t off = (uint32_t)(row * RS + lseg) * 2;
            cp_async16p(sb + off, Ah + (size_t)gmc * lda + kk + lseg, va);
            if (NP == 2)
                cp_async16p(sb + BUF + off, Al + (size_t)gmc * lda + kk + lseg, va);
            cp_async16(sb + 2 * BUF + off, Wh + (size_t)(n0 + row) * lda + kk + lseg);
        }
    };

    issue(0, 0); cp_commit();
    if (NC > 1) { issue(1, 1); cp_commit(); }

    for (int c = 0; c < NC; c++) {
        if (c + 1 < NC) cp_wait1(); else cp_wait0();
        __syncthreads();
        if (c + 2 < NC) { issue(c + 2, (c + 2) % 3); cp_commit(); }

        const uint32_t uAh = smb + (c % 3) * STAGE_BYTES;
        const uint32_t uAl = uAh + BUF;
        const uint32_t uBh = uAh + 2 * BUF;
#pragma unroll
        for (int ksp = 0; ksp < 2; ksp++) {
            uint32_t fAh[2][4], fAl[2][4], fBh[4][4];
#pragma unroll
            for (int mi = 0; mi < 2; mi++) {
                uint32_t off = 2u * ((wm + mi * 16 + arow) * RS + ksp * 16 + acol);
                ldmx4(fAh[mi], uAh + off);
                if (NP == 2) ldmx4(fAl[mi], uAl + off);
            }
#pragma unroll
            for (int nb = 0; nb < 4; nb++) {
                uint32_t off = 2u * ((wn + nb * 16 + bn_off) * RS + ksp * 16 + bk_off);
                ldmx4(fBh[nb], uBh + off);
            }
#pragma unroll
            for (int mi = 0; mi < 2; mi++)
#pragma unroll
                for (int nf = 0; nf < 8; nf++) {
                    const uint32_t* bh = &fBh[nf >> 1][(nf & 1) * 2];
                    mma_f16(acc[mi][nf], fAh[mi], bh[0], bh[1]);
                    if (NP == 2) mma_f16(acc[mi][nf], fAl[mi], bh[0], bh[1]);
                }
        }
    }
}

// ====== merged generator GEMM (M/V/S/Q), m-fastest raster, fp16 out ========
// z 0/1 (M/V): 1-pass (hi-only consumers); z 2/3 (S/Q): 2-pass hi+lo out.
__global__ void __launch_bounds__(256, 2) gen_gemm(
    const float* __restrict__ mb, const float* __restrict__ vb,
    const float* __restrict__ sb, const float* __restrict__ qb)
{
    extern __shared__ char sm[];

    const __half* Wh; const float* bias;
    __half *Ch, *Cl; int Nout, nt;
    switch (blockIdx.z) {
        case 0: Wh = g_mwh; bias = mb; Ch = g_Mh; Cl = nullptr; Nout = 16384; nt = 128; break;
        case 1: Wh = g_vwh; bias = vb; Ch = g_Vh; Cl = nullptr; Nout = 16384; nt = 128; break;
        case 2: Wh = g_swh; bias = sb; Ch = g_Sh; Cl = g_Sl;    Nout = 4096;  nt = 32;  break;
        default:Wh = g_qwh; bias = qb; Ch = g_Qh; Cl = g_Ql;    Nout = 4096;  nt = 32;  break;
    }
    if ((int)blockIdx.y >= nt) return;

    const int m0 = blockIdx.x * 128;
    const int n0 = blockIdx.y * 128;

    float acc[2][8][4];
    if (blockIdx.z < 2)
        gemm_core<1>(acc, g_qvh, g_qvl, Wh, sm, m0, n0, 2400, 256, 0, 8);
    else
        gemm_core<2>(acc, g_qvh, g_qvl, Wh, sm, m0, n0, 2400, 256, 0, 8);

    const int lane = threadIdx.x & 31, wid = threadIdx.x >> 5;
    const int wm = (wid & 3) * 32, wn = (wid >> 2) * 64;
    const int erow = lane >> 2, ecol = (lane & 3) * 2;
    const bool wantLo = (Cl != nullptr);
#pragma unroll
    for (int mi = 0; mi < 2; mi++) {
        int r0 = m0 + wm + mi * 16 + erow;
#pragma unroll
        for (int half = 0; half < 2; half++) {
            int r = r0 + half * 8;
            if (r >= 2400) continue;
#pragma unroll
            for (int nf = 0; nf < 8; nf++) {
                int col = n0 + wn + nf * 8 + ecol;
                float x0 = acc[mi][nf][half * 2 + 0] + __ldg(bias + col);
                float x1 = acc[mi][nf][half * 2 + 1] + __ldg(bias + col + 1);
                size_t o = (size_t)r * Nout + col;
                if (wantLo) {
                    uint32_t hp, lp;
                    split2_pack(x0, x1, hp, lp);
                    *(uint32_t*)(Ch + o) = hp;
                    *(uint32_t*)(Cl + o) = lp;
                } else {
                    *(uint32_t*)(Ch + o) = pack2h(x0, x1);
                }
            }
        }
    }
}

// ============ output-projection GEMM (split-K, fp32 out, 2-pass) ===========
__global__ void __launch_bounds__(256, 2) hmma_gemm(
    const __half* __restrict__ Ah0, const __half* __restrict__ Al0,
    const __half* __restrict__ Wh0,
    const float* __restrict__ b0, float* __restrict__ C0,
    const __half* __restrict__ Ah1, const __half* __restrict__ Al1,
    const __half* __restrict__ Wh1,
    const float* __restrict__ b1, float* __restrict__ C1,
    int M, int Nout, int lda, int kPerCta, int splitk, size_t sliceStride)
{
    extern __shared__ char sm[];

    const int z  = blockIdx.z / splitk;
    const int ks = blockIdx.z % splitk;
    const __half* Ah = z ? Ah1 : Ah0;
    const __half* Al = z ? Al1 : Al0;
    const __half* Wh = z ? Wh1 : Wh0;
    const float* bias = z ? b1 : b0;
    float* Cp = (z ? C1 : C0) + (size_t)ks * sliceStride;

    const int m0 = blockIdx.y * 128;
    const int n0 = blockIdx.x * 128;

    float acc[2][8][4];
    gemm_core<2>(acc, Ah, Al, Wh, sm, m0, n0, M, lda, ks * kPerCta, kPerCta / 32);

    const bool addB = (ks == 0);
    const int lane = threadIdx.x & 31, wid = threadIdx.x >> 5;
    const int wm = (wid & 3) * 32, wn = (wid >> 2) * 64;
    const int erow = lane >> 2, ecol = (lane & 3) * 2;
#pragma unroll
    for (int mi = 0; mi < 2; mi++) {
        int r0 = m0 + wm + mi * 16 + erow;
#pragma unroll
        for (int half = 0; half < 2; half++) {
            int r = r0 + half * 8;
            if (r >= M) continue;
#pragma unroll
            for (int nf = 0; nf < 8; nf++) {
                int col = n0 + wn + nf * 8 + ecol;
                float x0 = acc[mi][nf][half * 2 + 0];
                float x1 = acc[mi][nf][half * 2 + 1];
                if (addB) { x0 += __ldg(bias + col); x1 += __ldg(bias + col + 1); }
                *(float2*)(Cp + (size_t)r * Nout + col) = make_float2(x0, x1);
            }
        }
    }
}

// ========= fused per-(bn,g) kernel (HMMA, mixed 2/3-pass, ~24 KB smem) =====
static constexpr int STW = 72;
static constexpr int STN = 40;

__device__ __forceinline__ void ln2048_relu(float acc[4][4], float* red) {
    float s = 0.f, q = 0.f;
#pragma unroll
    for (int i = 0; i < 4; i++)
#pragma unroll
        for (int j = 0; j < 4; j++) { s += acc[i][j]; q += acc[i][j] * acc[i][j]; }
#pragma unroll
    for (int o = 16; o > 0; o >>= 1) {
        s += __shfl_xor_sync(0xffffffffu, s, o);
        q += __shfl_xor_sync(0xffffffffu, q, o);
    }
    int w = threadIdx.x >> 5;
    __syncthreads();
    if ((threadIdx.x & 31) == 0) { red[w] = s; red[4 + w] = q; }
    __syncthreads();
    s = red[0] + red[1] + red[2] + red[3];
    q = red[4] + red[5] + red[6] + red[7];
    float mean = s * (1.f / 2048.f);
    float var  = q * (1.f / 2048.f) - mean * mean;
    float inv  = rsqrtf(var + 1e-5f);
#pragma unroll
    for (int i = 0; i < 4; i++)
#pragma unroll
        for (int j = 0; j < 4; j++)
            acc[i][j] = fmaxf((acc[i][j] - mean) * inv, 0.f);
}

struct ALoadS {
    uint32_t addrH, addrL;
    __device__ __forceinline__ void load(int kt, uint32_t aH[4], uint32_t aL[4]) const {
        ldmx4(aH, addrH + kt * 32);
        ldmx4(aL, addrL + kt * 32);
    }
};
struct ALoadGB {
    const __half *H, *L; int ld, r0, k0;
    __device__ __forceinline__ void load(int kt, uint32_t aH[4], uint32_t aL[4]) const {
        int k = kt * 16 + k0;
        aH[0] = *(const uint32_t*)(H + r0 * ld + k);
        aH[1] = *(const uint32_t*)(H + (r0 + 8) * ld + k);
        aH[2] = *(const uint32_t*)(H + r0 * ld + k + 8);
        aH[3] = *(const uint32_t*)(H + (r0 + 8) * ld + k + 8);
        aL[0] = *(const uint32_t*)(L + r0 * ld + k);
        aL[1] = *(const uint32_t*)(L + (r0 + 8) * ld + k);
        aL[2] = *(const uint32_t*)(L + r0 * ld + k + 8);
        aL[3] = *(const uint32_t*)(L + (r0 + 8) * ld + k + 8);
    }
};
struct ALoadGF {
    const float* A; int ld, r0, k0;
    __device__ __forceinline__ void load(int kt, uint32_t aH[4], uint32_t aL[4]) const {
        int k = kt * 16 + k0;
        float2 v0 = *(const float2*)(A + r0 * ld + k);
        float2 v1 = *(const float2*)(A + (r0 + 8) * ld + k);
        float2 v2 = *(const float2*)(A + r0 * ld + k + 8);
        float2 v3 = *(const float2*)(A + (r0 + 8) * ld + k + 8);
        split2_pack(v0.x, v0.y, aH[0], aL[0]);
        split2_pack(v1.x, v1.y, aH[1], aL[1]);
        split2_pack(v2.x, v2.y, aH[2], aL[2]);
        split2_pack(v3.x, v3.y, aH[3], aL[3]);
    }
};

// 2-pass: B hi only
template<class AL, int NB, int KT, bool TRANS, int SB>
__device__ __forceinline__ void mm2p(float acc[NB][4], const AL& al,
    const __half* BH, int wn, int lane)
{
    const int b1 = ((lane >> 4) << 3) + (lane & 7);
    const int b2 = ((lane >> 3) & 1) * 8;
#pragma unroll
    for (int i = 0; i < NB; i++)
#pragma unroll
        for (int j = 0; j < 4; j++) acc[i][j] = 0.f;
#pragma unroll
    for (int kt = 0; kt < KT; kt++) {
        uint32_t aH[4], aL[4];
        al.load(kt, aH, aL);
#pragma unroll
        for (int nt = 0; nt < NB / 2; nt++) {
            uint32_t bH[4];
            if (TRANS) ldmx4_t(bH, smem_u32(BH + (kt * 16 + b1) * SB + wn + nt * 16 + b2));
            else       ldmx4(bH, smem_u32(BH + (wn + nt * 16 + b1) * SB + kt * 16 + b2));
#pragma unroll
            for (int h = 0; h < 2; h++) {
                int nb = nt * 2 + h;
                uint32_t h0, h1;
                if (TRANS) { h0 = bH[h]; h1 = bH[h + 2]; }
                else       { h0 = bH[2 * h]; h1 = bH[2 * h + 1]; }
                mma_f16(acc[nb], aH, h0, h1);
                mma_f16(acc[nb], aL, h0, h1);
            }
        }
    }
}

// 3-pass: B hi+lo
template<class AL, int NB, int KT, bool TRANS, int SB>
__device__ __forceinline__ void mm3p(float acc[NB][4], const AL& al,
    const __half* BH, const __half* BL, int wn, int lane)
{
    const int b1 = ((lane >> 4) << 3) + (lane & 7);
    const int b2 = ((lane >> 3) & 1) * 8;
#pragma unroll
    for (int i = 0; i < NB; i++)
#pragma unroll
        for (int j = 0; j < 4; j++) acc[i][j] = 0.f;
#pragma unroll
    for (int kt = 0; kt < KT; kt++) {
        uint32_t aH[4], aL[4];
        al.load(kt, aH, aL);
#pragma unroll
        for (int nt = 0; nt < NB / 2; nt++) {
            uint32_t bH[4], bL[4];
            if (TRANS) {
                ldmx4_t(bH, smem_u32(BH + (kt * 16 + b1) * SB + wn + nt * 16 + b2));
                ldmx4_t(bL, smem_u32(BL + (kt * 16 + b1) * SB + wn + nt * 16 + b2));
            } else {
                ldmx4(bH, smem_u32(BH + (wn + nt * 16 + b1) * SB + kt * 16 + b2));
                ldmx4(bL, smem_u32(BL + (wn + nt * 16 + b1) * SB + kt * 16 + b2));
            }
#pragma unroll
            for (int h = 0; h < 2; h++) {
                int nb = nt * 2 + h;
                uint32_t h0, h1, l0, l1;
                if (TRANS) { h0 = bH[h]; h1 = bH[h + 2]; l0 = bL[h]; l1 = bL[h + 2]; }
                else       { h0 = bH[2 * h]; h1 = bH[2 * h + 1];
                             l0 = bL[2 * h]; l1 = bL[2 * h + 1]; }
                mma_f16(acc[nb], aH, h0, h1);
                mma_f16(acc[nb], aL, h0, h1);
                mma_f16(acc[nb], aH, l0, l1);
            }
        }
    }
}

// hi-only global -> smem copy with padded stride
template<int W, int ST>
__device__ __forceinline__ void load_h1_smem(const __half* __restrict__ srcH,
                                             int n, __half* dh, int tid)
{
#pragma unroll
    for (int idx = tid * 8; idx < n; idx += 1024) {
        int row = idx / W, col = idx % W;
        *(uint4*)(dh + row * ST + col) = *(const uint4*)(srcH + idx);
    }
}

__global__ void __launch_bounds__(128, 6) fused_bg(
    const float* __restrict__ feats,
    const float* __restrict__ kw_g, const float* __restrict__ kb_g)
{
    __shared__ __align__(16) __half wS[64 * STW];
    __shared__ __align__(16) __half xS[2 * 32 * STW];
    __shared__ __align__(16) __half sS[2 * 32 * STN];
    __shared__ float red[8];

    __half *wH = wS;
    __half *xH = xS, *xL = xS + 32 * STW;
    __half *sH = sS, *sL = sS + 32 * STN;
    float* sc = (float*)wS;   // overlays dead w region at stage 5+ (4608 B)

    const int bn = blockIdx.x, g = blockIdx.y;
    const int tid = threadIdx.x;
    const int lane = tid & 31, wrp = tid >> 5;
    const int rw   = (wrp & 1) * 16;
    const int wn32 = (wrp >> 1) * 32;
    const int wn16 = (wrp >> 1) * 16;
    const int lr = lane >> 2, lc = 2 * (lane & 3);
    const int fr0 = rw + lr, fk0 = lc;
    const size_t bg = (size_t)bn * 4 + g;

    load_h1_smem<64, STW>(g_Mh + bg * 4096, 4096, wH, tid);
    __syncthreads();

    float acc[4][4];
    const ALoadGF af{feats + bg * 2048, 64, fr0, fk0};

    // stage 1: fM = relu(ln2d(f @ M)) -> x (2-pass; x stored hi+lo)
    mm2p<ALoadGF, 4, 4, true, STW>(acc, af, wH, wn32, lane);
    ln2048_relu(acc, red);
    load_h1_smem<64, STW>(g_Vh + bg * 4096, 4096, wH, tid);   // w dead -> Vw
#pragma unroll
    for (int nb = 0; nb < 4; nb++) {
        int c = wn32 + nb * 8 + lc;
        uint32_t hp, lp;
        split2_pack(acc[nb][0], acc[nb][1], hp, lp);
        *(uint32_t*)(xH + fr0 * STW + c) = hp;
        *(uint32_t*)(xL + fr0 * STW + c) = lp;
        split2_pack(acc[nb][2], acc[nb][3], hp, lp);
        *(uint32_t*)(xH + (fr0 + 8) * STW + c) = hp;
        *(uint32_t*)(xL + (fr0 + 8) * STW + c) = lp;
    }
    __syncthreads();

    // stage 2: fMS = relu(ln2d(S @ fM)) -> global (3-pass on x)
    {
        const ALoadGB as{g_Sh + bg * 1024, g_Sl + bg * 1024, 32, fr0, fk0};
        mm3p<ALoadGB, 4, 2, true, STW>(acc, as, xH, xL, wn32, lane);
    }
    ln2048_relu(acc, red);
#pragma unroll
    for (int nb = 0; nb < 4; nb++) {
        int c = wn32 + nb * 8 + lc;
        size_t o0 = bg * 2048 + (size_t)fr0 * 64 + c;
        size_t o1 = o0 + 8 * 64;
        uint32_t hp, lp;
        split2_pack(acc[nb][0], acc[nb][1], hp, lp);
        *(uint32_t*)(g_FMSh + o0) = hp;
        *(uint32_t*)(g_FMSl + o0) = lp;
        split2_pack(acc[nb][2], acc[nb][3], hp, lp);
        *(uint32_t*)(g_FMSh + o1) = hp;
        *(uint32_t*)(g_FMSl + o1) = lp;
    }
    __syncthreads();

    // stage 3: v = relu(ln2d(f @ Vw)) -> x (2-pass)
    mm2p<ALoadGF, 4, 4, true, STW>(acc, af, wH, wn32, lane);
    ln2048_relu(acc, red);
#pragma unroll
    for (int nb = 0; nb < 4; nb++) {
        int c = wn32 + nb * 8 + lc;
        uint32_t hp, lp;
        split2_pack(acc[nb][0], acc[nb][1], hp, lp);
        *(uint32_t*)(xH + fr0 * STW + c) = hp;
        *(uint32_t*)(xL + fr0 * STW + c) = lp;
        split2_pack(acc[nb][2], acc[nb][3], hp, lp);
        *(uint32_t*)(xH + (fr0 + 8) * STW + c) = hp;
        *(uint32_t*)(xL + (fr0 + 8) * STW + c) = lp;
    }
    __syncthreads();

    float a2[2][4];

    // stage 4: k = kw @ v^T + kb -> sH (3-pass on x; k stored hi only)
    {
        const ALoadGF akw{kw_g + g * 2048, 64, fr0, fk0};
        mm3p<ALoadGF, 2, 4, false, STW>(a2, akw, xH, xL, wn16, lane);
        float b0 = __ldg(kb_g + g * 32 + fr0);
        float b1 = __ldg(kb_g + g * 32 + fr0 + 8);
#pragma unroll
        for (int nb = 0; nb < 2; nb++) {
            int c = wn16 + nb * 8 + lc;
            *(uint32_t*)(sH + fr0 * STN + c)       = pack2h(a2[nb][0] + b0, a2[nb][1] + b0);
            *(uint32_t*)(sH + (fr0 + 8) * STN + c) = pack2h(a2[nb][2] + b1, a2[nb][3] + b1);
        }
    }
    __syncthreads();

    // stage 5: scores = q @ k -> sc (2-pass; k hi only)
    {
        const ALoadGB aq{g_Qh + bg * 1024, g_Ql + bg * 1024, 32, fr0, fk0};
        mm2p<ALoadGB, 2, 2, true, STN>(a2, aq, sH, wn16, lane);
#pragma unroll
        for (int nb = 0; nb < 2; nb++) {
            int c = wn16 + nb * 8 + lc;
            *(float2*)(sc + fr0 * 36 + c)       = make_float2(a2[nb][0], a2[nb][1]);
            *(float2*)(sc + (fr0 + 8) * 36 + c) = make_float2(a2[nb][2], a2[nb][3]);
        }
    }
    __syncthreads();

    // stage 6: softmax(sc / 8) -> att hi/lo in s buffers
    {
        const int tx8 = tid & 7, ty16 = tid >> 3;
#pragma unroll
        for (int i = 0; i < 2; i++) {
            int row = 2 * ty16 + i;
            float v[4];
#pragma unroll
            for (int j = 0; j < 4; j++) v[j] = sc[row * 36 + 4 * tx8 + j];
            float m = fmaxf(fmaxf(v[0], v[1]), fmaxf(v[2], v[3]));
#pragma unroll
            for (int o = 4; o > 0; o >>= 1)
                m = fmaxf(m, __shfl_xor_sync(0xffffffffu, m, o));
            float s = 0.f;
#pragma unroll
            for (int j = 0; j < 4; j++) { v[j] = __expf((v[j] - m) * 0.125f); s += v[j]; }
#pragma unroll
            for (int o = 4; o > 0; o >>= 1)
                s += __shfl_xor_sync(0xffffffffu, s, o);
            float inv = __frcp_rn(s);
#pragma unroll
            for (int j = 0; j < 4; j++) {
                float p = v[j] * inv;
                __half h, l;
                split_h(p, h, l);
                sH[row * STN + 4 * tx8 + j] = h;
                sL[row * STN + 4 * tx8 + j] = l;
            }
        }
    }
    __syncthreads();

    // stage 7: fc = relu(ln2d(att @ v)) -> global (3-pass on x)
    {
        const ALoadS aatt{
            smem_u32(sH + (rw + (lane & 15)) * STN + (lane >> 4) * 8),
            smem_u32(sL + (rw + (lane & 15)) * STN + (lane >> 4) * 8)};
        mm3p<ALoadS, 4, 2, true, STW>(acc, aatt, xH, xL, wn32, lane);
    }
    ln2048_relu(acc, red);
#pragma unroll
    for (int nb = 0; nb < 4; nb++) {
        int c = wn32 + nb * 8 + lc;
        size_t o0 = bg * 2048 + (size_t)fr0 * 64 + c;
        size_t o1 = o0 + 8 * 64;
        uint32_t hp, lp;
        split2_pack(acc[nb][0], acc[nb][1], hp, lp);
        *(uint32_t*)(g_FCh + o0) = hp;
        *(uint32_t*)(g_FCl + o0) = lp;
        split2_pack(acc[nb][2], acc[nb][3], hp, lp);
        *(uint32_t*)(g_FCh + o1) = hp;
        *(uint32_t*)(g_FCl + o1) = lp;
    }
}

// ============== residual + split-K reduce + affine LayerNorm ===============
__global__ void __launch_bounds__(256) final_ln(
    const float* __restrict__ qv,
    const float* __restrict__ wA, const float* __restrict__ bA,
    const float* __restrict__ wB, const float* __restrict__ bB,
    float* __restrict__ out)
{
    const int r = blockIdx.x, z = blockIdx.y, c = threadIdx.x;
    const float* w = z ? wB : wA;
    const float* b = z ? bB : bA;
    float x = qv[(size_t)r * 256 + c];
#pragma unroll
    for (int k = 0; k < 4; k++)
        x += g_P[(size_t)(z * 4 + k) * 614400 + (size_t)r * 256 + c];

    __shared__ float sred[16];
    float s = x, q = x * x;
#pragma unroll
    for (int o = 16; o > 0; o >>= 1) {
        s += __shfl_xor_sync(0xffffffffu, s, o);
        q += __shfl_xor_sync(0xffffffffu, q, o);
    }
    int wp = threadIdx.x >> 5;
    if ((threadIdx.x & 31) == 0) { sred[wp] = s; sred[8 + wp] = q; }
    __syncthreads();
    float S = 0.f, Q2 = 0.f;
#pragma unroll
    for (int i = 0; i < 8; i++) { S += sred[i]; Q2 += sred[8 + i]; }
    float mean = S * (1.f / 256.f);
    float var  = Q2 * (1.f / 256.f) - mean * mean;
    float inv  = rsqrtf(var + 1e-5f);
    out[(size_t)z * 614400 + (size_t)r * 256 + c] = (x - mean) * inv * w[c] + b[c];
}

// ================================ launcher =================================
extern "C" void kernel_launch(void* const* d_in, const int* in_sizes, int n_in,
                              void* d_out, int out_size)
{
    const float* feats = (const float*)d_in[0];
    const float* qv    = (const float*)d_in[1];
    const float* m_w   = (const float*)d_in[7];
    const float* m_b   = (const float*)d_in[8];
    const float* s_w   = (const float*)d_in[9];
    const float* s_b   = (const float*)d_in[10];
    const float* q_w   = (const float*)d_in[11];
    const float* q_b   = (const float*)d_in[12];
    const float* v_w   = (const float*)d_in[13];
    const float* v_b   = (const float*)d_in[14];
    const float* k_w   = (const float*)d_in[15];
    const float* k_b   = (const float*)d_in[16];
    const float* Wv_w  = (const float*)d_in[17];
    const float* Wv_b  = (const float*)d_in[18];
    const float* Wv2_w = (const float*)d_in[19];
    const float* Wv2_b = (const float*)d_in[20];
    const float* lnA_w = (const float*)d_in[21];
    const float* lnA_b = (const float*)d_in[22];
    const float* lnB_w = (const float*)d_in[23];
    const float* lnB_b = (const float*)d_in[24];
    float* out = (float*)d_out;

    float* gP;
    cudaGetSymbolAddress((void**)&gP, g_P);
    __half *Wvh, *W2h, *FMSh, *FMSl, *FCh, *FCl;
    cudaGetSymbolAddress((void**)&Wvh, g_Wvh);
    cudaGetSymbolAddress((void**)&W2h, g_W2h);
    cudaGetSymbolAddress((void**)&FMSh, g_FMSh); cudaGetSymbolAddress((void**)&FMSl, g_FMSl);
    cudaGetSymbolAddress((void**)&FCh, g_FCh);   cudaGetSymbolAddress((void**)&FCl, g_FCl);

    cudaFuncSetAttribute(gen_gemm, cudaFuncAttributeMaxDynamicSharedMemorySize, GEMM_SMEM);
    cudaFuncSetAttribute(hmma_gemm, cudaFuncAttributeMaxDynamicSharedMemorySize, GEMM_SMEM);

    // 0) split fp32 operands into fp16 (qv hi+lo, weights hi only)
    split_kernel<<<dim3(4096, 1, 7), 256>>>(qv, m_w, v_w, s_w, q_w, Wv_w, Wv2_w);

    // 1) merged M/V/S/Q generators (M/V 1-pass; S/Q 2-pass)
    gen_gemm<<<dim3(19, 128, 4), 256, GEMM_SMEM>>>(m_b, v_b, s_b, q_b);

    // 2) fused per-(bn,g) dynamic conv + attention (mixed 2/3-pass)
    fused_bg<<<dim3(2400, 4), 128>>>(feats, k_w, k_b);

    // 3) output projections: (2400x8192) @ (256x8192)^T, split-K=4, 2-pass
    hmma_gemm<<<dim3(2, 19, 8), 256, GEMM_SMEM>>>(
        FMSh, FMSl, Wvh, Wv_b, gP,
        FCh,  FCl,  W2h, Wv2_b, gP + 4 * 614400,
        2400, 256, 8192, 2048, 4, 614400);

    // 4) residual + split-K reduce + affine LayerNorm
    final_ln<<<dim3(2400, 2), 256>>>(qv, lnA_w, lnA_b, lnB_w, lnB_b, out);
}